// round 1
// baseline (speedup 1.0000x reference)
#include <cuda_runtime.h>
#include <math.h>

#define B_    2
#define S_    2048
#define HID_  2048
#define NH_   16
#define NKV_  8
#define D_    128
#define G_    (NH_/NKV_)
#define BSR_  (B_*S_)          // 4096 rows

// -------- scratch (no allocations allowed; __device__ globals) --------
__device__ float g_Q[BSR_ * NH_ * D_];   // [b*S+s, h, d] 33.5 MB
__device__ float g_K[BSR_ * NKV_ * D_];  // 16.8 MB
__device__ float g_V[BSR_ * NKV_ * D_];  // 16.8 MB
__device__ float g_C[BSR_ * NH_ * D_];   // context, 33.5 MB

// ============================================================
// SGEMM: C[M,N] = A[M,K] @ W[K,N] (+ bias). 128x128x8 tile,
// 256 threads, 8x8 per-thread register tile, float4 everywhere.
// M,N,K all multiples of the tile sizes here (4096 / 2048|1024 / 2048).
// ============================================================
#define BM 128
#define BN 128
#define BKk 8
#define TM 8
#define TN 8

__global__ __launch_bounds__(256) void sgemm_bias(
    const float* __restrict__ A, const float* __restrict__ W,
    const float* __restrict__ bias, float* __restrict__ C,
    int M, int N, int K)
{
    __shared__ float As[BKk][BM];
    __shared__ float Bs[BKk][BN];

    const int tid  = threadIdx.x;
    const int tx   = tid & 15;         // 0..15  (N direction)
    const int ty   = tid >> 4;         // 0..15  (M direction)
    const int aRow = tid >> 1;         // 0..127
    const int aCol = (tid & 1) * 4;    // 0 or 4
    const int bRow = tid >> 5;         // 0..7
    const int bCol = (tid & 31) * 4;   // 0..124

    const float* Ab = A + (size_t)blockIdx.y * BM * K;
    const float* Wb = W + (size_t)blockIdx.x * BN;

    float acc[TM][TN];
#pragma unroll
    for (int i = 0; i < TM; i++)
#pragma unroll
        for (int j = 0; j < TN; j++) acc[i][j] = 0.0f;

    for (int k0 = 0; k0 < K; k0 += BKk) {
        float4 av = *(const float4*)(Ab + (size_t)aRow * K + k0 + aCol);
        As[aCol + 0][aRow] = av.x;
        As[aCol + 1][aRow] = av.y;
        As[aCol + 2][aRow] = av.z;
        As[aCol + 3][aRow] = av.w;
        float4 bv = *(const float4*)(Wb + (size_t)(k0 + bRow) * N + bCol);
        *(float4*)&Bs[bRow][bCol] = bv;
        __syncthreads();

#pragma unroll
        for (int kk = 0; kk < BKk; kk++) {
            float a[TM], b[TN];
#pragma unroll
            for (int i = 0; i < TM; i += 4)
                *(float4*)&a[i] = *(const float4*)&As[kk][ty * TM + i];
#pragma unroll
            for (int j = 0; j < TN; j += 4)
                *(float4*)&b[j] = *(const float4*)&Bs[kk][tx * TN + j];
#pragma unroll
            for (int i = 0; i < TM; i++)
#pragma unroll
                for (int j = 0; j < TN; j++)
                    acc[i][j] += a[i] * b[j];
        }
        __syncthreads();
    }

#pragma unroll
    for (int i = 0; i < TM; i++) {
        int row = blockIdx.y * BM + ty * TM + i;
#pragma unroll
        for (int j = 0; j < TN; j += 4) {
            int col = blockIdx.x * BN + tx * TN + j;
            float4 o = make_float4(acc[i][j], acc[i][j+1], acc[i][j+2], acc[i][j+3]);
            if (bias) {
                o.x += bias[col];     o.y += bias[col + 1];
                o.z += bias[col + 2]; o.w += bias[col + 3];
            }
            *(float4*)&C[(size_t)row * N + col] = o;
        }
    }
}

// ============================================================
// RoPE applied in-place to g_Q (16 heads) and g_K (8 heads).
// One block per (b,s) row. Double-precision angle math so the
// tables match the fp32 reference to within rounding.
// ============================================================
__global__ void rope_kernel()
{
    const int bs = blockIdx.x;            // 0..B*S-1
    const int s  = bs % S_;
    // ln(1e6)/64
    const double NEG_LOG_STEP = -0.2158673524681918;

    for (int p = threadIdx.x; p < (NH_ + NKV_) * 64; p += blockDim.x) {
        int head = p >> 6;
        int i    = p & 63;
        double freq = exp((double)i * NEG_LOG_STEP);
        double ang  = (double)s * freq;
        double sd, cd;
        sincos(ang, &sd, &cd);
        float c = (float)cd, sn = (float)sd;
        float* base;
        if (head < NH_) base = g_Q + ((size_t)bs * NH_ + head) * D_;
        else            base = g_K + ((size_t)bs * NKV_ + (head - NH_)) * D_;
        float x1 = base[i], x2 = base[i + 64];
        base[i]      = x1 * c - x2 * sn;
        base[i + 64] = x2 * c + x1 * sn;
    }
}

// ============================================================
// Flash attention (causal, GQA G=2), fp32.
// Grid: (S/64, NH, B). Block: 256 threads (8 warps x 8 rows each).
// Shared: Qs[64][132], Ks[64][129], Vs[64][132], Ps[64][64].
// Ks stride 129 -> per-lane key rows (lane, lane+32) are bank-
// conflict-free on scalar loads: bank = (lane + d) mod 32.
// ============================================================
#define QSS 132
#define KSS 129
#define VSS 132
#define FLASH_SMEM ((64*QSS + 64*KSS + 64*VSS + 64*64) * 4)

__global__ __launch_bounds__(256) void flash_kernel()
{
    extern __shared__ float sm[];
    float* Qs = sm;
    float* Ks = Qs + 64 * QSS;
    float* Vs = Ks + 64 * KSS;
    float* Ps = Vs + 64 * VSS;

    const int tid   = threadIdx.x;
    const int lane  = tid & 31;
    const int warp  = tid >> 5;
    const int qtile = blockIdx.x;
    const int h     = blockIdx.y;
    const int b     = blockIdx.z;
    const int kvh   = h / G_;
    const int qbase = qtile * 64;
    const int r0    = warp * 8;
    const float scale = 0.08838834764831845f;   // 1/sqrt(128)

    // load Q tile
    for (int idx = tid; idx < 64 * 32; idx += 256) {
        int r = idx >> 5, c4 = (idx & 31) << 2;
        float4 q = *(const float4*)(g_Q +
            (((size_t)b * S_ + qbase + r) * NH_ + h) * D_ + c4);
        *(float4*)&Qs[r * QSS + c4] = q;
    }

    float m_i[8], l_i[8], acc[8][4];
#pragma unroll
    for (int r = 0; r < 8; r++) {
        m_i[r] = -INFINITY; l_i[r] = 0.0f;
        acc[r][0] = acc[r][1] = acc[r][2] = acc[r][3] = 0.0f;
    }

    for (int j = 0; j <= qtile; j++) {
        const int kb = j * 64;
        __syncthreads();   // previous tile fully consumed; Q stores visible (1st iter)
        for (int idx = tid; idx < 64 * 32; idx += 256) {
            int r = idx >> 5, c4 = (idx & 31) << 2;
            size_t goff = (((size_t)b * S_ + kb + r) * NKV_ + kvh) * D_ + c4;
            float4 kk = *(const float4*)(g_K + goff);
            Ks[r * KSS + c4 + 0] = kk.x;
            Ks[r * KSS + c4 + 1] = kk.y;
            Ks[r * KSS + c4 + 2] = kk.z;
            Ks[r * KSS + c4 + 3] = kk.w;
            float4 vv = *(const float4*)(g_V + goff);
            *(float4*)&Vs[r * VSS + c4] = vv;
        }
        __syncthreads();

        // ---- scores: key rows (lane) and (lane+32) ----
        float s0[8], s1[8];
#pragma unroll
        for (int r = 0; r < 8; r++) { s0[r] = 0.0f; s1[r] = 0.0f; }
        const float* kA = &Ks[lane * KSS];
        const float* kB = &Ks[(lane + 32) * KSS];
#pragma unroll 2
        for (int d = 0; d < 128; d += 4) {
            float a0 = kA[d], a1 = kA[d+1], a2 = kA[d+2], a3 = kA[d+3];
            float b0 = kB[d], b1 = kB[d+1], b2 = kB[d+2], b3 = kB[d+3];
#pragma unroll
            for (int r = 0; r < 8; r++) {
                float4 q = *(const float4*)&Qs[(r0 + r) * QSS + d];
                s0[r] += q.x*a0 + q.y*a1 + q.z*a2 + q.w*a3;
                s1[r] += q.x*b0 + q.y*b1 + q.z*b2 + q.w*b3;
            }
        }

        const bool diag = (j == qtile);
#pragma unroll
        for (int r = 0; r < 8; r++) {
            float v0 = s0[r] * scale, v1 = s1[r] * scale;
            if (diag) {
                int qi = r0 + r;               // kb == qbase on the diagonal
                if (lane > qi)       v0 = -INFINITY;
                if (lane + 32 > qi)  v1 = -INFINITY;
            }
            float mt = fmaxf(v0, v1);
#pragma unroll
            for (int o = 16; o > 0; o >>= 1)
                mt = fmaxf(mt, __shfl_xor_sync(0xffffffffu, mt, o));
            float mnew  = fmaxf(m_i[r], mt);
            float alpha = expf(m_i[r] - mnew);
            float p0 = expf(v0 - mnew);
            float p1 = expf(v1 - mnew);
            float ps = p0 + p1;
#pragma unroll
            for (int o = 16; o > 0; o >>= 1)
                ps += __shfl_xor_sync(0xffffffffu, ps, o);
            l_i[r] = l_i[r] * alpha + ps;
            m_i[r] = mnew;
            acc[r][0] *= alpha; acc[r][1] *= alpha;
            acc[r][2] *= alpha; acc[r][3] *= alpha;
            Ps[(r0 + r) * 64 + lane]      = p0;
            Ps[(r0 + r) * 64 + lane + 32] = p1;
        }
        __syncwarp();

        // ---- PV: lane owns output dims [4*lane, 4*lane+4) ----
#pragma unroll 2
        for (int k = 0; k < 64; k++) {
            float4 v = *(const float4*)&Vs[k * VSS + (lane << 2)];
#pragma unroll
            for (int r = 0; r < 8; r++) {
                float p = Ps[(r0 + r) * 64 + k];
                acc[r][0] += p * v.x; acc[r][1] += p * v.y;
                acc[r][2] += p * v.z; acc[r][3] += p * v.w;
            }
        }
    }

#pragma unroll
    for (int r = 0; r < 8; r++) {
        float inv = 1.0f / l_i[r];
        float4 o = make_float4(acc[r][0]*inv, acc[r][1]*inv,
                               acc[r][2]*inv, acc[r][3]*inv);
        *(float4*)(g_C + (((size_t)b * S_ + qbase + r0 + r) * NH_ + h) * D_
                   + (lane << 2)) = o;
    }
}

// ============================================================
// launch
// ============================================================
extern "C" void kernel_launch(void* const* d_in, const int* in_sizes, int n_in,
                              void* d_out, int out_size)
{
    (void)in_sizes; (void)n_in; (void)out_size;
    const float* hidden = (const float*)d_in[0];
    const float* Wq = (const float*)d_in[1];
    const float* bq = (const float*)d_in[2];
    const float* Wk = (const float*)d_in[3];
    const float* bk = (const float*)d_in[4];
    const float* Wv = (const float*)d_in[5];
    const float* bv = (const float*)d_in[6];
    const float* Wo = (const float*)d_in[7];
    float* out = (float*)d_out;

    float *qp, *kp, *vp, *cp;
    cudaGetSymbolAddress((void**)&qp, g_Q);
    cudaGetSymbolAddress((void**)&kp, g_K);
    cudaGetSymbolAddress((void**)&vp, g_V);
    cudaGetSymbolAddress((void**)&cp, g_C);

    cudaFuncSetAttribute(flash_kernel,
        cudaFuncAttributeMaxDynamicSharedMemorySize, FLASH_SMEM);

    const int M = BSR_;  // 4096

    // QKV projections
    sgemm_bias<<<dim3(HID_ / BN, M / BM), 256>>>(hidden, Wq, bq, qp, M, NH_ * D_, HID_);
    sgemm_bias<<<dim3((NKV_*D_) / BN, M / BM), 256>>>(hidden, Wk, bk, kp, M, NKV_ * D_, HID_);
    sgemm_bias<<<dim3((NKV_*D_) / BN, M / BM), 256>>>(hidden, Wv, bv, vp, M, NKV_ * D_, HID_);

    // RoPE on Q and K
    rope_kernel<<<BSR_, 256>>>();

    // causal GQA flash attention
    flash_kernel<<<dim3(S_ / 64, NH_, B_), 256, FLASH_SMEM>>>();

    // output projection (no bias)
    sgemm_bias<<<dim3(HID_ / BN, M / BM), 256>>>(cp, Wo, nullptr, out, M, HID_, NH_ * D_);
}

// round 2
// speedup vs baseline: 2.0681x; 2.0681x over previous
#include <cuda_runtime.h>
#include <math.h>

#define B_    2
#define S_    2048
#define HID_  2048
#define NH_   16
#define NKV_  8
#define D_    128
#define G_    (NH_/NKV_)
#define BSR_  (B_*S_)          // 4096 rows

// -------- scratch (no allocations allowed; __device__ globals) --------
__device__ float g_Q[BSR_ * NH_ * D_];   // 33.5 MB
__device__ float g_K[BSR_ * NKV_ * D_];  // 16.8 MB
__device__ float g_V[BSR_ * NKV_ * D_];  // 16.8 MB
__device__ float g_C[BSR_ * NH_ * D_];   // 33.5 MB
__device__ float g_cos[S_ * 64];         // RoPE tables, 512 KB each
__device__ float g_sin[S_ * 64];

// ============================================================
// TF32 tensor-core GEMM: C[M,N] = A[M,K] @ W[K,N] (+bias)
// Block 128x128x32, 256 threads = 8 warps (2x4), warp tile 64x32,
// mma.sync.m16n8k8 tf32. M%128==0, N%128==0, K%32==0 (true here).
// As stride 36, Bs stride 132 -> conflict-free fragment LDS.
// ============================================================
#define BM 128
#define BN 128
#define BK 32
#define ASTR 36
#define BSTR 132

__device__ __forceinline__ unsigned f2tf(float x) {
    unsigned u;
    asm("cvt.rna.tf32.f32 %0, %1;" : "=r"(u) : "f"(x));
    return u;
}

__device__ __forceinline__ void mma_tf32(float* d, const unsigned* a, const unsigned* b) {
    asm volatile(
        "mma.sync.aligned.m16n8k8.row.col.f32.tf32.tf32.f32 "
        "{%0,%1,%2,%3}, {%4,%5,%6,%7}, {%8,%9}, {%0,%1,%2,%3};\n"
        : "+f"(d[0]), "+f"(d[1]), "+f"(d[2]), "+f"(d[3])
        : "r"(a[0]), "r"(a[1]), "r"(a[2]), "r"(a[3]), "r"(b[0]), "r"(b[1]));
}

__global__ __launch_bounds__(256, 2) void gemm_tf32(
    const float* __restrict__ A, const float* __restrict__ W,
    const float* __restrict__ bias, float* __restrict__ C,
    int M, int N, int K)
{
    __shared__ unsigned As[BM * ASTR];
    __shared__ unsigned Bs[BK * BSTR];

    const int tid  = threadIdx.x;
    const int lane = tid & 31;
    const int warp = tid >> 5;
    const int wm   = warp >> 2;     // 0..1
    const int wn   = warp & 3;      // 0..3

    const float* Ab = A + (size_t)blockIdx.y * BM * K;
    const float* Wb = W + (size_t)blockIdx.x * BN;

    float acc[4][4][4];
#pragma unroll
    for (int i = 0; i < 4; i++)
#pragma unroll
        for (int j = 0; j < 4; j++)
#pragma unroll
            for (int e = 0; e < 4; e++) acc[i][j][e] = 0.0f;

    const int arow = tid >> 3;            // 0..31 (+32*p)
    const int acol = (tid & 7) << 2;      // 0..28
    const int bc4  = lane << 2;           // 0..124

    for (int k0 = 0; k0 < K; k0 += BK) {
        float4 av[4], bv[4];
#pragma unroll
        for (int p = 0; p < 4; p++)
            av[p] = *(const float4*)(Ab + (size_t)(arow + p * 32) * K + k0 + acol);
#pragma unroll
        for (int p = 0; p < 4; p++)
            bv[p] = *(const float4*)(Wb + (size_t)(k0 + warp + p * 8) * N + bc4);

        __syncthreads();   // previous iter's MMA done reading smem
#pragma unroll
        for (int p = 0; p < 4; p++) {
            int base = (arow + p * 32) * ASTR + acol;
            As[base + 0] = f2tf(av[p].x);
            As[base + 1] = f2tf(av[p].y);
            As[base + 2] = f2tf(av[p].z);
            As[base + 3] = f2tf(av[p].w);
        }
#pragma unroll
        for (int p = 0; p < 4; p++) {
            int base = (warp + p * 8) * BSTR + bc4;
            Bs[base + 0] = f2tf(bv[p].x);
            Bs[base + 1] = f2tf(bv[p].y);
            Bs[base + 2] = f2tf(bv[p].z);
            Bs[base + 3] = f2tf(bv[p].w);
        }
        __syncthreads();

#pragma unroll
        for (int kk = 0; kk < BK; kk += 8) {
            unsigned a[4][4], b[4][2];
#pragma unroll
            for (int mf = 0; mf < 4; mf++) {
                int r = wm * 64 + mf * 16 + (lane >> 2);
                int c = kk + (lane & 3);
                a[mf][0] = As[r * ASTR + c];
                a[mf][1] = As[(r + 8) * ASTR + c];
                a[mf][2] = As[r * ASTR + c + 4];
                a[mf][3] = As[(r + 8) * ASTR + c + 4];
            }
#pragma unroll
            for (int nf = 0; nf < 4; nf++) {
                int n = wn * 32 + nf * 8 + (lane >> 2);
                b[nf][0] = Bs[(kk + (lane & 3)) * BSTR + n];
                b[nf][1] = Bs[(kk + 4 + (lane & 3)) * BSTR + n];
            }
#pragma unroll
            for (int mf = 0; mf < 4; mf++)
#pragma unroll
                for (int nf = 0; nf < 4; nf++)
                    mma_tf32(acc[mf][nf], a[mf], b[nf]);
        }
    }

    // epilogue: bias + store (float2 per fragment half)
#pragma unroll
    for (int mf = 0; mf < 4; mf++) {
        int row = blockIdx.y * BM + wm * 64 + mf * 16 + (lane >> 2);
#pragma unroll
        for (int nf = 0; nf < 4; nf++) {
            int col = blockIdx.x * BN + wn * 32 + nf * 8 + 2 * (lane & 3);
            float b0 = 0.0f, b1 = 0.0f;
            if (bias) { b0 = bias[col]; b1 = bias[col + 1]; }
            float2 o0 = make_float2(acc[mf][nf][0] + b0, acc[mf][nf][1] + b1);
            float2 o1 = make_float2(acc[mf][nf][2] + b0, acc[mf][nf][3] + b1);
            *(float2*)&C[(size_t)row * N + col]       = o0;
            *(float2*)&C[(size_t)(row + 8) * N + col] = o1;
        }
    }
}

// ============================================================
// RoPE: precompute tables (131K angles, DP trig once), then apply.
// ============================================================
__global__ void rope_table_kernel()
{
    int idx = blockIdx.x * blockDim.x + threadIdx.x;   // s*64 + i
    if (idx >= S_ * 64) return;
    int s = idx >> 6, i = idx & 63;
    const double NEG_LOG_STEP = -0.2158673524681918;   // -ln(1e6)/64
    double freq = exp((double)i * NEG_LOG_STEP);
    double sd, cd;
    sincos((double)s * freq, &sd, &cd);
    g_cos[idx] = (float)cd;
    g_sin[idx] = (float)sd;
}

__global__ void rope_apply_kernel()
{
    __shared__ float sc[64], ss[64];
    const int bs = blockIdx.x;
    const int s  = bs % S_;
    if (threadIdx.x < 64) {
        sc[threadIdx.x] = g_cos[s * 64 + threadIdx.x];
        ss[threadIdx.x] = g_sin[s * 64 + threadIdx.x];
    }
    __syncthreads();

    for (int p = threadIdx.x; p < (NH_ + NKV_) * 64; p += blockDim.x) {
        int head = p >> 6;
        int i    = p & 63;
        float c = sc[i], sn = ss[i];
        float* base;
        if (head < NH_) base = g_Q + ((size_t)bs * NH_ + head) * D_;
        else            base = g_K + ((size_t)bs * NKV_ + (head - NH_)) * D_;
        float x1 = base[i], x2 = base[i + 64];
        base[i]      = x1 * c - x2 * sn;
        base[i + 64] = x2 * c + x1 * sn;
    }
}

// ============================================================
// Flash attention (causal, GQA G=2), fp32 — unchanged from R1.
// ============================================================
#define QSS 132
#define KSS 129
#define VSS 132
#define FLASH_SMEM ((64*QSS + 64*KSS + 64*VSS + 64*64) * 4)

__global__ __launch_bounds__(256) void flash_kernel()
{
    extern __shared__ float sm[];
    float* Qs = sm;
    float* Ks = Qs + 64 * QSS;
    float* Vs = Ks + 64 * KSS;
    float* Ps = Vs + 64 * VSS;

    const int tid   = threadIdx.x;
    const int lane  = tid & 31;
    const int warp  = tid >> 5;
    const int qtile = blockIdx.x;
    const int h     = blockIdx.y;
    const int b     = blockIdx.z;
    const int kvh   = h / G_;
    const int qbase = qtile * 64;
    const int r0    = warp * 8;
    const float scale = 0.08838834764831845f;   // 1/sqrt(128)

    for (int idx = tid; idx < 64 * 32; idx += 256) {
        int r = idx >> 5, c4 = (idx & 31) << 2;
        float4 q = *(const float4*)(g_Q +
            (((size_t)b * S_ + qbase + r) * NH_ + h) * D_ + c4);
        *(float4*)&Qs[r * QSS + c4] = q;
    }

    float m_i[8], l_i[8], acc[8][4];
#pragma unroll
    for (int r = 0; r < 8; r++) {
        m_i[r] = -INFINITY; l_i[r] = 0.0f;
        acc[r][0] = acc[r][1] = acc[r][2] = acc[r][3] = 0.0f;
    }

    for (int j = 0; j <= qtile; j++) {
        const int kb = j * 64;
        __syncthreads();
        for (int idx = tid; idx < 64 * 32; idx += 256) {
            int r = idx >> 5, c4 = (idx & 31) << 2;
            size_t goff = (((size_t)b * S_ + kb + r) * NKV_ + kvh) * D_ + c4;
            float4 kk = *(const float4*)(g_K + goff);
            Ks[r * KSS + c4 + 0] = kk.x;
            Ks[r * KSS + c4 + 1] = kk.y;
            Ks[r * KSS + c4 + 2] = kk.z;
            Ks[r * KSS + c4 + 3] = kk.w;
            float4 vv = *(const float4*)(g_V + goff);
            *(float4*)&Vs[r * VSS + c4] = vv;
        }
        __syncthreads();

        float s0[8], s1[8];
#pragma unroll
        for (int r = 0; r < 8; r++) { s0[r] = 0.0f; s1[r] = 0.0f; }
        const float* kA = &Ks[lane * KSS];
        const float* kB = &Ks[(lane + 32) * KSS];
#pragma unroll 2
        for (int d = 0; d < 128; d += 4) {
            float a0 = kA[d], a1 = kA[d+1], a2 = kA[d+2], a3 = kA[d+3];
            float b0 = kB[d], b1 = kB[d+1], b2 = kB[d+2], b3 = kB[d+3];
#pragma unroll
            for (int r = 0; r < 8; r++) {
                float4 q = *(const float4*)&Qs[(r0 + r) * QSS + d];
                s0[r] += q.x*a0 + q.y*a1 + q.z*a2 + q.w*a3;
                s1[r] += q.x*b0 + q.y*b1 + q.z*b2 + q.w*b3;
            }
        }

        const bool diag = (j == qtile);
#pragma unroll
        for (int r = 0; r < 8; r++) {
            float v0 = s0[r] * scale, v1 = s1[r] * scale;
            if (diag) {
                int qi = r0 + r;
                if (lane > qi)       v0 = -INFINITY;
                if (lane + 32 > qi)  v1 = -INFINITY;
            }
            float mt = fmaxf(v0, v1);
#pragma unroll
            for (int o = 16; o > 0; o >>= 1)
                mt = fmaxf(mt, __shfl_xor_sync(0xffffffffu, mt, o));
            float mnew  = fmaxf(m_i[r], mt);
            float alpha = expf(m_i[r] - mnew);
            float p0 = expf(v0 - mnew);
            float p1 = expf(v1 - mnew);
            float ps = p0 + p1;
#pragma unroll
            for (int o = 16; o > 0; o >>= 1)
                ps += __shfl_xor_sync(0xffffffffu, ps, o);
            l_i[r] = l_i[r] * alpha + ps;
            m_i[r] = mnew;
            acc[r][0] *= alpha; acc[r][1] *= alpha;
            acc[r][2] *= alpha; acc[r][3] *= alpha;
            Ps[(r0 + r) * 64 + lane]      = p0;
            Ps[(r0 + r) * 64 + lane + 32] = p1;
        }
        __syncwarp();

#pragma unroll 2
        for (int k = 0; k < 64; k++) {
            float4 v = *(const float4*)&Vs[k * VSS + (lane << 2)];
#pragma unroll
            for (int r = 0; r < 8; r++) {
                float p = Ps[(r0 + r) * 64 + k];
                acc[r][0] += p * v.x; acc[r][1] += p * v.y;
                acc[r][2] += p * v.z; acc[r][3] += p * v.w;
            }
        }
    }

#pragma unroll
    for (int r = 0; r < 8; r++) {
        float inv = 1.0f / l_i[r];
        float4 o = make_float4(acc[r][0]*inv, acc[r][1]*inv,
                               acc[r][2]*inv, acc[r][3]*inv);
        *(float4*)(g_C + (((size_t)b * S_ + qbase + r0 + r) * NH_ + h) * D_
                   + (lane << 2)) = o;
    }
}

// ============================================================
// launch
// ============================================================
extern "C" void kernel_launch(void* const* d_in, const int* in_sizes, int n_in,
                              void* d_out, int out_size)
{
    (void)in_sizes; (void)n_in; (void)out_size;
    const float* hidden = (const float*)d_in[0];
    const float* Wq = (const float*)d_in[1];
    const float* bq = (const float*)d_in[2];
    const float* Wk = (const float*)d_in[3];
    const float* bk = (const float*)d_in[4];
    const float* Wv = (const float*)d_in[5];
    const float* bv = (const float*)d_in[6];
    const float* Wo = (const float*)d_in[7];
    float* out = (float*)d_out;

    float *qp, *kp, *vp, *cp;
    cudaGetSymbolAddress((void**)&qp, g_Q);
    cudaGetSymbolAddress((void**)&kp, g_K);
    cudaGetSymbolAddress((void**)&vp, g_V);
    cudaGetSymbolAddress((void**)&cp, g_C);

    cudaFuncSetAttribute(flash_kernel,
        cudaFuncAttributeMaxDynamicSharedMemorySize, FLASH_SMEM);

    const int M = BSR_;  // 4096

    // QKV projections (TF32 tensor cores)
    gemm_tf32<<<dim3(HID_ / BN, M / BM), 256>>>(hidden, Wq, bq, qp, M, NH_ * D_, HID_);
    gemm_tf32<<<dim3((NKV_*D_) / BN, M / BM), 256>>>(hidden, Wk, bk, kp, M, NKV_ * D_, HID_);
    gemm_tf32<<<dim3((NKV_*D_) / BN, M / BM), 256>>>(hidden, Wv, bv, vp, M, NKV_ * D_, HID_);

    // RoPE tables + apply
    rope_table_kernel<<<(S_ * 64 + 255) / 256, 256>>>();
    rope_apply_kernel<<<BSR_, 256>>>();

    // causal GQA flash attention (fp32)
    flash_kernel<<<dim3(S_ / 64, NH_, B_), 256, FLASH_SMEM>>>();

    // output projection (TF32, no bias)
    gemm_tf32<<<dim3(HID_ / BN, M / BM), 256>>>(cp, Wo, nullptr, out, M, HID_, NH_ * D_);
}

// round 3
// speedup vs baseline: 2.6889x; 1.3002x over previous
#include <cuda_runtime.h>
#include <cuda_bf16.h>
#include <math.h>

#define B_    2
#define S_    2048
#define HID_  2048
#define NH_   16
#define NKV_  8
#define D_    128
#define G_    (NH_/NKV_)
#define BSR_  (B_*S_)          // 4096 rows

// -------- scratch (no allocations allowed; __device__ globals) --------
__device__ float g_Q[BSR_ * NH_ * D_];    // unroped Q (rope fused into flash)
__device__ float g_K[BSR_ * NKV_ * D_];   // unroped K
__device__ float g_Vt[(size_t)B_ * NKV_ * D_ * S_];  // V transposed: [b][kvh][d][s]
__device__ float g_C[BSR_ * NH_ * D_];
__device__ float g_cos[S_ * 64];
__device__ float g_sin[S_ * 64];

// ============================================================
// TF32 tensor-core GEMM (validated R2): C = A@W + bias
// ============================================================
#define BM 128
#define BN 128
#define BK 32
#define ASTR 36
#define BSTR 132

__device__ __forceinline__ unsigned f2tf(float x) {
    unsigned u;
    asm("cvt.rna.tf32.f32 %0, %1;" : "=r"(u) : "f"(x));
    return u;
}

__device__ __forceinline__ void mma_tf32(float* d, const unsigned* a, const unsigned* b) {
    asm volatile(
        "mma.sync.aligned.m16n8k8.row.col.f32.tf32.tf32.f32 "
        "{%0,%1,%2,%3}, {%4,%5,%6,%7}, {%8,%9}, {%0,%1,%2,%3};\n"
        : "+f"(d[0]), "+f"(d[1]), "+f"(d[2]), "+f"(d[3])
        : "r"(a[0]), "r"(a[1]), "r"(a[2]), "r"(a[3]), "r"(b[0]), "r"(b[1]));
}

// core compute shared by both gemm entry points
__device__ __forceinline__ void gemm_core(
    const float* __restrict__ A, const float* __restrict__ W,
    int N, int K, float acc[4][4][4],
    unsigned* As, unsigned* Bs)
{
    const int tid  = threadIdx.x;
    const int lane = tid & 31;
    const int warp = tid >> 5;
    const int wm   = warp >> 2;
    const int wn   = warp & 3;

    const float* Ab = A + (size_t)blockIdx.y * BM * K;
    const float* Wb = W + (size_t)blockIdx.x * BN;

    const int arow = tid >> 3;
    const int acol = (tid & 7) << 2;
    const int bc4  = lane << 2;

    for (int k0 = 0; k0 < K; k0 += BK) {
        float4 av[4], bv[4];
#pragma unroll
        for (int p = 0; p < 4; p++)
            av[p] = *(const float4*)(Ab + (size_t)(arow + p * 32) * K + k0 + acol);
#pragma unroll
        for (int p = 0; p < 4; p++)
            bv[p] = *(const float4*)(Wb + (size_t)(k0 + warp + p * 8) * N + bc4);

        __syncthreads();
#pragma unroll
        for (int p = 0; p < 4; p++) {
            int base = (arow + p * 32) * ASTR + acol;
            As[base + 0] = f2tf(av[p].x);
            As[base + 1] = f2tf(av[p].y);
            As[base + 2] = f2tf(av[p].z);
            As[base + 3] = f2tf(av[p].w);
        }
#pragma unroll
        for (int p = 0; p < 4; p++) {
            int base = (warp + p * 8) * BSTR + bc4;
            Bs[base + 0] = f2tf(bv[p].x);
            Bs[base + 1] = f2tf(bv[p].y);
            Bs[base + 2] = f2tf(bv[p].z);
            Bs[base + 3] = f2tf(bv[p].w);
        }
        __syncthreads();

#pragma unroll
        for (int kk = 0; kk < BK; kk += 8) {
            unsigned a[4][4], b[4][2];
#pragma unroll
            for (int mf = 0; mf < 4; mf++) {
                int r = wm * 64 + mf * 16 + (lane >> 2);
                int c = kk + (lane & 3);
                a[mf][0] = As[r * ASTR + c];
                a[mf][1] = As[(r + 8) * ASTR + c];
                a[mf][2] = As[r * ASTR + c + 4];
                a[mf][3] = As[(r + 8) * ASTR + c + 4];
            }
#pragma unroll
            for (int nf = 0; nf < 4; nf++) {
                int n = wn * 32 + nf * 8 + (lane >> 2);
                b[nf][0] = Bs[(kk + (lane & 3)) * BSTR + n];
                b[nf][1] = Bs[(kk + 4 + (lane & 3)) * BSTR + n];
            }
#pragma unroll
            for (int mf = 0; mf < 4; mf++)
#pragma unroll
                for (int nf = 0; nf < 4; nf++)
                    mma_tf32(acc[mf][nf], a[mf], b[nf]);
        }
    }
}

__global__ __launch_bounds__(256, 2) void gemm_tf32(
    const float* __restrict__ A, const float* __restrict__ W,
    const float* __restrict__ bias, float* __restrict__ C,
    int N, int K)
{
    __shared__ unsigned As[BM * ASTR];
    __shared__ unsigned Bs[BK * BSTR];
    float acc[4][4][4];
#pragma unroll
    for (int i = 0; i < 4; i++)
#pragma unroll
        for (int j = 0; j < 4; j++)
#pragma unroll
            for (int e = 0; e < 4; e++) acc[i][j][e] = 0.0f;

    gemm_core(A, W, N, K, acc, As, Bs);

    const int lane = threadIdx.x & 31;
    const int warp = threadIdx.x >> 5;
    const int wm = warp >> 2, wn = warp & 3;
#pragma unroll
    for (int mf = 0; mf < 4; mf++) {
        int row = blockIdx.y * BM + wm * 64 + mf * 16 + (lane >> 2);
#pragma unroll
        for (int nf = 0; nf < 4; nf++) {
            int col = blockIdx.x * BN + wn * 32 + nf * 8 + 2 * (lane & 3);
            float b0 = 0.0f, b1 = 0.0f;
            if (bias) { b0 = bias[col]; b1 = bias[col + 1]; }
            *(float2*)&C[(size_t)row * N + col] =
                make_float2(acc[mf][nf][0] + b0, acc[mf][nf][1] + b1);
            *(float2*)&C[(size_t)(row + 8) * N + col] =
                make_float2(acc[mf][nf][2] + b0, acc[mf][nf][3] + b1);
        }
    }
}

// K and V projections in one launch (grid.z: 0=K normal, 1=V transposed out)
__global__ __launch_bounds__(256, 2) void gemm_kv(
    const float* __restrict__ A,
    const float* __restrict__ Wk, const float* __restrict__ bk,
    const float* __restrict__ Wv, const float* __restrict__ bv,
    float* __restrict__ Kout, float* __restrict__ Vt)
{
    __shared__ unsigned As[BM * ASTR];
    __shared__ unsigned Bs[BK * BSTR];
    const int z = blockIdx.z;
    const float* W    = z ? Wv : Wk;
    const float* bias = z ? bv : bk;
    const int N = NKV_ * D_;   // 1024
    const int K = HID_;

    float acc[4][4][4];
#pragma unroll
    for (int i = 0; i < 4; i++)
#pragma unroll
        for (int j = 0; j < 4; j++)
#pragma unroll
            for (int e = 0; e < 4; e++) acc[i][j][e] = 0.0f;

    gemm_core(A, W, N, K, acc, As, Bs);

    const int lane = threadIdx.x & 31;
    const int warp = threadIdx.x >> 5;
    const int wm = warp >> 2, wn = warp & 3;
#pragma unroll
    for (int mf = 0; mf < 4; mf++) {
        int row = blockIdx.y * BM + wm * 64 + mf * 16 + (lane >> 2);
#pragma unroll
        for (int nf = 0; nf < 4; nf++) {
            int col = blockIdx.x * BN + wn * 32 + nf * 8 + 2 * (lane & 3);
            float b0 = bias[col], b1 = bias[col + 1];
            float v00 = acc[mf][nf][0] + b0, v01 = acc[mf][nf][1] + b1;
            float v10 = acc[mf][nf][2] + b0, v11 = acc[mf][nf][3] + b1;
            if (z == 0) {
                *(float2*)&Kout[(size_t)row * N + col]       = make_float2(v00, v01);
                *(float2*)&Kout[(size_t)(row + 8) * N + col] = make_float2(v10, v11);
            } else {
                // Vt[b][kvh][d][s]
                int bb = row >> 11, s = row & 2047;
                int kvh = col >> 7, d = col & 127;
                size_t base = ((size_t)(bb * NKV_ + kvh) * D_ + d) * S_;
                Vt[base + s]            = v00;
                Vt[base + S_ + s]       = v01;     // d+1
                Vt[base + s + 8]        = v10;
                Vt[base + S_ + s + 8]   = v11;
            }
        }
    }
}

// ============================================================
// RoPE tables (DP trig, once per call)
// ============================================================
__global__ void rope_table_kernel()
{
    int idx = blockIdx.x * blockDim.x + threadIdx.x;
    if (idx >= S_ * 64) return;
    int s = idx >> 6, i = idx & 63;
    const double NEG_LOG_STEP = -0.2158673524681918;
    double freq = exp((double)i * NEG_LOG_STEP);
    double sd, cd;
    sincos((double)s * freq, &sd, &cd);
    g_cos[idx] = (float)cd;
    g_sin[idx] = (float)sd;
}

// ============================================================
// Flash attention, causal GQA, 3xBF16 tensor cores.
// Block: 64 q-rows, ktile 64 keys, 256 threads (8 warps).
// RoPE applied to Q/K tiles at load.
// ============================================================
// smem byte offsets (strides in bf16 elements: Q/K 136, V/P 72; Ss f32 stride 68)
#define QS0_OFF 0
#define QS1_OFF (QS0_OFF + 64*136*2)
#define KS0_OFF (QS1_OFF + 64*136*2)
#define KS1_OFF (KS0_OFF + 64*136*2)
#define VS0_OFF (KS1_OFF + 64*136*2)
#define VS1_OFF (VS0_OFF + 128*72*2)
#define PS0_OFF (VS1_OFF + 128*72*2)
#define PS1_OFF (PS0_OFF + 64*72*2)
#define SS_OFF  (PS1_OFF + 64*72*2)
#define AL_OFF  (SS_OFF + 64*68*4)
#define LI_OFF  (AL_OFF + 64*4)
#define FLASH_SMEM (LI_OFF + 64*4)

__device__ __forceinline__ void mma_bf16(float* d, const unsigned* a, const unsigned* b) {
    asm volatile(
        "mma.sync.aligned.m16n8k16.row.col.f32.bf16.bf16.f32 "
        "{%0,%1,%2,%3}, {%4,%5,%6,%7}, {%8,%9}, {%0,%1,%2,%3};\n"
        : "+f"(d[0]), "+f"(d[1]), "+f"(d[2]), "+f"(d[3])
        : "r"(a[0]), "r"(a[1]), "r"(a[2]), "r"(a[3]), "r"(b[0]), "r"(b[1]));
}

// split two floats into packed-bf16 (hi) and packed-bf16 (lo residual)
__device__ __forceinline__ void split2(float x, float y, unsigned& hi, unsigned& lo) {
    __nv_bfloat16 hx = __float2bfloat16_rn(x);
    __nv_bfloat16 hy = __float2bfloat16_rn(y);
    float rx = x - __bfloat162float(hx);
    float ry = y - __bfloat162float(hy);
    __nv_bfloat162 h; h.x = hx; h.y = hy;
    __nv_bfloat162 l; l.x = __float2bfloat16_rn(rx); l.y = __float2bfloat16_rn(ry);
    hi = *(unsigned*)&h;
    lo = *(unsigned*)&l;
}

__global__ __launch_bounds__(256, 1) void flash_bf16()
{
    extern __shared__ char sm[];
    const int tid  = threadIdx.x;
    const int lane = tid & 31;
    const int warp = tid >> 5;
    const int qtile = (gridDim.x - 1) - blockIdx.x;    // heavy tiles first
    const int h    = blockIdx.y;
    const int b    = blockIdx.z;
    const int kvh  = h / G_;
    const int qbase = qtile * 64;
    const float scale = 0.08838834764831845f;

    const int g = lane >> 2;          // groupID
    const int t = lane & 3;           // thread in group
    const int wm = warp >> 1;         // 0..3  (16 q-rows)
    const int wn = warp & 1;          // 0..1
    const int m0 = wm * 16;

    float* alpha_s = (float*)(sm + AL_OFF);
    float* linv_s  = (float*)(sm + LI_OFF);

    // ---- load Q tile with RoPE, split to Qs0/Qs1 ----
    for (int it = tid; it < 64 * 16; it += 256) {
        int r  = it >> 4;
        int c4 = (it & 15) << 2;       // d in [0,64)
        int s  = qbase + r;
        const float* qrow = g_Q + (((size_t)(b * S_ + s)) * NH_ + h) * D_;
        float4 qa = *(const float4*)(qrow + c4);
        float4 qb = *(const float4*)(qrow + c4 + 64);
        float4 cz = *(const float4*)(g_cos + s * 64 + c4);
        float4 sz = *(const float4*)(g_sin + s * 64 + c4);
        float4 oa = make_float4(qa.x*cz.x - qb.x*sz.x, qa.y*cz.y - qb.y*sz.y,
                                qa.z*cz.z - qb.z*sz.z, qa.w*cz.w - qb.w*sz.w);
        float4 ob = make_float4(qb.x*cz.x + qa.x*sz.x, qb.y*cz.y + qa.y*sz.y,
                                qb.z*cz.z + qa.z*sz.z, qb.w*cz.w + qa.w*sz.w);
        unsigned h0, l0, h1, l1;
        int base = r * 136 + c4;
        split2(oa.x, oa.y, h0, l0); split2(oa.z, oa.w, h1, l1);
        *(unsigned*)(sm + QS0_OFF + base * 2)     = h0;
        *(unsigned*)(sm + QS0_OFF + base * 2 + 4) = h1;
        *(unsigned*)(sm + QS1_OFF + base * 2)     = l0;
        *(unsigned*)(sm + QS1_OFF + base * 2 + 4) = l1;
        base = r * 136 + c4 + 64;
        split2(ob.x, ob.y, h0, l0); split2(ob.z, ob.w, h1, l1);
        *(unsigned*)(sm + QS0_OFF + base * 2)     = h0;
        *(unsigned*)(sm + QS0_OFF + base * 2 + 4) = h1;
        *(unsigned*)(sm + QS1_OFF + base * 2)     = l0;
        *(unsigned*)(sm + QS1_OFF + base * 2 + 4) = l1;
    }

    float m_i[8], l_i[8];          // softmax state: warp owns rows 8*warp..+7
#pragma unroll
    for (int r = 0; r < 8; r++) { m_i[r] = -INFINITY; l_i[r] = 0.0f; }
    float ctx[8][4];               // PV acc: warp tile 16q x 64d
#pragma unroll
    for (int i = 0; i < 8; i++)
#pragma unroll
        for (int e = 0; e < 4; e++) ctx[i][e] = 0.0f;

    for (int j = 0; j <= qtile; j++) {
        const int kb = j * 64;
        __syncthreads();   // prev PV done with Vs/Ps; Ks free

        // ---- load K tile (RoPE) ----
        for (int it = tid; it < 64 * 16; it += 256) {
            int r  = it >> 4;
            int c4 = (it & 15) << 2;
            int s  = kb + r;
            const float* krow = g_K + (((size_t)(b * S_ + s)) * NKV_ + kvh) * D_;
            float4 ka = *(const float4*)(krow + c4);
            float4 kb4 = *(const float4*)(krow + c4 + 64);
            float4 cz = *(const float4*)(g_cos + s * 64 + c4);
            float4 sz = *(const float4*)(g_sin + s * 64 + c4);
            float4 oa = make_float4(ka.x*cz.x - kb4.x*sz.x, ka.y*cz.y - kb4.y*sz.y,
                                    ka.z*cz.z - kb4.z*sz.z, ka.w*cz.w - kb4.w*sz.w);
            float4 ob = make_float4(kb4.x*cz.x + ka.x*sz.x, kb4.y*cz.y + ka.y*sz.y,
                                    kb4.z*cz.z + ka.z*sz.z, kb4.w*cz.w + ka.w*sz.w);
            unsigned h0, l0, h1, l1;
            int base = r * 136 + c4;
            split2(oa.x, oa.y, h0, l0); split2(oa.z, oa.w, h1, l1);
            *(unsigned*)(sm + KS0_OFF + base * 2)     = h0;
            *(unsigned*)(sm + KS0_OFF + base * 2 + 4) = h1;
            *(unsigned*)(sm + KS1_OFF + base * 2)     = l0;
            *(unsigned*)(sm + KS1_OFF + base * 2 + 4) = l1;
            base = r * 136 + c4 + 64;
            split2(ob.x, ob.y, h0, l0); split2(ob.z, ob.w, h1, l1);
            *(unsigned*)(sm + KS0_OFF + base * 2)     = h0;
            *(unsigned*)(sm + KS0_OFF + base * 2 + 4) = h1;
            *(unsigned*)(sm + KS1_OFF + base * 2)     = l0;
            *(unsigned*)(sm + KS1_OFF + base * 2 + 4) = l1;
        }
        // ---- load V tile from g_Vt [d][s] ----
        for (int it = tid; it < 128 * 16; it += 256) {
            int d  = it >> 4;
            int c4 = (it & 15) << 2;     // key in [0,64)
            const float* vrow = g_Vt + ((size_t)(b * NKV_ + kvh) * D_ + d) * S_ + kb;
            float4 v = *(const float4*)(vrow + c4);
            unsigned h0, l0, h1, l1;
            split2(v.x, v.y, h0, l0); split2(v.z, v.w, h1, l1);
            int base = d * 72 + c4;
            *(unsigned*)(sm + VS0_OFF + base * 2)     = h0;
            *(unsigned*)(sm + VS0_OFF + base * 2 + 4) = h1;
            *(unsigned*)(sm + VS1_OFF + base * 2)     = l0;
            *(unsigned*)(sm + VS1_OFF + base * 2 + 4) = l1;
        }
        __syncthreads();

        // ---- QK: warp tile 16q x 32keys, acc 4 nfrags ----
        {
            const int n0 = wn * 32;
            float acc[4][4];
#pragma unroll
            for (int nf = 0; nf < 4; nf++)
#pragma unroll
                for (int e = 0; e < 4; e++) acc[nf][e] = 0.0f;

#pragma unroll
            for (int kk = 0; kk < 8; kk++) {
                int c = kk * 16 + 2 * t;
                unsigned aH[4], aL[4];
                aH[0] = *(const unsigned*)(sm + QS0_OFF + ((m0+g)*136 + c)*2);
                aH[1] = *(const unsigned*)(sm + QS0_OFF + ((m0+g+8)*136 + c)*2);
                aH[2] = *(const unsigned*)(sm + QS0_OFF + ((m0+g)*136 + c + 8)*2);
                aH[3] = *(const unsigned*)(sm + QS0_OFF + ((m0+g+8)*136 + c + 8)*2);
                aL[0] = *(const unsigned*)(sm + QS1_OFF + ((m0+g)*136 + c)*2);
                aL[1] = *(const unsigned*)(sm + QS1_OFF + ((m0+g+8)*136 + c)*2);
                aL[2] = *(const unsigned*)(sm + QS1_OFF + ((m0+g)*136 + c + 8)*2);
                aL[3] = *(const unsigned*)(sm + QS1_OFF + ((m0+g+8)*136 + c + 8)*2);
#pragma unroll
                for (int nf = 0; nf < 4; nf++) {
                    int n = n0 + nf * 8 + g;
                    unsigned bH[2], bL[2];
                    bH[0] = *(const unsigned*)(sm + KS0_OFF + (n*136 + c)*2);
                    bH[1] = *(const unsigned*)(sm + KS0_OFF + (n*136 + c + 8)*2);
                    bL[0] = *(const unsigned*)(sm + KS1_OFF + (n*136 + c)*2);
                    bL[1] = *(const unsigned*)(sm + KS1_OFF + (n*136 + c + 8)*2);
                    mma_bf16(acc[nf], aH, bH);
                    mma_bf16(acc[nf], aH, bL);
                    mma_bf16(acc[nf], aL, bH);
                }
            }
            // write scores to Ss
#pragma unroll
            for (int nf = 0; nf < 4; nf++) {
                int col = n0 + nf * 8 + 2 * t;
                *(float2*)(sm + SS_OFF + ((m0+g)*68 + col)*4)   = make_float2(acc[nf][0], acc[nf][1]);
                *(float2*)(sm + SS_OFF + ((m0+g+8)*68 + col)*4) = make_float2(acc[nf][2], acc[nf][3]);
            }
        }
        __syncthreads();

        // ---- softmax: warp owns rows 8*warp..+7; lane owns cols lane, lane+32 ----
        {
            const bool diag = (j == qtile);
            const float* Ss = (const float*)(sm + SS_OFF);
#pragma unroll
            for (int r = 0; r < 8; r++) {
                int row = warp * 8 + r;
                float v0 = Ss[row * 68 + lane] * scale;
                float v1 = Ss[row * 68 + lane + 32] * scale;
                if (diag) {
                    if (lane > row)      v0 = -INFINITY;
                    if (lane + 32 > row) v1 = -INFINITY;
                }
                float mt = fmaxf(v0, v1);
#pragma unroll
                for (int o = 16; o > 0; o >>= 1)
                    mt = fmaxf(mt, __shfl_xor_sync(0xffffffffu, mt, o));
                float mnew  = fmaxf(m_i[r], mt);
                float alpha = expf(m_i[r] - mnew);
                float p0 = expf(v0 - mnew);
                float p1 = expf(v1 - mnew);
                float ps = p0 + p1;
#pragma unroll
                for (int o = 16; o > 0; o >>= 1)
                    ps += __shfl_xor_sync(0xffffffffu, ps, o);
                l_i[r] = l_i[r] * alpha + ps;
                m_i[r] = mnew;
                // split P to bf16 hi/lo
                __nv_bfloat16 h0 = __float2bfloat16_rn(p0);
                __nv_bfloat16 h1 = __float2bfloat16_rn(p1);
                *(__nv_bfloat16*)(sm + PS0_OFF + (row*72 + lane)*2)      = h0;
                *(__nv_bfloat16*)(sm + PS0_OFF + (row*72 + lane + 32)*2) = h1;
                *(__nv_bfloat16*)(sm + PS1_OFF + (row*72 + lane)*2)      =
                    __float2bfloat16_rn(p0 - __bfloat162float(h0));
                *(__nv_bfloat16*)(sm + PS1_OFF + (row*72 + lane + 32)*2) =
                    __float2bfloat16_rn(p1 - __bfloat162float(h1));
                if (lane == 0) alpha_s[row] = alpha;
            }
        }
        __syncthreads();

        // ---- PV: warp tile 16q x 64d; rescale ctx then accumulate ----
        {
            const int d0 = wn * 64;
            float a0f = alpha_s[m0 + g];
            float a1f = alpha_s[m0 + g + 8];
#pragma unroll
            for (int nf = 0; nf < 8; nf++) {
                ctx[nf][0] *= a0f; ctx[nf][1] *= a0f;
                ctx[nf][2] *= a1f; ctx[nf][3] *= a1f;
            }
#pragma unroll
            for (int kk = 0; kk < 4; kk++) {
                int c = kk * 16 + 2 * t;
                unsigned pH[4], pL[4];
                pH[0] = *(const unsigned*)(sm + PS0_OFF + ((m0+g)*72 + c)*2);
                pH[1] = *(const unsigned*)(sm + PS0_OFF + ((m0+g+8)*72 + c)*2);
                pH[2] = *(const unsigned*)(sm + PS0_OFF + ((m0+g)*72 + c + 8)*2);
                pH[3] = *(const unsigned*)(sm + PS0_OFF + ((m0+g+8)*72 + c + 8)*2);
                pL[0] = *(const unsigned*)(sm + PS1_OFF + ((m0+g)*72 + c)*2);
                pL[1] = *(const unsigned*)(sm + PS1_OFF + ((m0+g+8)*72 + c)*2);
                pL[2] = *(const unsigned*)(sm + PS1_OFF + ((m0+g)*72 + c + 8)*2);
                pL[3] = *(const unsigned*)(sm + PS1_OFF + ((m0+g+8)*72 + c + 8)*2);
#pragma unroll
                for (int nf = 0; nf < 8; nf++) {
                    int n = d0 + nf * 8 + g;
                    unsigned vH[2], vL[2];
                    vH[0] = *(const unsigned*)(sm + VS0_OFF + (n*72 + c)*2);
                    vH[1] = *(const unsigned*)(sm + VS0_OFF + (n*72 + c + 8)*2);
                    vL[0] = *(const unsigned*)(sm + VS1_OFF + (n*72 + c)*2);
                    vL[1] = *(const unsigned*)(sm + VS1_OFF + (n*72 + c + 8)*2);
                    mma_bf16(ctx[nf], pH, vH);
                    mma_bf16(ctx[nf], pH, vL);
                    mma_bf16(ctx[nf], pL, vH);
                }
            }
        }
    }

    // ---- finalize: 1/l, write ctx ----
    __syncthreads();
#pragma unroll
    for (int r = 0; r < 8; r++)
        if (lane == 0) linv_s[warp * 8 + r] = 1.0f / l_i[r];
    __syncthreads();

    {
        const int d0 = wn * 64;
        float il0 = linv_s[m0 + g];
        float il1 = linv_s[m0 + g + 8];
        int q0 = qbase + m0 + g;
#pragma unroll
        for (int nf = 0; nf < 8; nf++) {
            int d = d0 + nf * 8 + 2 * t;
            float* o0 = g_C + (((size_t)(b * S_ + q0)) * NH_ + h) * D_ + d;
            float* o1 = g_C + (((size_t)(b * S_ + q0 + 8)) * NH_ + h) * D_ + d;
            *(float2*)o0 = make_float2(ctx[nf][0] * il0, ctx[nf][1] * il0);
            *(float2*)o1 = make_float2(ctx[nf][2] * il1, ctx[nf][3] * il1);
        }
    }
}

// ============================================================
// launch
// ============================================================
extern "C" void kernel_launch(void* const* d_in, const int* in_sizes, int n_in,
                              void* d_out, int out_size)
{
    (void)in_sizes; (void)n_in; (void)out_size;
    const float* hidden = (const float*)d_in[0];
    const float* Wq = (const float*)d_in[1];
    const float* bq = (const float*)d_in[2];
    const float* Wk = (const float*)d_in[3];
    const float* bk = (const float*)d_in[4];
    const float* Wv = (const float*)d_in[5];
    const float* bv = (const float*)d_in[6];
    const float* Wo = (const float*)d_in[7];
    float* out = (float*)d_out;

    float *qp, *kp, *vtp, *cp;
    cudaGetSymbolAddress((void**)&qp,  g_Q);
    cudaGetSymbolAddress((void**)&kp,  g_K);
    cudaGetSymbolAddress((void**)&vtp, g_Vt);
    cudaGetSymbolAddress((void**)&cp,  g_C);

    cudaFuncSetAttribute(flash_bf16,
        cudaFuncAttributeMaxDynamicSharedMemorySize, FLASH_SMEM);

    // 1: RoPE tables
    rope_table_kernel<<<(S_ * 64 + 255) / 256, 256>>>();
    // 2: Q projection
    gemm_tf32<<<dim3(HID_ / BN, BSR_ / BM), 256>>>(hidden, Wq, bq, qp, NH_ * D_, HID_);
    // 3: K + V projections (V written transposed)
    gemm_kv<<<dim3((NKV_ * D_) / BN, BSR_ / BM, 2), 256>>>(hidden, Wk, bk, Wv, bv, kp, vtp);
    // 4: flash attention (profiled launch)
    flash_bf16<<<dim3(S_ / 64, NH_, B_), 256, FLASH_SMEM>>>();
    // 5: O projection
    gemm_tf32<<<dim3(HID_ / BN, BSR_ / BM), 256>>>(cp, Wo, nullptr, out, HID_, NH_ * D_);
}

// round 4
// speedup vs baseline: 3.1895x; 1.1861x over previous
#include <cuda_runtime.h>
#include <cuda_bf16.h>
#include <math.h>

#define B_    2
#define S_    2048
#define HID_  2048
#define NH_   16
#define NKV_  8
#define D_    128
#define G_    (NH_/NKV_)
#define BSR_  (B_*S_)          // 4096 rows

// -------- scratch (no allocations allowed; __device__ globals) --------
__device__ float g_Q[BSR_ * NH_ * D_];    // unroped Q (rope fused into flash)
__device__ float g_K[BSR_ * NKV_ * D_];   // unroped K
__device__ float g_Vt[(size_t)B_ * NKV_ * D_ * S_];  // V transposed: [b][kvh][d][s]
__device__ float g_C[BSR_ * NH_ * D_];
__device__ float g_cos[S_ * 64];
__device__ float g_sin[S_ * 64];

// ============================================================
// TF32 tensor-core GEMM (validated R2/R3): C = A@W + bias
// ============================================================
#define BM 128
#define BN 128
#define BK 32
#define ASTR 36
#define BSTR 132

__device__ __forceinline__ unsigned f2tf(float x) {
    unsigned u;
    asm("cvt.rna.tf32.f32 %0, %1;" : "=r"(u) : "f"(x));
    return u;
}

__device__ __forceinline__ void mma_tf32(float* d, const unsigned* a, const unsigned* b) {
    asm volatile(
        "mma.sync.aligned.m16n8k8.row.col.f32.tf32.tf32.f32 "
        "{%0,%1,%2,%3}, {%4,%5,%6,%7}, {%8,%9}, {%0,%1,%2,%3};\n"
        : "+f"(d[0]), "+f"(d[1]), "+f"(d[2]), "+f"(d[3])
        : "r"(a[0]), "r"(a[1]), "r"(a[2]), "r"(a[3]), "r"(b[0]), "r"(b[1]));
}

__device__ __forceinline__ void gemm_core(
    const float* __restrict__ A, const float* __restrict__ W,
    int N, int K, float acc[4][4][4],
    unsigned* As, unsigned* Bs)
{
    const int tid  = threadIdx.x;
    const int lane = tid & 31;
    const int warp = tid >> 5;
    const int wm   = warp >> 2;
    const int wn   = warp & 3;

    const float* Ab = A + (size_t)blockIdx.y * BM * K;
    const float* Wb = W + (size_t)blockIdx.x * BN;

    const int arow = tid >> 3;
    const int acol = (tid & 7) << 2;
    const int bc4  = lane << 2;

    for (int k0 = 0; k0 < K; k0 += BK) {
        float4 av[4], bv[4];
#pragma unroll
        for (int p = 0; p < 4; p++)
            av[p] = *(const float4*)(Ab + (size_t)(arow + p * 32) * K + k0 + acol);
#pragma unroll
        for (int p = 0; p < 4; p++)
            bv[p] = *(const float4*)(Wb + (size_t)(k0 + warp + p * 8) * N + bc4);

        __syncthreads();
#pragma unroll
        for (int p = 0; p < 4; p++) {
            int base = (arow + p * 32) * ASTR + acol;
            As[base + 0] = f2tf(av[p].x);
            As[base + 1] = f2tf(av[p].y);
            As[base + 2] = f2tf(av[p].z);
            As[base + 3] = f2tf(av[p].w);
        }
#pragma unroll
        for (int p = 0; p < 4; p++) {
            int base = (warp + p * 8) * BSTR + bc4;
            Bs[base + 0] = f2tf(bv[p].x);
            Bs[base + 1] = f2tf(bv[p].y);
            Bs[base + 2] = f2tf(bv[p].z);
            Bs[base + 3] = f2tf(bv[p].w);
        }
        __syncthreads();

#pragma unroll
        for (int kk = 0; kk < BK; kk += 8) {
            unsigned a[4][4], b[4][2];
#pragma unroll
            for (int mf = 0; mf < 4; mf++) {
                int r = wm * 64 + mf * 16 + (lane >> 2);
                int c = kk + (lane & 3);
                a[mf][0] = As[r * ASTR + c];
                a[mf][1] = As[(r + 8) * ASTR + c];
                a[mf][2] = As[r * ASTR + c + 4];
                a[mf][3] = As[(r + 8) * ASTR + c + 4];
            }
#pragma unroll
            for (int nf = 0; nf < 4; nf++) {
                int n = wn * 32 + nf * 8 + (lane >> 2);
                b[nf][0] = Bs[(kk + (lane & 3)) * BSTR + n];
                b[nf][1] = Bs[(kk + 4 + (lane & 3)) * BSTR + n];
            }
#pragma unroll
            for (int mf = 0; mf < 4; mf++)
#pragma unroll
                for (int nf = 0; nf < 4; nf++)
                    mma_tf32(acc[mf][nf], a[mf], b[nf]);
        }
    }
}

__global__ __launch_bounds__(256, 2) void gemm_tf32(
    const float* __restrict__ A, const float* __restrict__ W,
    const float* __restrict__ bias, float* __restrict__ C,
    int N, int K)
{
    __shared__ unsigned As[BM * ASTR];
    __shared__ unsigned Bs[BK * BSTR];
    float acc[4][4][4];
#pragma unroll
    for (int i = 0; i < 4; i++)
#pragma unroll
        for (int j = 0; j < 4; j++)
#pragma unroll
            for (int e = 0; e < 4; e++) acc[i][j][e] = 0.0f;

    gemm_core(A, W, N, K, acc, As, Bs);

    const int lane = threadIdx.x & 31;
    const int warp = threadIdx.x >> 5;
    const int wm = warp >> 2, wn = warp & 3;
#pragma unroll
    for (int mf = 0; mf < 4; mf++) {
        int row = blockIdx.y * BM + wm * 64 + mf * 16 + (lane >> 2);
#pragma unroll
        for (int nf = 0; nf < 4; nf++) {
            int col = blockIdx.x * BN + wn * 32 + nf * 8 + 2 * (lane & 3);
            float b0 = 0.0f, b1 = 0.0f;
            if (bias) { b0 = bias[col]; b1 = bias[col + 1]; }
            *(float2*)&C[(size_t)row * N + col] =
                make_float2(acc[mf][nf][0] + b0, acc[mf][nf][1] + b1);
            *(float2*)&C[(size_t)(row + 8) * N + col] =
                make_float2(acc[mf][nf][2] + b0, acc[mf][nf][3] + b1);
        }
    }
}

__global__ __launch_bounds__(256, 2) void gemm_kv(
    const float* __restrict__ A,
    const float* __restrict__ Wk, const float* __restrict__ bk,
    const float* __restrict__ Wv, const float* __restrict__ bv,
    float* __restrict__ Kout, float* __restrict__ Vt)
{
    __shared__ unsigned As[BM * ASTR];
    __shared__ unsigned Bs[BK * BSTR];
    const int z = blockIdx.z;
    const float* W    = z ? Wv : Wk;
    const float* bias = z ? bv : bk;
    const int N = NKV_ * D_;
    const int K = HID_;

    float acc[4][4][4];
#pragma unroll
    for (int i = 0; i < 4; i++)
#pragma unroll
        for (int j = 0; j < 4; j++)
#pragma unroll
            for (int e = 0; e < 4; e++) acc[i][j][e] = 0.0f;

    gemm_core(A, W, N, K, acc, As, Bs);

    const int lane = threadIdx.x & 31;
    const int warp = threadIdx.x >> 5;
    const int wm = warp >> 2, wn = warp & 3;
#pragma unroll
    for (int mf = 0; mf < 4; mf++) {
        int row = blockIdx.y * BM + wm * 64 + mf * 16 + (lane >> 2);
#pragma unroll
        for (int nf = 0; nf < 4; nf++) {
            int col = blockIdx.x * BN + wn * 32 + nf * 8 + 2 * (lane & 3);
            float b0 = bias[col], b1 = bias[col + 1];
            float v00 = acc[mf][nf][0] + b0, v01 = acc[mf][nf][1] + b1;
            float v10 = acc[mf][nf][2] + b0, v11 = acc[mf][nf][3] + b1;
            if (z == 0) {
                *(float2*)&Kout[(size_t)row * N + col]       = make_float2(v00, v01);
                *(float2*)&Kout[(size_t)(row + 8) * N + col] = make_float2(v10, v11);
            } else {
                int bb = row >> 11, s = row & 2047;
                int kvh = col >> 7, d = col & 127;
                size_t base = ((size_t)(bb * NKV_ + kvh) * D_ + d) * S_;
                Vt[base + s]            = v00;
                Vt[base + S_ + s]       = v01;
                Vt[base + s + 8]        = v10;
                Vt[base + S_ + s + 8]   = v11;
            }
        }
    }
}

// ============================================================
// RoPE tables
// ============================================================
__global__ void rope_table_kernel()
{
    int idx = blockIdx.x * blockDim.x + threadIdx.x;
    if (idx >= S_ * 64) return;
    int s = idx >> 6, i = idx & 63;
    const double NEG_LOG_STEP = -0.2158673524681918;
    double freq = exp((double)i * NEG_LOG_STEP);
    double sd, cd;
    sincos((double)s * freq, &sd, &cd);
    g_cos[idx] = (float)cd;
    g_sin[idx] = (float)sd;
}

// ============================================================
// Flash attention v2: 128q-tile, register-resident softmax + P,
// 3xBF16 tensor cores, 2 syncs per k-tile (loads only).
// 8 warps; warp w owns q rows [16w,16w+16) x all 64 keys.
// ============================================================
#define BQ 128
#define QH_OFF 0
#define QL_OFF (QH_OFF + BQ*136*2)
#define KH_OFF (QL_OFF + BQ*136*2)
#define KL_OFF (KH_OFF + 64*136*2)
#define VH_OFF (KL_OFF + 64*136*2)
#define VL_OFF (VH_OFF + 128*72*2)
#define FLASH_SMEM (VL_OFF + 128*72*2)   // 141,312 B

__device__ __forceinline__ void mma_bf16(float* d, const unsigned* a, const unsigned* b) {
    asm volatile(
        "mma.sync.aligned.m16n8k16.row.col.f32.bf16.bf16.f32 "
        "{%0,%1,%2,%3}, {%4,%5,%6,%7}, {%8,%9}, {%0,%1,%2,%3};\n"
        : "+f"(d[0]), "+f"(d[1]), "+f"(d[2]), "+f"(d[3])
        : "r"(a[0]), "r"(a[1]), "r"(a[2]), "r"(a[3]), "r"(b[0]), "r"(b[1]));
}

__device__ __forceinline__ void split2(float x, float y, unsigned& hi, unsigned& lo) {
    __nv_bfloat16 hx = __float2bfloat16_rn(x);
    __nv_bfloat16 hy = __float2bfloat16_rn(y);
    float rx = x - __bfloat162float(hx);
    float ry = y - __bfloat162float(hy);
    __nv_bfloat162 h; h.x = hx; h.y = hy;
    __nv_bfloat162 l; l.x = __float2bfloat16_rn(rx); l.y = __float2bfloat16_rn(ry);
    hi = *(unsigned*)&h;
    lo = *(unsigned*)&l;
}

__global__ __launch_bounds__(256, 1) void flash_bf16()
{
    extern __shared__ char sm[];
    const int tid  = threadIdx.x;
    const int lane = tid & 31;
    const int warp = tid >> 5;
    const int qtile = (gridDim.x - 1) - blockIdx.x;   // heavy tiles first
    const int h    = blockIdx.y;
    const int b    = blockIdx.z;
    const int kvh  = h / G_;
    const int qbase = qtile * BQ;
    const float scale = 0.08838834764831845f;
    const int g = lane >> 2;
    const int t = lane & 3;
    const int m0 = warp * 16;

    // ---- load Q tile (RoPE + split), STS.64 ----
    for (int it = tid; it < BQ * 16; it += 256) {
        int r  = it >> 4;
        int c4 = (it & 15) << 2;
        int s  = qbase + r;
        const float* qrow = g_Q + (((size_t)(b * S_ + s)) * NH_ + h) * D_;
        float4 qa = *(const float4*)(qrow + c4);
        float4 qb = *(const float4*)(qrow + c4 + 64);
        float4 cz = *(const float4*)(g_cos + s * 64 + c4);
        float4 sz = *(const float4*)(g_sin + s * 64 + c4);
        float4 oa = make_float4(qa.x*cz.x - qb.x*sz.x, qa.y*cz.y - qb.y*sz.y,
                                qa.z*cz.z - qb.z*sz.z, qa.w*cz.w - qb.w*sz.w);
        float4 ob = make_float4(qb.x*cz.x + qa.x*sz.x, qb.y*cz.y + qa.y*sz.y,
                                qb.z*cz.z + qa.z*sz.z, qb.w*cz.w + qa.w*sz.w);
        uint2 hv, lv;
        int base = (r * 136 + c4) * 2;
        split2(oa.x, oa.y, hv.x, lv.x); split2(oa.z, oa.w, hv.y, lv.y);
        *(uint2*)(sm + QH_OFF + base) = hv;
        *(uint2*)(sm + QL_OFF + base) = lv;
        base = (r * 136 + c4 + 64) * 2;
        split2(ob.x, ob.y, hv.x, lv.x); split2(ob.z, ob.w, hv.y, lv.y);
        *(uint2*)(sm + QH_OFF + base) = hv;
        *(uint2*)(sm + QL_OFF + base) = lv;
    }

    float ctx[16][4];
#pragma unroll
    for (int i = 0; i < 16; i++)
#pragma unroll
        for (int e = 0; e < 4; e++) ctx[i][e] = 0.0f;
    float mr0 = -INFINITY, mr1 = -INFINITY, lr0 = 0.0f, lr1 = 0.0f;

    const int row0 = qbase + m0 + g;
    const int row1 = row0 + 8;
    const int ntile = 2 * qtile + 2;

    for (int j = 0; j < ntile; j++) {
        const int kb = j * 64;
        __syncthreads();   // all warps done reading prev K/V

        // ---- K tile (RoPE + split) ----
        for (int it = tid; it < 64 * 16; it += 256) {
            int r  = it >> 4;
            int c4 = (it & 15) << 2;
            int s  = kb + r;
            const float* krow = g_K + (((size_t)(b * S_ + s)) * NKV_ + kvh) * D_;
            float4 ka  = *(const float4*)(krow + c4);
            float4 kb4 = *(const float4*)(krow + c4 + 64);
            float4 cz  = *(const float4*)(g_cos + s * 64 + c4);
            float4 sz  = *(const float4*)(g_sin + s * 64 + c4);
            float4 oa = make_float4(ka.x*cz.x - kb4.x*sz.x, ka.y*cz.y - kb4.y*sz.y,
                                    ka.z*cz.z - kb4.z*sz.z, ka.w*cz.w - kb4.w*sz.w);
            float4 ob = make_float4(kb4.x*cz.x + ka.x*sz.x, kb4.y*cz.y + ka.y*sz.y,
                                    kb4.z*cz.z + ka.z*sz.z, kb4.w*cz.w + ka.w*sz.w);
            uint2 hv, lv;
            int base = (r * 136 + c4) * 2;
            split2(oa.x, oa.y, hv.x, lv.x); split2(oa.z, oa.w, hv.y, lv.y);
            *(uint2*)(sm + KH_OFF + base) = hv;
            *(uint2*)(sm + KL_OFF + base) = lv;
            base = (r * 136 + c4 + 64) * 2;
            split2(ob.x, ob.y, hv.x, lv.x); split2(ob.z, ob.w, hv.y, lv.y);
            *(uint2*)(sm + KH_OFF + base) = hv;
            *(uint2*)(sm + KL_OFF + base) = lv;
        }
        // ---- V tile from g_Vt [d][s] ----
        for (int it = tid; it < 128 * 16; it += 256) {
            int d  = it >> 4;
            int c4 = (it & 15) << 2;
            const float* vrow = g_Vt + ((size_t)(b * NKV_ + kvh) * D_ + d) * S_ + kb;
            float4 v = *(const float4*)(vrow + c4);
            uint2 hv, lv;
            split2(v.x, v.y, hv.x, lv.x); split2(v.z, v.w, hv.y, lv.y);
            int base = (d * 72 + c4) * 2;
            *(uint2*)(sm + VH_OFF + base) = hv;
            *(uint2*)(sm + VL_OFF + base) = lv;
        }
        __syncthreads();

        // ---- QK: 16q x 64keys per warp ----
        float acc[8][4];
#pragma unroll
        for (int nf = 0; nf < 8; nf++)
#pragma unroll
            for (int e = 0; e < 4; e++) acc[nf][e] = 0.0f;

#pragma unroll
        for (int kk = 0; kk < 8; kk++) {
            int c = kk * 16 + 2 * t;
            unsigned aH[4], aL[4];
            aH[0] = *(const unsigned*)(sm + QH_OFF + ((m0+g)*136 + c)*2);
            aH[1] = *(const unsigned*)(sm + QH_OFF + ((m0+g+8)*136 + c)*2);
            aH[2] = *(const unsigned*)(sm + QH_OFF + ((m0+g)*136 + c + 8)*2);
            aH[3] = *(const unsigned*)(sm + QH_OFF + ((m0+g+8)*136 + c + 8)*2);
            aL[0] = *(const unsigned*)(sm + QL_OFF + ((m0+g)*136 + c)*2);
            aL[1] = *(const unsigned*)(sm + QL_OFF + ((m0+g+8)*136 + c)*2);
            aL[2] = *(const unsigned*)(sm + QL_OFF + ((m0+g)*136 + c + 8)*2);
            aL[3] = *(const unsigned*)(sm + QL_OFF + ((m0+g+8)*136 + c + 8)*2);
#pragma unroll
            for (int nf = 0; nf < 8; nf++) {
                int n = nf * 8 + g;
                unsigned bH[2], bL[2];
                bH[0] = *(const unsigned*)(sm + KH_OFF + (n*136 + c)*2);
                bH[1] = *(const unsigned*)(sm + KH_OFF + (n*136 + c + 8)*2);
                bL[0] = *(const unsigned*)(sm + KL_OFF + (n*136 + c)*2);
                bL[1] = *(const unsigned*)(sm + KL_OFF + (n*136 + c + 8)*2);
                mma_bf16(acc[nf], aH, bH);
                mma_bf16(acc[nf], aH, bL);
                mma_bf16(acc[nf], aL, bH);
            }
        }

        // ---- scale + causal mask (warp-uniform branch) ----
#pragma unroll
        for (int nf = 0; nf < 8; nf++)
#pragma unroll
            for (int e = 0; e < 4; e++) acc[nf][e] *= scale;

        if (kb + 63 > qbase + m0) {
#pragma unroll
            for (int nf = 0; nf < 8; nf++) {
                int k0 = kb + nf * 8 + 2 * t;
                if (k0     > row0) acc[nf][0] = -INFINITY;
                if (k0 + 1 > row0) acc[nf][1] = -INFINITY;
                if (k0     > row1) acc[nf][2] = -INFINITY;
                if (k0 + 1 > row1) acc[nf][3] = -INFINITY;
            }
        }

        // ---- in-register softmax (quad shuffles) ----
        float mx0 = -INFINITY, mx1 = -INFINITY;
#pragma unroll
        for (int nf = 0; nf < 8; nf++) {
            mx0 = fmaxf(mx0, fmaxf(acc[nf][0], acc[nf][1]));
            mx1 = fmaxf(mx1, fmaxf(acc[nf][2], acc[nf][3]));
        }
        mx0 = fmaxf(mx0, __shfl_xor_sync(0xffffffffu, mx0, 1));
        mx0 = fmaxf(mx0, __shfl_xor_sync(0xffffffffu, mx0, 2));
        mx1 = fmaxf(mx1, __shfl_xor_sync(0xffffffffu, mx1, 1));
        mx1 = fmaxf(mx1, __shfl_xor_sync(0xffffffffu, mx1, 2));

        float mn0 = fmaxf(mr0, mx0);
        float mn1 = fmaxf(mr1, mx1);
        float al0 = __expf(mr0 - mn0);
        float al1 = __expf(mr1 - mn1);
        mr0 = mn0; mr1 = mn1;

        unsigned pH[4][4], pL[4][4];
        float s0 = 0.0f, s1 = 0.0f;
#pragma unroll
        for (int nf = 0; nf < 8; nf++) {
            float p00 = __expf(acc[nf][0] - mn0);
            float p01 = __expf(acc[nf][1] - mn0);
            float p10 = __expf(acc[nf][2] - mn1);
            float p11 = __expf(acc[nf][3] - mn1);
            s0 += p00 + p01;
            s1 += p10 + p11;
            int kk2 = nf >> 1;
            int sl  = (nf & 1) << 1;    // 0 or 2
            split2(p00, p01, pH[kk2][sl],     pL[kk2][sl]);
            split2(p10, p11, pH[kk2][sl + 1], pL[kk2][sl + 1]);
        }
        s0 += __shfl_xor_sync(0xffffffffu, s0, 1);
        s0 += __shfl_xor_sync(0xffffffffu, s0, 2);
        s1 += __shfl_xor_sync(0xffffffffu, s1, 1);
        s1 += __shfl_xor_sync(0xffffffffu, s1, 2);
        lr0 = lr0 * al0 + s0;
        lr1 = lr1 * al1 + s1;

        // ---- rescale ctx, PV ----
#pragma unroll
        for (int nf = 0; nf < 16; nf++) {
            ctx[nf][0] *= al0; ctx[nf][1] *= al0;
            ctx[nf][2] *= al1; ctx[nf][3] *= al1;
        }
#pragma unroll
        for (int kk2 = 0; kk2 < 4; kk2++) {
            int c = kk2 * 16 + 2 * t;
#pragma unroll
            for (int nf = 0; nf < 16; nf++) {
                int n = nf * 8 + g;
                unsigned vH[2], vL[2];
                vH[0] = *(const unsigned*)(sm + VH_OFF + (n*72 + c)*2);
                vH[1] = *(const unsigned*)(sm + VH_OFF + (n*72 + c + 8)*2);
                vL[0] = *(const unsigned*)(sm + VL_OFF + (n*72 + c)*2);
                vL[1] = *(const unsigned*)(sm + VL_OFF + (n*72 + c + 8)*2);
                mma_bf16(ctx[nf], pH[kk2], vH);
                mma_bf16(ctx[nf], pL[kk2], vH);
                mma_bf16(ctx[nf], pH[kk2], vL);
            }
        }
    }

    // ---- finalize ----
    float il0 = 1.0f / lr0;
    float il1 = 1.0f / lr1;
    float* o0 = g_C + (((size_t)(b * S_ + row0)) * NH_ + h) * D_;
    float* o1 = g_C + (((size_t)(b * S_ + row1)) * NH_ + h) * D_;
#pragma unroll
    for (int nf = 0; nf < 16; nf++) {
        int d = nf * 8 + 2 * t;
        *(float2*)(o0 + d) = make_float2(ctx[nf][0] * il0, ctx[nf][1] * il0);
        *(float2*)(o1 + d) = make_float2(ctx[nf][2] * il1, ctx[nf][3] * il1);
    }
}

// ============================================================
// launch
// ============================================================
extern "C" void kernel_launch(void* const* d_in, const int* in_sizes, int n_in,
                              void* d_out, int out_size)
{
    (void)in_sizes; (void)n_in; (void)out_size;
    const float* hidden = (const float*)d_in[0];
    const float* Wq = (const float*)d_in[1];
    const float* bq = (const float*)d_in[2];
    const float* Wk = (const float*)d_in[3];
    const float* bk = (const float*)d_in[4];
    const float* Wv = (const float*)d_in[5];
    const float* bv = (const float*)d_in[6];
    const float* Wo = (const float*)d_in[7];
    float* out = (float*)d_out;

    float *qp, *kp, *vtp, *cp;
    cudaGetSymbolAddress((void**)&qp,  g_Q);
    cudaGetSymbolAddress((void**)&kp,  g_K);
    cudaGetSymbolAddress((void**)&vtp, g_Vt);
    cudaGetSymbolAddress((void**)&cp,  g_C);

    cudaFuncSetAttribute(flash_bf16,
        cudaFuncAttributeMaxDynamicSharedMemorySize, FLASH_SMEM);

    // 1: RoPE tables
    rope_table_kernel<<<(S_ * 64 + 255) / 256, 256>>>();
    // 2: Q projection
    gemm_tf32<<<dim3(HID_ / BN, BSR_ / BM), 256>>>(hidden, Wq, bq, qp, NH_ * D_, HID_);
    // 3: K + V projections (V written transposed)
    gemm_kv<<<dim3((NKV_ * D_) / BN, BSR_ / BM, 2), 256>>>(hidden, Wk, bk, Wv, bv, kp, vtp);
    // 4: flash attention (profiled launch)
    flash_bf16<<<dim3(S_ / BQ, NH_, B_), 256, FLASH_SMEM>>>();
    // 5: O projection
    gemm_tf32<<<dim3(HID_ / BN, BSR_ / BM), 256>>>(cp, Wo, nullptr, out, HID_, NH_ * D_);
}

// round 5
// speedup vs baseline: 3.7425x; 1.1734x over previous
#include <cuda_runtime.h>
#include <cuda_bf16.h>
#include <math.h>

#define B_    2
#define S_    2048
#define HID_  2048
#define NH_   16
#define NKV_  8
#define D_    128
#define G_    (NH_/NKV_)
#define BSR_  (B_*S_)          // 4096

// -------- scratch (__device__ globals; no allocations) --------
__device__ float    g_Q [BSR_ * NH_ * D_];          // f32 Q (pre-rope)
__device__ float    g_K [BSR_ * NKV_ * D_];         // f32 K (pre-rope)
__device__ unsigned g_Ct[BSR_ * NH_ * D_];          // ctx as tf32 bits
__device__ __nv_bfloat16 g_Qh[BSR_ * NH_ * D_];     // roped Q hi/lo
__device__ __nv_bfloat16 g_Ql[BSR_ * NH_ * D_];
__device__ __nv_bfloat16 g_Kh[BSR_ * NKV_ * D_];    // roped K hi/lo
__device__ __nv_bfloat16 g_Kl[BSR_ * NKV_ * D_];
__device__ __nv_bfloat16 g_Vth[(size_t)B_ * NKV_ * D_ * S_];  // V^T hi/lo [b][kvh][d][s]
__device__ __nv_bfloat16 g_Vtl[(size_t)B_ * NKV_ * D_ * S_];
__device__ unsigned g_Xt [BSR_ * HID_];             // hidden as tf32 bits
__device__ unsigned g_Wqt[HID_ * NH_ * D_];
__device__ unsigned g_Wkt[HID_ * NKV_ * D_];
__device__ unsigned g_Wvt[HID_ * NKV_ * D_];
__device__ unsigned g_Wot[NH_ * D_ * HID_];
__device__ float g_cos[S_ * 64];
__device__ float g_sin[S_ * 64];

// ---------------- helpers ----------------
__device__ __forceinline__ unsigned f2tf(float x) {
    unsigned u;
    asm("cvt.rna.tf32.f32 %0, %1;" : "=r"(u) : "f"(x));
    return u;
}
__device__ __forceinline__ void cp16(unsigned dst, const void* src) {
    asm volatile("cp.async.cg.shared.global [%0], [%1], 16;" :: "r"(dst), "l"(src));
}
__device__ __forceinline__ void cp_commit() { asm volatile("cp.async.commit_group;"); }
__device__ __forceinline__ void cp_wait1()  { asm volatile("cp.async.wait_group 1;"); }
__device__ __forceinline__ void cp_wait0()  { asm volatile("cp.async.wait_group 0;"); }

__device__ __forceinline__ void mma_tf32(float* d, const unsigned* a, const unsigned* b) {
    asm volatile(
        "mma.sync.aligned.m16n8k8.row.col.f32.tf32.tf32.f32 "
        "{%0,%1,%2,%3}, {%4,%5,%6,%7}, {%8,%9}, {%0,%1,%2,%3};\n"
        : "+f"(d[0]), "+f"(d[1]), "+f"(d[2]), "+f"(d[3])
        : "r"(a[0]), "r"(a[1]), "r"(a[2]), "r"(a[3]), "r"(b[0]), "r"(b[1]));
}
__device__ __forceinline__ void mma_bf16(float* d, const unsigned* a, const unsigned* b) {
    asm volatile(
        "mma.sync.aligned.m16n8k16.row.col.f32.bf16.bf16.f32 "
        "{%0,%1,%2,%3}, {%4,%5,%6,%7}, {%8,%9}, {%0,%1,%2,%3};\n"
        : "+f"(d[0]), "+f"(d[1]), "+f"(d[2]), "+f"(d[3])
        : "r"(a[0]), "r"(a[1]), "r"(a[2]), "r"(a[3]), "r"(b[0]), "r"(b[1]));
}

// ============================================================
// prep: convert hidden + weights to tf32 bit buffers
// ============================================================
__global__ void prep_tf32(const float* __restrict__ hidden,
                          const float* __restrict__ Wq, const float* __restrict__ Wk,
                          const float* __restrict__ Wv, const float* __restrict__ Wo)
{
    const int NV_H  = (BSR_ * HID_) / 4;
    const int NV_WQ = (HID_ * NH_ * D_) / 4;
    const int NV_WK = (HID_ * NKV_ * D_) / 4;
    const int NV_WV = NV_WK;
    const int NV_WO = (NH_ * D_ * HID_) / 4;
    const int total = NV_H + NV_WQ + NV_WK + NV_WV + NV_WO;
    int idx = blockIdx.x * blockDim.x + threadIdx.x;
    if (idx >= total) return;
    const float4* src; uint4* dst; int off;
    if (idx < NV_H) { src = (const float4*)hidden; dst = (uint4*)g_Xt;  off = idx; }
    else if (idx < NV_H + NV_WQ) { src = (const float4*)Wq; dst = (uint4*)g_Wqt; off = idx - NV_H; }
    else if (idx < NV_H + NV_WQ + NV_WK) { src = (const float4*)Wk; dst = (uint4*)g_Wkt; off = idx - NV_H - NV_WQ; }
    else if (idx < NV_H + NV_WQ + NV_WK + NV_WV) { src = (const float4*)Wv; dst = (uint4*)g_Wvt; off = idx - NV_H - NV_WQ - NV_WK; }
    else { src = (const float4*)Wo; dst = (uint4*)g_Wot; off = idx - NV_H - NV_WQ - NV_WK - NV_WV; }
    float4 v = src[off];
    dst[off] = make_uint4(f2tf(v.x), f2tf(v.y), f2tf(v.z), f2tf(v.w));
}

// ============================================================
// TF32 GEMM v2: cp.async 2-stage pipeline, pre-converted inputs
// ============================================================
#define BM 128
#define BN 128
#define BK 32
#define ASTR 36
#define BSTR 132
#define AS_BYTES (BM*ASTR*4)                 // 18432
#define BS_BYTES (BK*BSTR*4)                 // 16896
#define GEMM_SMEM (2*(AS_BYTES+BS_BYTES))    // 70656

__device__ __forceinline__ void gemm_issue(
    unsigned sbase, int stage, const unsigned* __restrict__ Ab,
    const unsigned* __restrict__ Wb, int k0, int N, int K, int tid)
{
    unsigned sA = sbase + stage * AS_BYTES;
    unsigned sB = sbase + 2 * AS_BYTES + stage * BS_BYTES;
#pragma unroll
    for (int p = 0; p < 4; p++) {
        int id = tid + p * 256;
        int r = id >> 3, c = (id & 7) << 2;
        cp16(sA + (r * ASTR + c) * 4, Ab + (size_t)r * K + k0 + c);
    }
#pragma unroll
    for (int p = 0; p < 4; p++) {
        int id = tid + p * 256;
        int r = id >> 5, c = (id & 31) << 2;
        cp16(sB + (r * BSTR + c) * 4, Wb + (size_t)(k0 + r) * N + c);
    }
    cp_commit();
}

__device__ __forceinline__ void gemm_compute(
    const unsigned* __restrict__ As, const unsigned* __restrict__ Bs,
    float acc[4][4][4], int lane, int wm, int wn)
{
#pragma unroll
    for (int kk = 0; kk < BK; kk += 8) {
        unsigned a[4][4], b[4][2];
#pragma unroll
        for (int mf = 0; mf < 4; mf++) {
            int r = wm * 64 + mf * 16 + (lane >> 2);
            int c = kk + (lane & 3);
            a[mf][0] = As[r * ASTR + c];
            a[mf][1] = As[(r + 8) * ASTR + c];
            a[mf][2] = As[r * ASTR + c + 4];
            a[mf][3] = As[(r + 8) * ASTR + c + 4];
        }
#pragma unroll
        for (int nf = 0; nf < 4; nf++) {
            int n = wn * 32 + nf * 8 + (lane >> 2);
            b[nf][0] = Bs[(kk + (lane & 3)) * BSTR + n];
            b[nf][1] = Bs[(kk + 4 + (lane & 3)) * BSTR + n];
        }
#pragma unroll
        for (int mf = 0; mf < 4; mf++)
#pragma unroll
            for (int nf = 0; nf < 4; nf++)
                mma_tf32(acc[mf][nf], a[mf], b[nf]);
    }
}

__device__ __forceinline__ void gemm_main(
    const unsigned* __restrict__ A, const unsigned* __restrict__ W,
    int N, int K, float acc[4][4][4], char* smem)
{
    const int tid  = threadIdx.x;
    const int lane = tid & 31;
    const int wm   = (tid >> 5) >> 2;
    const int wn   = (tid >> 5) & 3;
    unsigned sbase = (unsigned)__cvta_generic_to_shared(smem);
    const unsigned* Ab = A + (size_t)blockIdx.y * BM * K;
    const unsigned* Wb = W + (size_t)blockIdx.x * BN;

    gemm_issue(sbase, 0, Ab, Wb, 0, N, K, tid);
    const int niter = K / BK;
    for (int i = 0; i < niter; i++) {
        if (i + 1 < niter) {
            gemm_issue(sbase, (i + 1) & 1, Ab, Wb, (i + 1) * BK, N, K, tid);
            cp_wait1();
        } else {
            cp_wait0();
        }
        __syncthreads();
        const unsigned* As = (const unsigned*)(smem + (i & 1) * AS_BYTES);
        const unsigned* Bs = (const unsigned*)(smem + 2 * AS_BYTES + (i & 1) * BS_BYTES);
        gemm_compute(As, Bs, acc, lane, wm, wn);
        __syncthreads();
    }
}

__global__ __launch_bounds__(256, 2) void gemm_v2(
    const unsigned* __restrict__ A, const unsigned* __restrict__ W,
    const float* __restrict__ bias, float* __restrict__ C, int N, int K)
{
    extern __shared__ char smem[];
    float acc[4][4][4];
#pragma unroll
    for (int i = 0; i < 4; i++)
#pragma unroll
        for (int j = 0; j < 4; j++)
#pragma unroll
            for (int e = 0; e < 4; e++) acc[i][j][e] = 0.0f;

    gemm_main(A, W, N, K, acc, smem);

    const int lane = threadIdx.x & 31;
    const int warp = threadIdx.x >> 5;
    const int wm = warp >> 2, wn = warp & 3;
#pragma unroll
    for (int mf = 0; mf < 4; mf++) {
        int row = blockIdx.y * BM + wm * 64 + mf * 16 + (lane >> 2);
#pragma unroll
        for (int nf = 0; nf < 4; nf++) {
            int col = blockIdx.x * BN + wn * 32 + nf * 8 + 2 * (lane & 3);
            float b0 = 0.0f, b1 = 0.0f;
            if (bias) { b0 = bias[col]; b1 = bias[col + 1]; }
            *(float2*)&C[(size_t)row * N + col] =
                make_float2(acc[mf][nf][0] + b0, acc[mf][nf][1] + b1);
            *(float2*)&C[(size_t)(row + 8) * N + col] =
                make_float2(acc[mf][nf][2] + b0, acc[mf][nf][3] + b1);
        }
    }
}

// K + V in one launch; V epilogue writes bf16 hi/lo transposed
__global__ __launch_bounds__(256, 2) void gemm_kv_v2(
    const unsigned* __restrict__ A,
    const float* __restrict__ bk, const float* __restrict__ bv,
    float* __restrict__ Kout)
{
    extern __shared__ char smem[];
    const int z = blockIdx.z;
    const unsigned* W    = z ? g_Wvt : g_Wkt;
    const float*    bias = z ? bv : bk;
    const int N = NKV_ * D_;
    const int K = HID_;

    float acc[4][4][4];
#pragma unroll
    for (int i = 0; i < 4; i++)
#pragma unroll
        for (int j = 0; j < 4; j++)
#pragma unroll
            for (int e = 0; e < 4; e++) acc[i][j][e] = 0.0f;

    gemm_main(A, W, N, K, acc, smem);

    const int lane = threadIdx.x & 31;
    const int warp = threadIdx.x >> 5;
    const int wm = warp >> 2, wn = warp & 3;
#pragma unroll
    for (int mf = 0; mf < 4; mf++) {
        int row = blockIdx.y * BM + wm * 64 + mf * 16 + (lane >> 2);
#pragma unroll
        for (int nf = 0; nf < 4; nf++) {
            int col = blockIdx.x * BN + wn * 32 + nf * 8 + 2 * (lane & 3);
            float b0 = bias[col], b1 = bias[col + 1];
            float v00 = acc[mf][nf][0] + b0, v01 = acc[mf][nf][1] + b1;
            float v10 = acc[mf][nf][2] + b0, v11 = acc[mf][nf][3] + b1;
            if (z == 0) {
                *(float2*)&Kout[(size_t)row * N + col]       = make_float2(v00, v01);
                *(float2*)&Kout[(size_t)(row + 8) * N + col] = make_float2(v10, v11);
            } else {
                int bb = row >> 11, s = row & 2047;
                int kvh = col >> 7, d = col & 127;
                size_t base = ((size_t)(bb * NKV_ + kvh) * D_ + d) * S_;
                __nv_bfloat16 h;
                h = __float2bfloat16_rn(v00);
                g_Vth[base + s] = h;
                g_Vtl[base + s] = __float2bfloat16_rn(v00 - __bfloat162float(h));
                h = __float2bfloat16_rn(v01);
                g_Vth[base + S_ + s] = h;
                g_Vtl[base + S_ + s] = __float2bfloat16_rn(v01 - __bfloat162float(h));
                h = __float2bfloat16_rn(v10);
                g_Vth[base + s + 8] = h;
                g_Vtl[base + s + 8] = __float2bfloat16_rn(v10 - __bfloat162float(h));
                h = __float2bfloat16_rn(v11);
                g_Vth[base + S_ + s + 8] = h;
                g_Vtl[base + S_ + s + 8] = __float2bfloat16_rn(v11 - __bfloat162float(h));
            }
        }
    }
}

// ============================================================
// RoPE tables + rope/split pass for Q,K
// ============================================================
__global__ void rope_table_kernel()
{
    int idx = blockIdx.x * blockDim.x + threadIdx.x;
    if (idx >= S_ * 64) return;
    int s = idx >> 6, i = idx & 63;
    const double NEG_LOG_STEP = -0.2158673524681918;
    double freq = exp((double)i * NEG_LOG_STEP);
    double sd, cd;
    sincos((double)s * freq, &sd, &cd);
    g_cos[idx] = (float)cd;
    g_sin[idx] = (float)sd;
}

__global__ void rope_split_kernel()
{
    __shared__ float sc[64], ss[64];
    const int bs = blockIdx.x;
    const int s  = bs % S_;
    if (threadIdx.x < 64) {
        sc[threadIdx.x] = g_cos[s * 64 + threadIdx.x];
        ss[threadIdx.x] = g_sin[s * 64 + threadIdx.x];
    }
    __syncthreads();

    for (int p = threadIdx.x; p < (NH_ + NKV_) * 64; p += blockDim.x) {
        int head = p >> 6;
        int i    = p & 63;
        float c = sc[i], sn = ss[i];
        if (head < NH_) {
            size_t base = ((size_t)bs * NH_ + head) * D_;
            float x1 = g_Q[base + i], x2 = g_Q[base + i + 64];
            float o1 = x1 * c - x2 * sn;
            float o2 = x2 * c + x1 * sn;
            __nv_bfloat16 h1 = __float2bfloat16_rn(o1);
            __nv_bfloat16 h2 = __float2bfloat16_rn(o2);
            g_Qh[base + i]      = h1;
            g_Ql[base + i]      = __float2bfloat16_rn(o1 - __bfloat162float(h1));
            g_Qh[base + i + 64] = h2;
            g_Ql[base + i + 64] = __float2bfloat16_rn(o2 - __bfloat162float(h2));
        } else {
            size_t base = ((size_t)bs * NKV_ + (head - NH_)) * D_;
            float x1 = g_K[base + i], x2 = g_K[base + i + 64];
            float o1 = x1 * c - x2 * sn;
            float o2 = x2 * c + x1 * sn;
            __nv_bfloat16 h1 = __float2bfloat16_rn(o1);
            __nv_bfloat16 h2 = __float2bfloat16_rn(o2);
            g_Kh[base + i]      = h1;
            g_Kl[base + i]      = __float2bfloat16_rn(o1 - __bfloat162float(h1));
            g_Kh[base + i + 64] = h2;
            g_Kl[base + i + 64] = __float2bfloat16_rn(o2 - __bfloat162float(h2));
        }
    }
}

// ============================================================
// Flash attention v3: pre-split bf16 operands, cp.async
// double-buffered K/V, register softmax/P (R4 core).
// ============================================================
#define BQ 128
#define QH_OFF 0
#define QL_OFF (QH_OFF + BQ*136*2)            // 34816
#define ST0_OFF (QL_OFF + BQ*136*2)           // 69632
#define KH_SZ (64*136*2)                      // 17408
#define VH_SZ (128*72*2)                      // 18432
#define STAGE_SZ (2*KH_SZ + 2*VH_SZ)          // 71680
#define FLASH_SMEM (ST0_OFF + 2*STAGE_SZ)     // 212992

__device__ __forceinline__ void split2(float x, float y, unsigned& hi, unsigned& lo) {
    __nv_bfloat16 hx = __float2bfloat16_rn(x);
    __nv_bfloat16 hy = __float2bfloat16_rn(y);
    float rx = x - __bfloat162float(hx);
    float ry = y - __bfloat162float(hy);
    __nv_bfloat162 h; h.x = hx; h.y = hy;
    __nv_bfloat162 l; l.x = __float2bfloat16_rn(rx); l.y = __float2bfloat16_rn(ry);
    hi = *(unsigned*)&h;
    lo = *(unsigned*)&l;
}

__device__ __forceinline__ void flash_issue(
    unsigned sbase, int stage, int b, int kvh, int kb, int tid)
{
    unsigned st = sbase + ST0_OFF + stage * STAGE_SZ;
#pragma unroll
    for (int p = 0; p < 4; p++) {
        int id = tid + p * 256;
        int r = id >> 4, c8 = (id & 15) << 3;
        size_t go = (((size_t)(b * S_ + kb + r)) * NKV_ + kvh) * D_ + c8;
        unsigned so = st + (r * 136 + c8) * 2;
        cp16(so,         g_Kh + go);
        cp16(so + KH_SZ, g_Kl + go);
    }
#pragma unroll
    for (int p = 0; p < 4; p++) {
        int id = tid + p * 256;
        int d = id >> 3, c8 = (id & 7) << 3;
        size_t go = ((size_t)(b * NKV_ + kvh) * D_ + d) * S_ + kb + c8;
        unsigned so = st + 2 * KH_SZ + (d * 72 + c8) * 2;
        cp16(so,         g_Vth + go);
        cp16(so + VH_SZ, g_Vtl + go);
    }
    cp_commit();
}

__global__ __launch_bounds__(256, 1) void flash_bf16()
{
    extern __shared__ char sm[];
    const int tid  = threadIdx.x;
    const int lane = tid & 31;
    const int warp = tid >> 5;
    const int qtile = (gridDim.x - 1) - blockIdx.x;
    const int h    = blockIdx.y;
    const int b    = blockIdx.z;
    const int kvh  = h / G_;
    const int qbase = qtile * BQ;
    const float scale = 0.08838834764831845f;
    const int g = lane >> 2;
    const int t = lane & 3;
    const int m0 = warp * 16;
    unsigned sbase = (unsigned)__cvta_generic_to_shared(sm);

    // prefetch k-tile 0 immediately
    flash_issue(sbase, 0, b, kvh, 0, tid);

    // Q tile: plain copy of pre-split bf16
    for (int it = tid; it < BQ * 16; it += 256) {
        int r = it >> 4, c8 = (it & 15) << 3;
        size_t go = (((size_t)(b * S_ + qbase + r)) * NH_ + h) * D_ + c8;
        *(uint4*)(sm + QH_OFF + (r * 136 + c8) * 2) = *(const uint4*)(g_Qh + go);
        *(uint4*)(sm + QL_OFF + (r * 136 + c8) * 2) = *(const uint4*)(g_Ql + go);
    }

    float ctx[16][4];
#pragma unroll
    for (int i = 0; i < 16; i++)
#pragma unroll
        for (int e = 0; e < 4; e++) ctx[i][e] = 0.0f;
    float mr0 = -INFINITY, mr1 = -INFINITY, lr0 = 0.0f, lr1 = 0.0f;

    const int row0 = qbase + m0 + g;
    const int row1 = row0 + 8;
    const int ntile = 2 * qtile + 2;

    for (int j = 0; j < ntile; j++) {
        const int kb = j * 64;
        if (j + 1 < ntile) {
            flash_issue(sbase, (j + 1) & 1, b, kvh, (j + 1) * 64, tid);
            cp_wait1();
        } else {
            cp_wait0();
        }
        __syncthreads();

        const char* stK = sm + ST0_OFF + (j & 1) * STAGE_SZ;   // KH
        const char* stKL = stK + KH_SZ;
        const char* stV  = stK + 2 * KH_SZ;                    // VH
        const char* stVL = stV + VH_SZ;

        // ---- QK: 16q x 64keys per warp ----
        float acc[8][4];
#pragma unroll
        for (int nf = 0; nf < 8; nf++)
#pragma unroll
            for (int e = 0; e < 4; e++) acc[nf][e] = 0.0f;

#pragma unroll
        for (int kk = 0; kk < 8; kk++) {
            int c = kk * 16 + 2 * t;
            unsigned aH[4], aL[4];
            aH[0] = *(const unsigned*)(sm + QH_OFF + ((m0+g)*136 + c)*2);
            aH[1] = *(const unsigned*)(sm + QH_OFF + ((m0+g+8)*136 + c)*2);
            aH[2] = *(const unsigned*)(sm + QH_OFF + ((m0+g)*136 + c + 8)*2);
            aH[3] = *(const unsigned*)(sm + QH_OFF + ((m0+g+8)*136 + c + 8)*2);
            aL[0] = *(const unsigned*)(sm + QL_OFF + ((m0+g)*136 + c)*2);
            aL[1] = *(const unsigned*)(sm + QL_OFF + ((m0+g+8)*136 + c)*2);
            aL[2] = *(const unsigned*)(sm + QL_OFF + ((m0+g)*136 + c + 8)*2);
            aL[3] = *(const unsigned*)(sm + QL_OFF + ((m0+g+8)*136 + c + 8)*2);
#pragma unroll
            for (int nf = 0; nf < 8; nf++) {
                int n = nf * 8 + g;
                unsigned bH[2], bL[2];
                bH[0] = *(const unsigned*)(stK  + (n*136 + c)*2);
                bH[1] = *(const unsigned*)(stK  + (n*136 + c + 8)*2);
                bL[0] = *(const unsigned*)(stKL + (n*136 + c)*2);
                bL[1] = *(const unsigned*)(stKL + (n*136 + c + 8)*2);
                mma_bf16(acc[nf], aH, bH);
                mma_bf16(acc[nf], aH, bL);
                mma_bf16(acc[nf], aL, bH);
            }
        }

#pragma unroll
        for (int nf = 0; nf < 8; nf++)
#pragma unroll
            for (int e = 0; e < 4; e++) acc[nf][e] *= scale;

        if (kb + 63 > qbase + m0) {
#pragma unroll
            for (int nf = 0; nf < 8; nf++) {
                int k0 = kb + nf * 8 + 2 * t;
                if (k0     > row0) acc[nf][0] = -INFINITY;
                if (k0 + 1 > row0) acc[nf][1] = -INFINITY;
                if (k0     > row1) acc[nf][2] = -INFINITY;
                if (k0 + 1 > row1) acc[nf][3] = -INFINITY;
            }
        }

        // ---- in-register softmax ----
        float mx0 = -INFINITY, mx1 = -INFINITY;
#pragma unroll
        for (int nf = 0; nf < 8; nf++) {
            mx0 = fmaxf(mx0, fmaxf(acc[nf][0], acc[nf][1]));
            mx1 = fmaxf(mx1, fmaxf(acc[nf][2], acc[nf][3]));
        }
        mx0 = fmaxf(mx0, __shfl_xor_sync(0xffffffffu, mx0, 1));
        mx0 = fmaxf(mx0, __shfl_xor_sync(0xffffffffu, mx0, 2));
        mx1 = fmaxf(mx1, __shfl_xor_sync(0xffffffffu, mx1, 1));
        mx1 = fmaxf(mx1, __shfl_xor_sync(0xffffffffu, mx1, 2));

        float mn0 = fmaxf(mr0, mx0);
        float mn1 = fmaxf(mr1, mx1);
        float al0 = __expf(mr0 - mn0);
        float al1 = __expf(mr1 - mn1);
        mr0 = mn0; mr1 = mn1;

        unsigned pH[4][4], pL[4][4];
        float s0 = 0.0f, s1 = 0.0f;
#pragma unroll
        for (int nf = 0; nf < 8; nf++) {
            float p00 = __expf(acc[nf][0] - mn0);
            float p01 = __expf(acc[nf][1] - mn0);
            float p10 = __expf(acc[nf][2] - mn1);
            float p11 = __expf(acc[nf][3] - mn1);
            s0 += p00 + p01;
            s1 += p10 + p11;
            int kk2 = nf >> 1;
            int sl  = (nf & 1) << 1;
            split2(p00, p01, pH[kk2][sl],     pL[kk2][sl]);
            split2(p10, p11, pH[kk2][sl + 1], pL[kk2][sl + 1]);
        }
        s0 += __shfl_xor_sync(0xffffffffu, s0, 1);
        s0 += __shfl_xor_sync(0xffffffffu, s0, 2);
        s1 += __shfl_xor_sync(0xffffffffu, s1, 1);
        s1 += __shfl_xor_sync(0xffffffffu, s1, 2);
        lr0 = lr0 * al0 + s0;
        lr1 = lr1 * al1 + s1;

#pragma unroll
        for (int nf = 0; nf < 16; nf++) {
            ctx[nf][0] *= al0; ctx[nf][1] *= al0;
            ctx[nf][2] *= al1; ctx[nf][3] *= al1;
        }
#pragma unroll
        for (int kk2 = 0; kk2 < 4; kk2++) {
            int c = kk2 * 16 + 2 * t;
#pragma unroll
            for (int nf = 0; nf < 16; nf++) {
                int n = nf * 8 + g;
                unsigned vH[2], vL[2];
                vH[0] = *(const unsigned*)(stV  + (n*72 + c)*2);
                vH[1] = *(const unsigned*)(stV  + (n*72 + c + 8)*2);
                vL[0] = *(const unsigned*)(stVL + (n*72 + c)*2);
                vL[1] = *(const unsigned*)(stVL + (n*72 + c + 8)*2);
                mma_bf16(ctx[nf], pH[kk2], vH);
                mma_bf16(ctx[nf], pL[kk2], vH);
                mma_bf16(ctx[nf], pH[kk2], vL);
            }
        }
        __syncthreads();
    }

    // ---- finalize: write ctx as tf32 bits for the O GEMM ----
    float il0 = 1.0f / lr0;
    float il1 = 1.0f / lr1;
    unsigned* o0 = g_Ct + (((size_t)(b * S_ + row0)) * NH_ + h) * D_;
    unsigned* o1 = g_Ct + (((size_t)(b * S_ + row1)) * NH_ + h) * D_;
#pragma unroll
    for (int nf = 0; nf < 16; nf++) {
        int d = nf * 8 + 2 * t;
        *(uint2*)(o0 + d) = make_uint2(f2tf(ctx[nf][0] * il0), f2tf(ctx[nf][1] * il0));
        *(uint2*)(o1 + d) = make_uint2(f2tf(ctx[nf][2] * il1), f2tf(ctx[nf][3] * il1));
    }
}

// ============================================================
// launch
// ============================================================
extern "C" void kernel_launch(void* const* d_in, const int* in_sizes, int n_in,
                              void* d_out, int out_size)
{
    (void)in_sizes; (void)n_in; (void)out_size;
    const float* hidden = (const float*)d_in[0];
    const float* Wq = (const float*)d_in[1];
    const float* bq = (const float*)d_in[2];
    const float* Wk = (const float*)d_in[3];
    const float* bk = (const float*)d_in[4];
    const float* Wv = (const float*)d_in[5];
    const float* bv = (const float*)d_in[6];
    const float* Wo = (const float*)d_in[7];
    float* out = (float*)d_out;

    float *qp, *kp;
    unsigned *xtp, *wqt, *wot, *ctp;
    cudaGetSymbolAddress((void**)&qp,  g_Q);
    cudaGetSymbolAddress((void**)&kp,  g_K);
    cudaGetSymbolAddress((void**)&xtp, g_Xt);
    cudaGetSymbolAddress((void**)&wqt, g_Wqt);
    cudaGetSymbolAddress((void**)&wot, g_Wot);
    cudaGetSymbolAddress((void**)&ctp, g_Ct);

    cudaFuncSetAttribute(gemm_v2,
        cudaFuncAttributeMaxDynamicSharedMemorySize, GEMM_SMEM);
    cudaFuncSetAttribute(gemm_kv_v2,
        cudaFuncAttributeMaxDynamicSharedMemorySize, GEMM_SMEM);
    cudaFuncSetAttribute(flash_bf16,
        cudaFuncAttributeMaxDynamicSharedMemorySize, FLASH_SMEM);

    const int prep_total = (BSR_*HID_ + HID_*NH_*D_ + 2*HID_*NKV_*D_ + NH_*D_*HID_) / 4;

    // 1: convert inputs to tf32
    prep_tf32<<<(prep_total + 255) / 256, 256>>>(hidden, Wq, Wk, Wv, Wo);
    // 2: RoPE tables
    rope_table_kernel<<<(S_ * 64 + 255) / 256, 256>>>();
    // 3: Q projection
    gemm_v2<<<dim3(HID_ / BN, BSR_ / BM), 256, GEMM_SMEM>>>(xtp, wqt, bq, qp, NH_ * D_, HID_);
    // 4: K + V projections (profiled launch)
    gemm_kv_v2<<<dim3((NKV_ * D_) / BN, BSR_ / BM, 2), 256, GEMM_SMEM>>>(xtp, bk, bv, kp);
    // 5: RoPE + bf16 split of Q,K
    rope_split_kernel<<<BSR_, 256>>>();
    // 6: flash attention
    flash_bf16<<<dim3(S_ / BQ, NH_, B_), 256, FLASH_SMEM>>>();
    // 7: O projection
    gemm_v2<<<dim3(HID_ / BN, BSR_ / BM), 256, GEMM_SMEM>>>(ctp, wot, nullptr, out, HID_, NH_ * D_);
}

// round 7
// speedup vs baseline: 4.3463x; 1.1614x over previous
#include <cuda_runtime.h>
#include <cuda_bf16.h>
#include <math.h>

#define B_    2
#define S_    2048
#define HID_  2048
#define NH_   16
#define NKV_  8
#define D_    128
#define G_    (NH_/NKV_)
#define BSR_  (B_*S_)          // 4096

// -------- scratch (__device__ globals; no allocations) --------
__device__ float g_Q[BSR_ * NH_ * D_];              // f32 Q (pre-rope)
__device__ float g_K[BSR_ * NKV_ * D_];             // f32 K (pre-rope)
__device__ float g_C[BSR_ * NH_ * D_];              // f32 ctx (flash out)
__device__ __nv_bfloat16 g_Qh[BSR_ * NH_ * D_];     // roped Q hi/lo
__device__ __nv_bfloat16 g_Ql[BSR_ * NH_ * D_];
__device__ __nv_bfloat16 g_Kh[BSR_ * NKV_ * D_];    // roped K hi/lo
__device__ __nv_bfloat16 g_Kl[BSR_ * NKV_ * D_];
__device__ __nv_bfloat16 g_Vth[BSR_ * NKV_ * D_];   // V^T hi/lo [b][kvh][d][s]
__device__ __nv_bfloat16 g_Vtl[BSR_ * NKV_ * D_];
// fragment-packed tf32 operands
__device__ unsigned g_Xp [BSR_ * HID_];             // hidden, A-packed
__device__ unsigned g_Ctp[BSR_ * NH_ * D_];         // ctx, A-packed
__device__ unsigned g_Wqp[HID_ * NH_ * D_];         // weights, B-packed
__device__ unsigned g_Wkp[HID_ * NKV_ * D_];
__device__ unsigned g_Wvp[HID_ * NKV_ * D_];
__device__ unsigned g_Wop[NH_ * D_ * HID_];
__device__ float g_cos[S_ * 64];
__device__ float g_sin[S_ * 64];

// ---------------- helpers ----------------
__device__ __forceinline__ unsigned f2tf(float x) {
    unsigned u;
    asm("cvt.rna.tf32.f32 %0, %1;" : "=r"(u) : "f"(x));
    return u;
}
__device__ __forceinline__ void cp16(unsigned dst, const void* src) {
    asm volatile("cp.async.cg.shared.global [%0], [%1], 16;" :: "r"(dst), "l"(src));
}
__device__ __forceinline__ void cp_commit() { asm volatile("cp.async.commit_group;"); }
__device__ __forceinline__ void cp_wait1()  { asm volatile("cp.async.wait_group 1;"); }
__device__ __forceinline__ void cp_wait0()  { asm volatile("cp.async.wait_group 0;"); }

__device__ __forceinline__ void split2(float x, float y, unsigned& hi, unsigned& lo) {
    __nv_bfloat16 hx = __float2bfloat16_rn(x);
    __nv_bfloat16 hy = __float2bfloat16_rn(y);
    float rx = x - __bfloat162float(hx);
    float ry = y - __bfloat162float(hy);
    __nv_bfloat162 h; h.x = hx; h.y = hy;
    __nv_bfloat162 l; l.x = __float2bfloat16_rn(rx); l.y = __float2bfloat16_rn(ry);
    hi = *(unsigned*)&h;
    lo = *(unsigned*)&l;
}

__device__ __forceinline__ void mma_tf32(float* d, const unsigned* a, const unsigned* b) {
    asm volatile(
        "mma.sync.aligned.m16n8k8.row.col.f32.tf32.tf32.f32 "
        "{%0,%1,%2,%3}, {%4,%5,%6,%7}, {%8,%9}, {%0,%1,%2,%3};\n"
        : "+f"(d[0]), "+f"(d[1]), "+f"(d[2]), "+f"(d[3])
        : "r"(a[0]), "r"(a[1]), "r"(a[2]), "r"(a[3]), "r"(b[0]), "r"(b[1]));
}
__device__ __forceinline__ void mma_bf16(float* d, const unsigned* a, const unsigned* b) {
    asm volatile(
        "mma.sync.aligned.m16n8k16.row.col.f32.bf16.bf16.f32 "
        "{%0,%1,%2,%3}, {%4,%5,%6,%7}, {%8,%9}, {%0,%1,%2,%3};\n"
        : "+f"(d[0]), "+f"(d[1]), "+f"(d[2]), "+f"(d[3])
        : "r"(a[0]), "r"(a[1]), "r"(a[2]), "r"(a[3]), "r"(b[0]), "r"(b[1]));
}

// ============================================================
// Fragment packing.
// A-packed: [mtile(128 rows)][kchunk(32)][kk(4)][rf(8)][lane(32)] uint4
//   uint4 = { A[r][c], A[r+8][c], A[r][c+4], A[r+8][c+4] } as tf32,
//   r = mtile*128 + rf*16 + (lane>>2), c = kchunk*32 + kk*8 + (lane&3)
// B-packed: [ntile(128 cols)][kchunk(32)][kk(4)][nb(16)][lane(32)] uint2
//   uint2 = { W[c][n], W[c+4][n] }, n = ntile*128 + nb*8 + (lane>>2)
// Chunk = 4096 words = 16 KB for both.
// ============================================================
__global__ void pack_a(const float* __restrict__ A, unsigned* __restrict__ P)
{
    int id = blockIdx.x * blockDim.x + threadIdx.x;     // one uint4 each
    if (id >= (BSR_ * HID_) / 4) return;
    int w      = id & 1023;
    int chunk  = id >> 10;
    int kchunk = chunk & 63;
    int mtile  = chunk >> 6;
    int lane = w & 31, rf = (w >> 5) & 7, kk = w >> 8;
    int row = mtile * 128 + rf * 16 + (lane >> 2);
    int col = kchunk * 32 + kk * 8 + (lane & 3);
    const float* a0 = A + (size_t)row * HID_ + col;
    ((uint4*)P)[id] = make_uint4(
        f2tf(a0[0]), f2tf(a0[8 * HID_]), f2tf(a0[4]), f2tf(a0[8 * HID_ + 4]));
}

__global__ void pack_b(const float* __restrict__ W, unsigned* __restrict__ P, int N)
{
    int id = blockIdx.x * blockDim.x + threadIdx.x;     // one uint2 each
    if (id >= (N * HID_) / 2) return;
    int w      = id & 2047;
    int chunk  = id >> 11;
    int kchunk = chunk & 63;
    int ntile  = chunk >> 6;
    int lane = w & 31, nb = (w >> 5) & 15, kk = w >> 9;
    int n = ntile * 128 + nb * 8 + (lane >> 2);
    int c = kchunk * 32 + kk * 8 + (lane & 3);
    ((uint2*)P)[id] = make_uint2(
        f2tf(W[(size_t)c * N + n]), f2tf(W[(size_t)(c + 4) * N + n]));
}

// ============================================================
// TF32 GEMM v3: fragment-packed operands, cp.async 2-stage.
// Tile 128x128, chunk K=32. LDS.128 for A frags, LDS.64 for B frags.
// ============================================================
#define CHUNK_BYTES 16384
#define STAGE_BYTES (2 * CHUNK_BYTES)          // A + B
#define GEMM_SMEM   (2 * STAGE_BYTES)          // 65536

__device__ __forceinline__ void gemm_issue_v3(
    unsigned sbase, int stage, const unsigned* __restrict__ Ac,
    const unsigned* __restrict__ Bc, int tid)
{
    unsigned st = sbase + stage * STAGE_BYTES;
#pragma unroll
    for (int p = 0; p < 4; p++) {
        int id = tid + p * 256;
        cp16(st + id * 16,               Ac + id * 4);
        cp16(st + CHUNK_BYTES + id * 16, Bc + id * 4);
    }
    cp_commit();
}

__device__ __forceinline__ void gemm_compute_v3(
    const char* st, float acc[4][4][4], int lane, int wm, int wn)
{
    const char* sA = st;
    const char* sB = st + CHUNK_BYTES;
#pragma unroll
    for (int kk = 0; kk < 4; kk++) {
        uint4 a[4]; uint2 b[4];
#pragma unroll
        for (int mf = 0; mf < 4; mf++)
            a[mf] = *(const uint4*)(sA + (((kk * 8 + wm * 4 + mf) * 32) + lane) * 16);
#pragma unroll
        for (int nf = 0; nf < 4; nf++)
            b[nf] = *(const uint2*)(sB + (((kk * 16 + wn * 4 + nf) * 32) + lane) * 8);
#pragma unroll
        for (int mf = 0; mf < 4; mf++)
#pragma unroll
            for (int nf = 0; nf < 4; nf++)
                mma_tf32(acc[mf][nf], (const unsigned*)&a[mf], (const unsigned*)&b[nf]);
    }
}

__device__ __forceinline__ void gemm_main_v3(
    const unsigned* __restrict__ Ap, const unsigned* __restrict__ Bp,
    float acc[4][4][4], char* smem)
{
    const int tid  = threadIdx.x;
    const int lane = tid & 31;
    const int wm   = (tid >> 5) >> 2;
    const int wn   = (tid >> 5) & 3;
    unsigned sbase = (unsigned)__cvta_generic_to_shared(smem);
    const unsigned* Ab = Ap + (size_t)blockIdx.y * 64 * 4096;
    const unsigned* Bb = Bp + (size_t)blockIdx.x * 64 * 4096;

    gemm_issue_v3(sbase, 0, Ab, Bb, tid);
    for (int i = 0; i < 64; i++) {
        if (i + 1 < 64) {
            gemm_issue_v3(sbase, (i + 1) & 1, Ab + (i + 1) * 4096,
                          Bb + (i + 1) * 4096, tid);
            cp_wait1();
        } else {
            cp_wait0();
        }
        __syncthreads();
        gemm_compute_v3(smem + (i & 1) * STAGE_BYTES, acc, lane, wm, wn);
        __syncthreads();
    }
}

__global__ __launch_bounds__(256, 2) void gemm_v3(
    const unsigned* __restrict__ Ap, const unsigned* __restrict__ Bp,
    const float* __restrict__ bias, float* __restrict__ C, int N)
{
    extern __shared__ char smem[];
    float acc[4][4][4];
#pragma unroll
    for (int i = 0; i < 4; i++)
#pragma unroll
        for (int j = 0; j < 4; j++)
#pragma unroll
            for (int e = 0; e < 4; e++) acc[i][j][e] = 0.0f;

    gemm_main_v3(Ap, Bp, acc, smem);

    const int lane = threadIdx.x & 31;
    const int warp = threadIdx.x >> 5;
    const int wm = warp >> 2, wn = warp & 3;
#pragma unroll
    for (int mf = 0; mf < 4; mf++) {
        int row = blockIdx.y * 128 + wm * 64 + mf * 16 + (lane >> 2);
#pragma unroll
        for (int nf = 0; nf < 4; nf++) {
            int col = blockIdx.x * 128 + wn * 32 + nf * 8 + 2 * (lane & 3);
            float b0 = 0.0f, b1 = 0.0f;
            if (bias) { b0 = bias[col]; b1 = bias[col + 1]; }
            *(float2*)&C[(size_t)row * N + col] =
                make_float2(acc[mf][nf][0] + b0, acc[mf][nf][1] + b1);
            *(float2*)&C[(size_t)(row + 8) * N + col] =
                make_float2(acc[mf][nf][2] + b0, acc[mf][nf][3] + b1);
        }
    }
}

// K + V in one launch; V epilogue writes bf16 hi/lo transposed
__global__ __launch_bounds__(256, 2) void gemm_kv_v3(
    const unsigned* __restrict__ Ap,
    const float* __restrict__ bk, const float* __restrict__ bv,
    float* __restrict__ Kout)
{
    extern __shared__ char smem[];
    const int z = blockIdx.z;
    const unsigned* Bp  = z ? g_Wvp : g_Wkp;
    const float*   bias = z ? bv : bk;
    const int N = NKV_ * D_;

    float acc[4][4][4];
#pragma unroll
    for (int i = 0; i < 4; i++)
#pragma unroll
        for (int j = 0; j < 4; j++)
#pragma unroll
            for (int e = 0; e < 4; e++) acc[i][j][e] = 0.0f;

    gemm_main_v3(Ap, Bp, acc, smem);

    const int lane = threadIdx.x & 31;
    const int warp = threadIdx.x >> 5;
    const int wm = warp >> 2, wn = warp & 3;
#pragma unroll
    for (int mf = 0; mf < 4; mf++) {
        int row = blockIdx.y * 128 + wm * 64 + mf * 16 + (lane >> 2);
#pragma unroll
        for (int nf = 0; nf < 4; nf++) {
            int col = blockIdx.x * 128 + wn * 32 + nf * 8 + 2 * (lane & 3);
            float b0 = bias[col], b1 = bias[col + 1];
            float v00 = acc[mf][nf][0] + b0, v01 = acc[mf][nf][1] + b1;
            float v10 = acc[mf][nf][2] + b0, v11 = acc[mf][nf][3] + b1;
            if (z == 0) {
                *(float2*)&Kout[(size_t)row * N + col]       = make_float2(v00, v01);
                *(float2*)&Kout[(size_t)(row + 8) * N + col] = make_float2(v10, v11);
            } else {
                int bb = row >> 11, s = row & 2047;
                int kvh = col >> 7, d = col & 127;
                size_t base = ((size_t)(bb * NKV_ + kvh) * D_ + d) * S_;
                __nv_bfloat16 h;
                h = __float2bfloat16_rn(v00);
                g_Vth[base + s] = h;
                g_Vtl[base + s] = __float2bfloat16_rn(v00 - __bfloat162float(h));
                h = __float2bfloat16_rn(v01);
                g_Vth[base + S_ + s] = h;
                g_Vtl[base + S_ + s] = __float2bfloat16_rn(v01 - __bfloat162float(h));
                h = __float2bfloat16_rn(v10);
                g_Vth[base + s + 8] = h;
                g_Vtl[base + s + 8] = __float2bfloat16_rn(v10 - __bfloat162float(h));
                h = __float2bfloat16_rn(v11);
                g_Vth[base + S_ + s + 8] = h;
                g_Vtl[base + S_ + s + 8] = __float2bfloat16_rn(v11 - __bfloat162float(h));
            }
        }
    }
}

// ============================================================
// RoPE tables + rope/split pass for Q,K
// ============================================================
__global__ void rope_table_kernel()
{
    int idx = blockIdx.x * blockDim.x + threadIdx.x;
    if (idx >= S_ * 64) return;
    int s = idx >> 6, i = idx & 63;
    const double NEG_LOG_STEP = -0.2158673524681918;
    double freq = exp((double)i * NEG_LOG_STEP);
    double sd, cd;
    sincos((double)s * freq, &sd, &cd);
    g_cos[idx] = (float)cd;
    g_sin[idx] = (float)sd;
}

__global__ void rope_split_kernel()
{
    __shared__ float sc[64], ss[64];
    const int bs = blockIdx.x;
    const int s  = bs % S_;
    if (threadIdx.x < 64) {
        sc[threadIdx.x] = g_cos[s * 64 + threadIdx.x];
        ss[threadIdx.x] = g_sin[s * 64 + threadIdx.x];
    }
    __syncthreads();

    for (int p = threadIdx.x; p < (NH_ + NKV_) * 64; p += blockDim.x) {
        int head = p >> 6;
        int i    = p & 63;
        float c = sc[i], sn = ss[i];
        if (head < NH_) {
            size_t base = ((size_t)bs * NH_ + head) * D_;
            float x1 = g_Q[base + i], x2 = g_Q[base + i + 64];
            float o1 = x1 * c - x2 * sn;
            float o2 = x2 * c + x1 * sn;
            __nv_bfloat16 h1 = __float2bfloat16_rn(o1);
            __nv_bfloat16 h2 = __float2bfloat16_rn(o2);
            g_Qh[base + i]      = h1;
            g_Ql[base + i]      = __float2bfloat16_rn(o1 - __bfloat162float(h1));
            g_Qh[base + i + 64] = h2;
            g_Ql[base + i + 64] = __float2bfloat16_rn(o2 - __bfloat162float(h2));
        } else {
            size_t base = ((size_t)bs * NKV_ + (head - NH_)) * D_;
            float x1 = g_K[base + i], x2 = g_K[base + i + 64];
            float o1 = x1 * c - x2 * sn;
            float o2 = x2 * c + x1 * sn;
            __nv_bfloat16 h1 = __float2bfloat16_rn(o1);
            __nv_bfloat16 h2 = __float2bfloat16_rn(o2);
            g_Kh[base + i]      = h1;
            g_Kl[base + i]      = __float2bfloat16_rn(o1 - __bfloat162float(h1));
            g_Kh[base + i + 64] = h2;
            g_Kl[base + i + 64] = __float2bfloat16_rn(o2 - __bfloat162float(h2));
        }
    }
}

// ============================================================
// Flash attention (identical to R5 core, passing at rel_err 5e-4).
// ============================================================
#define BQ 128
#define QH_OFF 0
#define QL_OFF (QH_OFF + BQ*136*2)
#define ST0_OFF (QL_OFF + BQ*136*2)
#define KH_SZ (64*136*2)
#define VH_SZ (128*72*2)
#define STAGE_SZ (2*KH_SZ + 2*VH_SZ)
#define FLASH_SMEM (ST0_OFF + 2*STAGE_SZ)     // 212992

__device__ __forceinline__ void flash_issue(
    unsigned sbase, int stage, int b, int kvh, int kb, int tid)
{
    unsigned st = sbase + ST0_OFF + stage * STAGE_SZ;
#pragma unroll
    for (int p = 0; p < 4; p++) {
        int id = tid + p * 256;
        int r = id >> 4, c8 = (id & 15) << 3;
        size_t go = (((size_t)(b * S_ + kb + r)) * NKV_ + kvh) * D_ + c8;
        unsigned so = st + (r * 136 + c8) * 2;
        cp16(so,         g_Kh + go);
        cp16(so + KH_SZ, g_Kl + go);
    }
#pragma unroll
    for (int p = 0; p < 4; p++) {
        int id = tid + p * 256;
        int d = id >> 3, c8 = (id & 7) << 3;
        size_t go = ((size_t)(b * NKV_ + kvh) * D_ + d) * S_ + kb + c8;
        unsigned so = st + 2 * KH_SZ + (d * 72 + c8) * 2;
        cp16(so,         g_Vth + go);
        cp16(so + VH_SZ, g_Vtl + go);
    }
    cp_commit();
}

__global__ __launch_bounds__(256, 1) void flash_bf16()
{
    extern __shared__ char sm[];
    const int tid  = threadIdx.x;
    const int lane = tid & 31;
    const int warp = tid >> 5;
    const int qtile = (gridDim.x - 1) - blockIdx.x;
    const int h    = blockIdx.y;
    const int b    = blockIdx.z;
    const int kvh  = h / G_;
    const int qbase = qtile * BQ;
    const float scale = 0.08838834764831845f;
    const int g = lane >> 2;
    const int t = lane & 3;
    const int m0 = warp * 16;
    unsigned sbase = (unsigned)__cvta_generic_to_shared(sm);

    flash_issue(sbase, 0, b, kvh, 0, tid);

    for (int it = tid; it < BQ * 16; it += 256) {
        int r = it >> 4, c8 = (it & 15) << 3;
        size_t go = (((size_t)(b * S_ + qbase + r)) * NH_ + h) * D_ + c8;
        *(uint4*)(sm + QH_OFF + (r * 136 + c8) * 2) = *(const uint4*)(g_Qh + go);
        *(uint4*)(sm + QL_OFF + (r * 136 + c8) * 2) = *(const uint4*)(g_Ql + go);
    }

    float ctx[16][4];
#pragma unroll
    for (int i = 0; i < 16; i++)
#pragma unroll
        for (int e = 0; e < 4; e++) ctx[i][e] = 0.0f;
    float mr0 = -INFINITY, mr1 = -INFINITY, lr0 = 0.0f, lr1 = 0.0f;

    const int row0 = qbase + m0 + g;
    const int row1 = row0 + 8;
    const int ntile = 2 * qtile + 2;

    for (int j = 0; j < ntile; j++) {
        const int kb = j * 64;
        if (j + 1 < ntile) {
            flash_issue(sbase, (j + 1) & 1, b, kvh, (j + 1) * 64, tid);
            cp_wait1();
        } else {
            cp_wait0();
        }
        __syncthreads();

        const char* stK  = sm + ST0_OFF + (j & 1) * STAGE_SZ;
        const char* stKL = stK + KH_SZ;
        const char* stV  = stK + 2 * KH_SZ;
        const char* stVL = stV + VH_SZ;

        float acc[8][4];
#pragma unroll
        for (int nf = 0; nf < 8; nf++)
#pragma unroll
            for (int e = 0; e < 4; e++) acc[nf][e] = 0.0f;

#pragma unroll
        for (int kk = 0; kk < 8; kk++) {
            int c = kk * 16 + 2 * t;
            unsigned aH[4], aL[4];
            aH[0] = *(const unsigned*)(sm + QH_OFF + ((m0+g)*136 + c)*2);
            aH[1] = *(const unsigned*)(sm + QH_OFF + ((m0+g+8)*136 + c)*2);
            aH[2] = *(const unsigned*)(sm + QH_OFF + ((m0+g)*136 + c + 8)*2);
            aH[3] = *(const unsigned*)(sm + QH_OFF + ((m0+g+8)*136 + c + 8)*2);
            aL[0] = *(const unsigned*)(sm + QL_OFF + ((m0+g)*136 + c)*2);
            aL[1] = *(const unsigned*)(sm + QL_OFF + ((m0+g+8)*136 + c)*2);
            aL[2] = *(const unsigned*)(sm + QL_OFF + ((m0+g)*136 + c + 8)*2);
            aL[3] = *(const unsigned*)(sm + QL_OFF + ((m0+g+8)*136 + c + 8)*2);
#pragma unroll
            for (int nf = 0; nf < 8; nf++) {
                int n = nf * 8 + g;
                unsigned bH[2], bL[2];
                bH[0] = *(const unsigned*)(stK  + (n*136 + c)*2);
                bH[1] = *(const unsigned*)(stK  + (n*136 + c + 8)*2);
                bL[0] = *(const unsigned*)(stKL + (n*136 + c)*2);
                bL[1] = *(const unsigned*)(stKL + (n*136 + c + 8)*2);
                mma_bf16(acc[nf], aH, bH);
                mma_bf16(acc[nf], aH, bL);
                mma_bf16(acc[nf], aL, bH);
            }
        }

#pragma unroll
        for (int nf = 0; nf < 8; nf++)
#pragma unroll
            for (int e = 0; e < 4; e++) acc[nf][e] *= scale;

        if (kb + 63 > qbase + m0) {
#pragma unroll
            for (int nf = 0; nf < 8; nf++) {
                int k0 = kb + nf * 8 + 2 * t;
                if (k0     > row0) acc[nf][0] = -INFINITY;
                if (k0 + 1 > row0) acc[nf][1] = -INFINITY;
                if (k0     > row1) acc[nf][2] = -INFINITY;
                if (k0 + 1 > row1) acc[nf][3] = -INFINITY;
            }
        }

        float mx0 = -INFINITY, mx1 = -INFINITY;
#pragma unroll
        for (int nf = 0; nf < 8; nf++) {
            mx0 = fmaxf(mx0, fmaxf(acc[nf][0], acc[nf][1]));
            mx1 = fmaxf(mx1, fmaxf(acc[nf][2], acc[nf][3]));
        }
        mx0 = fmaxf(mx0, __shfl_xor_sync(0xffffffffu, mx0, 1));
        mx0 = fmaxf(mx0, __shfl_xor_sync(0xffffffffu, mx0, 2));
        mx1 = fmaxf(mx1, __shfl_xor_sync(0xffffffffu, mx1, 1));
        mx1 = fmaxf(mx1, __shfl_xor_sync(0xffffffffu, mx1, 2));

        float mn0 = fmaxf(mr0, mx0);
        float mn1 = fmaxf(mr1, mx1);
        float al0 = __expf(mr0 - mn0);
        float al1 = __expf(mr1 - mn1);
        mr0 = mn0; mr1 = mn1;

        unsigned pH[4][4], pL[4][4];
        float s0 = 0.0f, s1 = 0.0f;
#pragma unroll
        for (int nf = 0; nf < 8; nf++) {
            float p00 = __expf(acc[nf][0] - mn0);
            float p01 = __expf(acc[nf][1] - mn0);
            float p10 = __expf(acc[nf][2] - mn1);
            float p11 = __expf(acc[nf][3] - mn1);
            s0 += p00 + p01;
            s1 += p10 + p11;
            int kk2 = nf >> 1;
            int sl  = (nf & 1) << 1;
            split2(p00, p01, pH[kk2][sl],     pL[kk2][sl]);
            split2(p10, p11, pH[kk2][sl + 1], pL[kk2][sl + 1]);
        }
        s0 += __shfl_xor_sync(0xffffffffu, s0, 1);
        s0 += __shfl_xor_sync(0xffffffffu, s0, 2);
        s1 += __shfl_xor_sync(0xffffffffu, s1, 1);
        s1 += __shfl_xor_sync(0xffffffffu, s1, 2);
        lr0 = lr0 * al0 + s0;
        lr1 = lr1 * al1 + s1;

#pragma unroll
        for (int nf = 0; nf < 16; nf++) {
            ctx[nf][0] *= al0; ctx[nf][1] *= al0;
            ctx[nf][2] *= al1; ctx[nf][3] *= al1;
        }
#pragma unroll
        for (int kk2 = 0; kk2 < 4; kk2++) {
            int c = kk2 * 16 + 2 * t;
#pragma unroll
            for (int nf = 0; nf < 16; nf++) {
                int n = nf * 8 + g;
                unsigned vH[2], vL[2];
                vH[0] = *(const unsigned*)(stV  + (n*72 + c)*2);
                vH[1] = *(const unsigned*)(stV  + (n*72 + c + 8)*2);
                vL[0] = *(const unsigned*)(stVL + (n*72 + c)*2);
                vL[1] = *(const unsigned*)(stVL + (n*72 + c + 8)*2);
                mma_bf16(ctx[nf], pH[kk2], vH);
                mma_bf16(ctx[nf], pL[kk2], vH);
                mma_bf16(ctx[nf], pH[kk2], vL);
            }
        }
        __syncthreads();
    }

    // finalize: f32 ctx (packed for O-GEMM by pack_a afterwards)
    float il0 = 1.0f / lr0;
    float il1 = 1.0f / lr1;
    float* o0 = g_C + (((size_t)(b * S_ + row0)) * NH_ + h) * D_;
    float* o1 = g_C + (((size_t)(b * S_ + row1)) * NH_ + h) * D_;
#pragma unroll
    for (int nf = 0; nf < 16; nf++) {
        int d = nf * 8 + 2 * t;
        *(float2*)(o0 + d) = make_float2(ctx[nf][0] * il0, ctx[nf][1] * il0);
        *(float2*)(o1 + d) = make_float2(ctx[nf][2] * il1, ctx[nf][3] * il1);
    }
}

// ============================================================
// launch
// ============================================================
extern "C" void kernel_launch(void* const* d_in, const int* in_sizes, int n_in,
                              void* d_out, int out_size)
{
    (void)in_sizes; (void)n_in; (void)out_size;
    const float* hidden = (const float*)d_in[0];
    const float* Wq = (const float*)d_in[1];
    const float* bq = (const float*)d_in[2];
    const float* Wk = (const float*)d_in[3];
    const float* bk = (const float*)d_in[4];
    const float* Wv = (const float*)d_in[5];
    const float* bv = (const float*)d_in[6];
    const float* Wo = (const float*)d_in[7];
    float* out = (float*)d_out;

    float *qp, *kp, *cp;
    unsigned *xp, *ctp, *wqp, *wkp, *wvp, *wop;
    cudaGetSymbolAddress((void**)&qp,  g_Q);
    cudaGetSymbolAddress((void**)&kp,  g_K);
    cudaGetSymbolAddress((void**)&cp,  g_C);
    cudaGetSymbolAddress((void**)&xp,  g_Xp);
    cudaGetSymbolAddress((void**)&ctp, g_Ctp);
    cudaGetSymbolAddress((void**)&wqp, g_Wqp);
    cudaGetSymbolAddress((void**)&wkp, g_Wkp);
    cudaGetSymbolAddress((void**)&wvp, g_Wvp);
    cudaGetSymbolAddress((void**)&wop, g_Wop);

    cudaFuncSetAttribute(gemm_v3,
        cudaFuncAttributeMaxDynamicSharedMemorySize, GEMM_SMEM);
    cudaFuncSetAttribute(gemm_kv_v3,
        cudaFuncAttributeMaxDynamicSharedMemorySize, GEMM_SMEM);
    cudaFuncSetAttribute(flash_bf16,
        cudaFuncAttributeMaxDynamicSharedMemorySize, FLASH_SMEM);

    // 0: pack hidden (A-packed tf32)
    pack_a<<<(BSR_ * HID_ / 4 + 255) / 256, 256>>>(hidden, xp);
    // 1: RoPE tables
    rope_table_kernel<<<(S_ * 64 + 255) / 256, 256>>>();
    // 2: pack Wq
    pack_b<<<(2048 * HID_ / 2 + 255) / 256, 256>>>(Wq, wqp, 2048);
    // 3: Q projection  ← profiled launch (index 3)
    gemm_v3<<<dim3(16, 32), 256, GEMM_SMEM>>>(xp, wqp, bq, qp, NH_ * D_);
    // 4-5: pack Wk, Wv
    pack_b<<<(1024 * HID_ / 2 + 255) / 256, 256>>>(Wk, wkp, 1024);
    pack_b<<<(1024 * HID_ / 2 + 255) / 256, 256>>>(Wv, wvp, 1024);
    // 6: K + V projections (V^T bf16 hi/lo epilogue)
    gemm_kv_v3<<<dim3(8, 32, 2), 256, GEMM_SMEM>>>(xp, bk, bv, kp);
    // 7: pack Wo
    pack_b<<<(2048 * HID_ / 2 + 255) / 256, 256>>>(Wo, wop, 2048);
    // 8: RoPE + bf16 split of Q,K
    rope_split_kernel<<<BSR_, 256>>>();
    // 9: flash attention
    flash_bf16<<<dim3(S_ / BQ, NH_, B_), 256, FLASH_SMEM>>>();
    // 10: pack ctx
    pack_a<<<(BSR_ * HID_ / 4 + 255) / 256, 256>>>(cp, ctp);
    // 11: O projection
    gemm_v3<<<dim3(16, 32), 256, GEMM_SMEM>>>(ctp, wop, nullptr, out, HID_);
}

// round 8
// speedup vs baseline: 4.5558x; 1.0482x over previous
#include <cuda_runtime.h>
#include <cuda_bf16.h>
#include <math.h>

#define B_    2
#define S_    2048
#define HID_  2048
#define NH_   16
#define NKV_  8
#define D_    128
#define G_    (NH_/NKV_)
#define BSR_  (B_*S_)          // 4096

// -------- scratch (__device__ globals; no allocations) --------
__device__ float g_Q[BSR_ * NH_ * D_];              // f32 Q (pre-rope)
__device__ float g_K[BSR_ * NKV_ * D_];             // f32 K (pre-rope)
__device__ float g_C[BSR_ * NH_ * D_];              // f32 ctx (flash out)
__device__ __nv_bfloat16 g_Qh[BSR_ * NH_ * D_];     // roped Q hi/lo
__device__ __nv_bfloat16 g_Ql[BSR_ * NH_ * D_];
__device__ __nv_bfloat16 g_Kh[BSR_ * NKV_ * D_];    // roped K hi/lo
__device__ __nv_bfloat16 g_Kl[BSR_ * NKV_ * D_];
__device__ __nv_bfloat16 g_Vth[BSR_ * NKV_ * D_];   // V^T hi/lo [b][kvh][d][s]
__device__ __nv_bfloat16 g_Vtl[BSR_ * NKV_ * D_];
// fragment-packed tf32 operands
__device__ unsigned g_Xp [BSR_ * HID_];             // hidden, A-packed
__device__ unsigned g_Ctp[BSR_ * NH_ * D_];         // ctx, A-packed
__device__ unsigned g_Wqp[HID_ * NH_ * D_];         // weights, B-packed
__device__ unsigned g_Wkp[HID_ * NKV_ * D_];
__device__ unsigned g_Wvp[HID_ * NKV_ * D_];
__device__ unsigned g_Wop[NH_ * D_ * HID_];
__device__ float g_cos[S_ * 64];
__device__ float g_sin[S_ * 64];

// ---------------- helpers ----------------
__device__ __forceinline__ unsigned f2tf(float x) {
    unsigned u;
    asm("cvt.rna.tf32.f32 %0, %1;" : "=r"(u) : "f"(x));
    return u;
}
__device__ __forceinline__ void cp16(unsigned dst, const void* src) {
    asm volatile("cp.async.cg.shared.global [%0], [%1], 16;" :: "r"(dst), "l"(src));
}
__device__ __forceinline__ void cp_commit() { asm volatile("cp.async.commit_group;"); }
__device__ __forceinline__ void cp_wait1()  { asm volatile("cp.async.wait_group 1;"); }
__device__ __forceinline__ void cp_wait0()  { asm volatile("cp.async.wait_group 0;"); }

__device__ __forceinline__ void split2(float x, float y, unsigned& hi, unsigned& lo) {
    __nv_bfloat16 hx = __float2bfloat16_rn(x);
    __nv_bfloat16 hy = __float2bfloat16_rn(y);
    float rx = x - __bfloat162float(hx);
    float ry = y - __bfloat162float(hy);
    __nv_bfloat162 h; h.x = hx; h.y = hy;
    __nv_bfloat162 l; l.x = __float2bfloat16_rn(rx); l.y = __float2bfloat16_rn(ry);
    hi = *(unsigned*)&h;
    lo = *(unsigned*)&l;
}

__device__ __forceinline__ void mma_tf32(float* d, const unsigned* a, const unsigned* b) {
    asm volatile(
        "mma.sync.aligned.m16n8k8.row.col.f32.tf32.tf32.f32 "
        "{%0,%1,%2,%3}, {%4,%5,%6,%7}, {%8,%9}, {%0,%1,%2,%3};\n"
        : "+f"(d[0]), "+f"(d[1]), "+f"(d[2]), "+f"(d[3])
        : "r"(a[0]), "r"(a[1]), "r"(a[2]), "r"(a[3]), "r"(b[0]), "r"(b[1]));
}
__device__ __forceinline__ void mma_bf16(float* d, const unsigned* a, const unsigned* b) {
    asm volatile(
        "mma.sync.aligned.m16n8k16.row.col.f32.bf16.bf16.f32 "
        "{%0,%1,%2,%3}, {%4,%5,%6,%7}, {%8,%9}, {%0,%1,%2,%3};\n"
        : "+f"(d[0]), "+f"(d[1]), "+f"(d[2]), "+f"(d[3])
        : "r"(a[0]), "r"(a[1]), "r"(a[2]), "r"(a[3]), "r"(b[0]), "r"(b[1]));
}

// ============================================================
// Fragment packing (layouts unchanged from R7, validated).
// ============================================================
__global__ void pack_a(const float* __restrict__ A, unsigned* __restrict__ P)
{
    int id = blockIdx.x * blockDim.x + threadIdx.x;
    if (id >= (BSR_ * HID_) / 4) return;
    int w      = id & 1023;
    int chunk  = id >> 10;
    int kchunk = chunk & 63;
    int mtile  = chunk >> 6;
    int lane = w & 31, rf = (w >> 5) & 7, kk = w >> 8;
    int row = mtile * 128 + rf * 16 + (lane >> 2);
    int col = kchunk * 32 + kk * 8 + (lane & 3);
    const float* a0 = A + (size_t)row * HID_ + col;
    ((uint4*)P)[id] = make_uint4(
        f2tf(a0[0]), f2tf(a0[8 * HID_]), f2tf(a0[4]), f2tf(a0[8 * HID_ + 4]));
}

__device__ __forceinline__ void pack_b_one(
    const float* __restrict__ W, unsigned* __restrict__ P, int N, int id)
{
    int w      = id & 2047;
    int chunk  = id >> 11;
    int kchunk = chunk & 63;
    int ntile  = chunk >> 6;
    int lane = w & 31, nb = (w >> 5) & 15, kk = w >> 9;
    int n = ntile * 128 + nb * 8 + (lane >> 2);
    int c = kchunk * 32 + kk * 8 + (lane & 3);
    ((uint2*)P)[id] = make_uint2(
        f2tf(W[(size_t)c * N + n]), f2tf(W[(size_t)(c + 4) * N + n]));
}

__global__ void pack_b(const float* __restrict__ W, unsigned* __restrict__ P, int N)
{
    int id = blockIdx.x * blockDim.x + threadIdx.x;
    if (id >= (N * HID_) / 2) return;
    pack_b_one(W, P, N, id);
}

// pack Wq + Wk + Wv in one launch
__global__ void pack_b3(const float* __restrict__ Wq,
                        const float* __restrict__ Wk,
                        const float* __restrict__ Wv)
{
    const int NQ = (2048 * HID_) / 2;     // uint2 jobs for Wq
    const int NK = (1024 * HID_) / 2;
    int id = blockIdx.x * blockDim.x + threadIdx.x;
    if (id < NQ)                 pack_b_one(Wq, g_Wqp, 2048, id);
    else if (id < NQ + NK)       pack_b_one(Wk, g_Wkp, 1024, id - NQ);
    else if (id < NQ + 2 * NK)   pack_b_one(Wv, g_Wvp, 1024, id - NQ - NK);
}

// ============================================================
// TF32 GEMM v4: fragment-packed, 3-stage cp.async, ONE barrier/chunk.
// ============================================================
#define CHUNK_BYTES 16384
#define STAGE_BYTES (2 * CHUNK_BYTES)          // A + B
#define GEMM_SMEM   (3 * STAGE_BYTES)          // 98304

__device__ __forceinline__ void gemm_issue_v3(
    unsigned sbase, int stage, const unsigned* __restrict__ Ac,
    const unsigned* __restrict__ Bc, int tid)
{
    unsigned st = sbase + stage * STAGE_BYTES;
#pragma unroll
    for (int p = 0; p < 4; p++) {
        int id = tid + p * 256;
        cp16(st + id * 16,               Ac + id * 4);
        cp16(st + CHUNK_BYTES + id * 16, Bc + id * 4);
    }
    cp_commit();
}

__device__ __forceinline__ void gemm_compute_v3(
    const char* st, float acc[4][4][4], int lane, int wm, int wn)
{
    const char* sA = st;
    const char* sB = st + CHUNK_BYTES;
#pragma unroll
    for (int kk = 0; kk < 4; kk++) {
        uint4 a[4]; uint2 b[4];
#pragma unroll
        for (int mf = 0; mf < 4; mf++)
            a[mf] = *(const uint4*)(sA + (((kk * 8 + wm * 4 + mf) * 32) + lane) * 16);
#pragma unroll
        for (int nf = 0; nf < 4; nf++)
            b[nf] = *(const uint2*)(sB + (((kk * 16 + wn * 4 + nf) * 32) + lane) * 8);
#pragma unroll
        for (int mf = 0; mf < 4; mf++)
#pragma unroll
            for (int nf = 0; nf < 4; nf++)
                mma_tf32(acc[mf][nf], (const unsigned*)&a[mf], (const unsigned*)&b[nf]);
    }
}

// 3-stage mainloop: wait → sync → issue(i+2 into freed stage) → compute
__device__ __forceinline__ void gemm_main_v4(
    const unsigned* __restrict__ Ab, const unsigned* __restrict__ Bb,
    float acc[4][4][4], char* smem)
{
    const int tid  = threadIdx.x;
    const int lane = tid & 31;
    const int wm   = (tid >> 5) >> 2;
    const int wn   = (tid >> 5) & 3;
    unsigned sbase = (unsigned)__cvta_generic_to_shared(smem);

    gemm_issue_v3(sbase, 0, Ab, Bb, tid);
    gemm_issue_v3(sbase, 1, Ab + 4096, Bb + 4096, tid);

    for (int i = 0; i < 64; i++) {
        if (i < 63) cp_wait1(); else cp_wait0();
        __syncthreads();
        if (i + 2 < 64)
            gemm_issue_v3(sbase, (i + 2) % 3,
                          Ab + (size_t)(i + 2) * 4096,
                          Bb + (size_t)(i + 2) * 4096, tid);
        gemm_compute_v3(smem + (i % 3) * STAGE_BYTES, acc, lane, wm, wn);
    }
}

// fused Q/K/V projections: 1024 blocks (512 Q, 256 K, 256 V)
__global__ __launch_bounds__(256, 2) void gemm_qkv(
    const unsigned* __restrict__ Ap,
    const float* __restrict__ bq, const float* __restrict__ bk,
    const float* __restrict__ bv,
    float* __restrict__ Qout, float* __restrict__ Kout)
{
    extern __shared__ char smem[];
    const int id = blockIdx.x;
    const unsigned* Bp; const float* bias; float* outp;
    int bx, by, N, vmode = 0;
    if (id < 512)      { Bp = g_Wqp; bias = bq; outp = Qout; bx = id & 15;  by = id >> 4; N = 2048; }
    else if (id < 768) { int t = id - 512; Bp = g_Wkp; bias = bk; outp = Kout; bx = t & 7; by = t >> 3; N = 1024; }
    else               { int t = id - 768; Bp = g_Wvp; bias = bv; outp = nullptr; bx = t & 7; by = t >> 3; N = 1024; vmode = 1; }

    float acc[4][4][4];
#pragma unroll
    for (int i = 0; i < 4; i++)
#pragma unroll
        for (int j = 0; j < 4; j++)
#pragma unroll
            for (int e = 0; e < 4; e++) acc[i][j][e] = 0.0f;

    gemm_main_v4(Ap + (size_t)by * 64 * 4096, Bp + (size_t)bx * 64 * 4096, acc, smem);

    const int lane = threadIdx.x & 31;
    const int warp = threadIdx.x >> 5;
    const int wm = warp >> 2, wn = warp & 3;
#pragma unroll
    for (int mf = 0; mf < 4; mf++) {
        int row = by * 128 + wm * 64 + mf * 16 + (lane >> 2);
#pragma unroll
        for (int nf = 0; nf < 4; nf++) {
            int col = bx * 128 + wn * 32 + nf * 8 + 2 * (lane & 3);
            float b0 = bias[col], b1 = bias[col + 1];
            float v00 = acc[mf][nf][0] + b0, v01 = acc[mf][nf][1] + b1;
            float v10 = acc[mf][nf][2] + b0, v11 = acc[mf][nf][3] + b1;
            if (!vmode) {
                *(float2*)&outp[(size_t)row * N + col]       = make_float2(v00, v01);
                *(float2*)&outp[(size_t)(row + 8) * N + col] = make_float2(v10, v11);
            } else {
                int bb = row >> 11, s = row & 2047;
                int kvh = col >> 7, d = col & 127;
                size_t base = ((size_t)(bb * NKV_ + kvh) * D_ + d) * S_;
                __nv_bfloat16 h;
                h = __float2bfloat16_rn(v00);
                g_Vth[base + s] = h;
                g_Vtl[base + s] = __float2bfloat16_rn(v00 - __bfloat162float(h));
                h = __float2bfloat16_rn(v01);
                g_Vth[base + S_ + s] = h;
                g_Vtl[base + S_ + s] = __float2bfloat16_rn(v01 - __bfloat162float(h));
                h = __float2bfloat16_rn(v10);
                g_Vth[base + s + 8] = h;
                g_Vtl[base + s + 8] = __float2bfloat16_rn(v10 - __bfloat162float(h));
                h = __float2bfloat16_rn(v11);
                g_Vth[base + S_ + s + 8] = h;
                g_Vtl[base + S_ + s + 8] = __float2bfloat16_rn(v11 - __bfloat162float(h));
            }
        }
    }
}

// standalone GEMM (O projection)
__global__ __launch_bounds__(256, 2) void gemm_v3(
    const unsigned* __restrict__ Ap, const unsigned* __restrict__ Bp,
    const float* __restrict__ bias, float* __restrict__ C, int N)
{
    extern __shared__ char smem[];
    float acc[4][4][4];
#pragma unroll
    for (int i = 0; i < 4; i++)
#pragma unroll
        for (int j = 0; j < 4; j++)
#pragma unroll
            for (int e = 0; e < 4; e++) acc[i][j][e] = 0.0f;

    gemm_main_v4(Ap + (size_t)blockIdx.y * 64 * 4096,
                 Bp + (size_t)blockIdx.x * 64 * 4096, acc, smem);

    const int lane = threadIdx.x & 31;
    const int warp = threadIdx.x >> 5;
    const int wm = warp >> 2, wn = warp & 3;
#pragma unroll
    for (int mf = 0; mf < 4; mf++) {
        int row = blockIdx.y * 128 + wm * 64 + mf * 16 + (lane >> 2);
#pragma unroll
        for (int nf = 0; nf < 4; nf++) {
            int col = blockIdx.x * 128 + wn * 32 + nf * 8 + 2 * (lane & 3);
            float b0 = 0.0f, b1 = 0.0f;
            if (bias) { b0 = bias[col]; b1 = bias[col + 1]; }
            *(float2*)&C[(size_t)row * N + col] =
                make_float2(acc[mf][nf][0] + b0, acc[mf][nf][1] + b1);
            *(float2*)&C[(size_t)(row + 8) * N + col] =
                make_float2(acc[mf][nf][2] + b0, acc[mf][nf][3] + b1);
        }
    }
}

// ============================================================
// RoPE tables + rope/split pass for Q,K (unchanged)
// ============================================================
__global__ void rope_table_kernel()
{
    int idx = blockIdx.x * blockDim.x + threadIdx.x;
    if (idx >= S_ * 64) return;
    int s = idx >> 6, i = idx & 63;
    const double NEG_LOG_STEP = -0.2158673524681918;
    double freq = exp((double)i * NEG_LOG_STEP);
    double sd, cd;
    sincos((double)s * freq, &sd, &cd);
    g_cos[idx] = (float)cd;
    g_sin[idx] = (float)sd;
}

__global__ void rope_split_kernel()
{
    __shared__ float sc[64], ss[64];
    const int bs = blockIdx.x;
    const int s  = bs % S_;
    if (threadIdx.x < 64) {
        sc[threadIdx.x] = g_cos[s * 64 + threadIdx.x];
        ss[threadIdx.x] = g_sin[s * 64 + threadIdx.x];
    }
    __syncthreads();

    for (int p = threadIdx.x; p < (NH_ + NKV_) * 64; p += blockDim.x) {
        int head = p >> 6;
        int i    = p & 63;
        float c = sc[i], sn = ss[i];
        if (head < NH_) {
            size_t base = ((size_t)bs * NH_ + head) * D_;
            float x1 = g_Q[base + i], x2 = g_Q[base + i + 64];
            float o1 = x1 * c - x2 * sn;
            float o2 = x2 * c + x1 * sn;
            __nv_bfloat16 h1 = __float2bfloat16_rn(o1);
            __nv_bfloat16 h2 = __float2bfloat16_rn(o2);
            g_Qh[base + i]      = h1;
            g_Ql[base + i]      = __float2bfloat16_rn(o1 - __bfloat162float(h1));
            g_Qh[base + i + 64] = h2;
            g_Ql[base + i + 64] = __float2bfloat16_rn(o2 - __bfloat162float(h2));
        } else {
            size_t base = ((size_t)bs * NKV_ + (head - NH_)) * D_;
            float x1 = g_K[base + i], x2 = g_K[base + i + 64];
            float o1 = x1 * c - x2 * sn;
            float o2 = x2 * c + x1 * sn;
            __nv_bfloat16 h1 = __float2bfloat16_rn(o1);
            __nv_bfloat16 h2 = __float2bfloat16_rn(o2);
            g_Kh[base + i]      = h1;
            g_Kl[base + i]      = __float2bfloat16_rn(o1 - __bfloat162float(h1));
            g_Kh[base + i + 64] = h2;
            g_Kl[base + i + 64] = __float2bfloat16_rn(o2 - __bfloat162float(h2));
        }
    }
}

// ============================================================
// Flash attention (identical to R7, passing).
// ============================================================
#define BQ 128
#define QH_OFF 0
#define QL_OFF (QH_OFF + BQ*136*2)
#define ST0_OFF (QL_OFF + BQ*136*2)
#define KH_SZ (64*136*2)
#define VH_SZ (128*72*2)
#define STAGE_SZ (2*KH_SZ + 2*VH_SZ)
#define FLASH_SMEM (ST0_OFF + 2*STAGE_SZ)     // 212992

__device__ __forceinline__ void flash_issue(
    unsigned sbase, int stage, int b, int kvh, int kb, int tid)
{
    unsigned st = sbase + ST0_OFF + stage * STAGE_SZ;
#pragma unroll
    for (int p = 0; p < 4; p++) {
        int id = tid + p * 256;
        int r = id >> 4, c8 = (id & 15) << 3;
        size_t go = (((size_t)(b * S_ + kb + r)) * NKV_ + kvh) * D_ + c8;
        unsigned so = st + (r * 136 + c8) * 2;
        cp16(so,         g_Kh + go);
        cp16(so + KH_SZ, g_Kl + go);
    }
#pragma unroll
    for (int p = 0; p < 4; p++) {
        int id = tid + p * 256;
        int d = id >> 3, c8 = (id & 7) << 3;
        size_t go = ((size_t)(b * NKV_ + kvh) * D_ + d) * S_ + kb + c8;
        unsigned so = st + 2 * KH_SZ + (d * 72 + c8) * 2;
        cp16(so,         g_Vth + go);
        cp16(so + VH_SZ, g_Vtl + go);
    }
    cp_commit();
}

__global__ __launch_bounds__(256, 1) void flash_bf16()
{
    extern __shared__ char sm[];
    const int tid  = threadIdx.x;
    const int lane = tid & 31;
    const int warp = tid >> 5;
    const int qtile = (gridDim.x - 1) - blockIdx.x;
    const int h    = blockIdx.y;
    const int b    = blockIdx.z;
    const int kvh  = h / G_;
    const int qbase = qtile * BQ;
    const float scale = 0.08838834764831845f;
    const int g = lane >> 2;
    const int t = lane & 3;
    const int m0 = warp * 16;
    unsigned sbase = (unsigned)__cvta_generic_to_shared(sm);

    flash_issue(sbase, 0, b, kvh, 0, tid);

    for (int it = tid; it < BQ * 16; it += 256) {
        int r = it >> 4, c8 = (it & 15) << 3;
        size_t go = (((size_t)(b * S_ + qbase + r)) * NH_ + h) * D_ + c8;
        *(uint4*)(sm + QH_OFF + (r * 136 + c8) * 2) = *(const uint4*)(g_Qh + go);
        *(uint4*)(sm + QL_OFF + (r * 136 + c8) * 2) = *(const uint4*)(g_Ql + go);
    }

    float ctx[16][4];
#pragma unroll
    for (int i = 0; i < 16; i++)
#pragma unroll
        for (int e = 0; e < 4; e++) ctx[i][e] = 0.0f;
    float mr0 = -INFINITY, mr1 = -INFINITY, lr0 = 0.0f, lr1 = 0.0f;

    const int row0 = qbase + m0 + g;
    const int row1 = row0 + 8;
    const int ntile = 2 * qtile + 2;

    for (int j = 0; j < ntile; j++) {
        const int kb = j * 64;
        if (j + 1 < ntile) {
            flash_issue(sbase, (j + 1) & 1, b, kvh, (j + 1) * 64, tid);
            cp_wait1();
        } else {
            cp_wait0();
        }
        __syncthreads();

        const char* stK  = sm + ST0_OFF + (j & 1) * STAGE_SZ;
        const char* stKL = stK + KH_SZ;
        const char* stV  = stK + 2 * KH_SZ;
        const char* stVL = stV + VH_SZ;

        float acc[8][4];
#pragma unroll
        for (int nf = 0; nf < 8; nf++)
#pragma unroll
            for (int e = 0; e < 4; e++) acc[nf][e] = 0.0f;

#pragma unroll
        for (int kk = 0; kk < 8; kk++) {
            int c = kk * 16 + 2 * t;
            unsigned aH[4], aL[4];
            aH[0] = *(const unsigned*)(sm + QH_OFF + ((m0+g)*136 + c)*2);
            aH[1] = *(const unsigned*)(sm + QH_OFF + ((m0+g+8)*136 + c)*2);
            aH[2] = *(const unsigned*)(sm + QH_OFF + ((m0+g)*136 + c + 8)*2);
            aH[3] = *(const unsigned*)(sm + QH_OFF + ((m0+g+8)*136 + c + 8)*2);
            aL[0] = *(const unsigned*)(sm + QL_OFF + ((m0+g)*136 + c)*2);
            aL[1] = *(const unsigned*)(sm + QL_OFF + ((m0+g+8)*136 + c)*2);
            aL[2] = *(const unsigned*)(sm + QL_OFF + ((m0+g)*136 + c + 8)*2);
            aL[3] = *(const unsigned*)(sm + QL_OFF + ((m0+g+8)*136 + c + 8)*2);
#pragma unroll
            for (int nf = 0; nf < 8; nf++) {
                int n = nf * 8 + g;
                unsigned bH[2], bL[2];
                bH[0] = *(const unsigned*)(stK  + (n*136 + c)*2);
                bH[1] = *(const unsigned*)(stK  + (n*136 + c + 8)*2);
                bL[0] = *(const unsigned*)(stKL + (n*136 + c)*2);
                bL[1] = *(const unsigned*)(stKL + (n*136 + c + 8)*2);
                mma_bf16(acc[nf], aH, bH);
                mma_bf16(acc[nf], aH, bL);
                mma_bf16(acc[nf], aL, bH);
            }
        }

#pragma unroll
        for (int nf = 0; nf < 8; nf++)
#pragma unroll
            for (int e = 0; e < 4; e++) acc[nf][e] *= scale;

        if (kb + 63 > qbase + m0) {
#pragma unroll
            for (int nf = 0; nf < 8; nf++) {
                int k0 = kb + nf * 8 + 2 * t;
                if (k0     > row0) acc[nf][0] = -INFINITY;
                if (k0 + 1 > row0) acc[nf][1] = -INFINITY;
                if (k0     > row1) acc[nf][2] = -INFINITY;
                if (k0 + 1 > row1) acc[nf][3] = -INFINITY;
            }
        }

        float mx0 = -INFINITY, mx1 = -INFINITY;
#pragma unroll
        for (int nf = 0; nf < 8; nf++) {
            mx0 = fmaxf(mx0, fmaxf(acc[nf][0], acc[nf][1]));
            mx1 = fmaxf(mx1, fmaxf(acc[nf][2], acc[nf][3]));
        }
        mx0 = fmaxf(mx0, __shfl_xor_sync(0xffffffffu, mx0, 1));
        mx0 = fmaxf(mx0, __shfl_xor_sync(0xffffffffu, mx0, 2));
        mx1 = fmaxf(mx1, __shfl_xor_sync(0xffffffffu, mx1, 1));
        mx1 = fmaxf(mx1, __shfl_xor_sync(0xffffffffu, mx1, 2));

        float mn0 = fmaxf(mr0, mx0);
        float mn1 = fmaxf(mr1, mx1);
        float al0 = __expf(mr0 - mn0);
        float al1 = __expf(mr1 - mn1);
        mr0 = mn0; mr1 = mn1;

        unsigned pH[4][4], pL[4][4];
        float s0 = 0.0f, s1 = 0.0f;
#pragma unroll
        for (int nf = 0; nf < 8; nf++) {
            float p00 = __expf(acc[nf][0] - mn0);
            float p01 = __expf(acc[nf][1] - mn0);
            float p10 = __expf(acc[nf][2] - mn1);
            float p11 = __expf(acc[nf][3] - mn1);
            s0 += p00 + p01;
            s1 += p10 + p11;
            int kk2 = nf >> 1;
            int sl  = (nf & 1) << 1;
            split2(p00, p01, pH[kk2][sl],     pL[kk2][sl]);
            split2(p10, p11, pH[kk2][sl + 1], pL[kk2][sl + 1]);
        }
        s0 += __shfl_xor_sync(0xffffffffu, s0, 1);
        s0 += __shfl_xor_sync(0xffffffffu, s0, 2);
        s1 += __shfl_xor_sync(0xffffffffu, s1, 1);
        s1 += __shfl_xor_sync(0xffffffffu, s1, 2);
        lr0 = lr0 * al0 + s0;
        lr1 = lr1 * al1 + s1;

#pragma unroll
        for (int nf = 0; nf < 16; nf++) {
            ctx[nf][0] *= al0; ctx[nf][1] *= al0;
            ctx[nf][2] *= al1; ctx[nf][3] *= al1;
        }
#pragma unroll
        for (int kk2 = 0; kk2 < 4; kk2++) {
            int c = kk2 * 16 + 2 * t;
#pragma unroll
            for (int nf = 0; nf < 16; nf++) {
                int n = nf * 8 + g;
                unsigned vH[2], vL[2];
                vH[0] = *(const unsigned*)(stV  + (n*72 + c)*2);
                vH[1] = *(const unsigned*)(stV  + (n*72 + c + 8)*2);
                vL[0] = *(const unsigned*)(stVL + (n*72 + c)*2);
                vL[1] = *(const unsigned*)(stVL + (n*72 + c + 8)*2);
                mma_bf16(ctx[nf], pH[kk2], vH);
                mma_bf16(ctx[nf], pL[kk2], vH);
                mma_bf16(ctx[nf], pH[kk2], vL);
            }
        }
        __syncthreads();
    }

    float il0 = 1.0f / lr0;
    float il1 = 1.0f / lr1;
    float* o0 = g_C + (((size_t)(b * S_ + row0)) * NH_ + h) * D_;
    float* o1 = g_C + (((size_t)(b * S_ + row1)) * NH_ + h) * D_;
#pragma unroll
    for (int nf = 0; nf < 16; nf++) {
        int d = nf * 8 + 2 * t;
        *(float2*)(o0 + d) = make_float2(ctx[nf][0] * il0, ctx[nf][1] * il0);
        *(float2*)(o1 + d) = make_float2(ctx[nf][2] * il1, ctx[nf][3] * il1);
    }
}

// ============================================================
// launch
// ============================================================
extern "C" void kernel_launch(void* const* d_in, const int* in_sizes, int n_in,
                              void* d_out, int out_size)
{
    (void)in_sizes; (void)n_in; (void)out_size;
    const float* hidden = (const float*)d_in[0];
    const float* Wq = (const float*)d_in[1];
    const float* bq = (const float*)d_in[2];
    const float* Wk = (const float*)d_in[3];
    const float* bk = (const float*)d_in[4];
    const float* Wv = (const float*)d_in[5];
    const float* bv = (const float*)d_in[6];
    const float* Wo = (const float*)d_in[7];
    float* out = (float*)d_out;

    float *qp, *kp, *cp;
    unsigned *xp, *ctp, *wop;
    cudaGetSymbolAddress((void**)&qp,  g_Q);
    cudaGetSymbolAddress((void**)&kp,  g_K);
    cudaGetSymbolAddress((void**)&cp,  g_C);
    cudaGetSymbolAddress((void**)&xp,  g_Xp);
    cudaGetSymbolAddress((void**)&ctp, g_Ctp);
    cudaGetSymbolAddress((void**)&wop, g_Wop);

    cudaFuncSetAttribute(gemm_qkv,
        cudaFuncAttributeMaxDynamicSharedMemorySize, GEMM_SMEM);
    cudaFuncSetAttribute(gemm_v3,
        cudaFuncAttributeMaxDynamicSharedMemorySize, GEMM_SMEM);
    cudaFuncSetAttribute(flash_bf16,
        cudaFuncAttributeMaxDynamicSharedMemorySize, FLASH_SMEM);

    const int NB3 = (2048 + 1024 + 1024) * HID_ / 2;

    // 1: pack hidden (A-packed tf32)
    pack_a<<<(BSR_ * HID_ / 4 + 255) / 256, 256>>>(hidden, xp);
    // 2: pack Wq+Wk+Wv
    pack_b3<<<(NB3 + 255) / 256, 256>>>(Wq, Wk, Wv);
    // 3: RoPE tables
    rope_table_kernel<<<(S_ * 64 + 255) / 256, 256>>>();
    // 4: fused QKV projections  ← profiled launch
    gemm_qkv<<<1024, 256, GEMM_SMEM>>>(xp, bq, bk, bv, qp, kp);
    // 5: pack Wo
    pack_b<<<(2048 * HID_ / 2 + 255) / 256, 256>>>(Wo, wop, 2048);
    // 6: RoPE + bf16 split of Q,K
    rope_split_kernel<<<BSR_, 256>>>();
    // 7: flash attention
    flash_bf16<<<dim3(S_ / BQ, NH_, B_), 256, FLASH_SMEM>>>();
    // 8: pack ctx
    pack_a<<<(BSR_ * HID_ / 4 + 255) / 256, 256>>>(cp, ctp);
    // 9: O projection
    gemm_v3<<<dim3(16, 32), 256, GEMM_SMEM>>>(ctp, wop, nullptr, out, HID_);
}

// round 9
// speedup vs baseline: 4.6199x; 1.0141x over previous
#include <cuda_runtime.h>
#include <cuda_bf16.h>
#include <math.h>

#define B_    2
#define S_    2048
#define HID_  2048
#define NH_   16
#define NKV_  8
#define D_    128
#define G_    (NH_/NKV_)
#define BSR_  (B_*S_)          // 4096

// -------- scratch (__device__ globals; no allocations) --------
__device__ __nv_bfloat16 g_Qh[BSR_ * NH_ * D_];     // roped Q hi/lo
__device__ __nv_bfloat16 g_Ql[BSR_ * NH_ * D_];
__device__ __nv_bfloat16 g_Kh[BSR_ * NKV_ * D_];    // roped K hi/lo
__device__ __nv_bfloat16 g_Kl[BSR_ * NKV_ * D_];
__device__ __nv_bfloat16 g_Vth[BSR_ * NKV_ * D_];   // V^T hi/lo [b][kvh][d][s]
__device__ __nv_bfloat16 g_Vtl[BSR_ * NKV_ * D_];
__device__ unsigned g_Xp [BSR_ * HID_];             // hidden, A-packed tf32
__device__ unsigned g_Ctp[BSR_ * NH_ * D_];         // ctx, A-packed tf32
__device__ unsigned g_Wqp[HID_ * NH_ * D_];         // weights, B-packed tf32
__device__ unsigned g_Wkp[HID_ * NKV_ * D_];
__device__ unsigned g_Wvp[HID_ * NKV_ * D_];
__device__ unsigned g_Wop[NH_ * D_ * HID_];
__device__ float g_cos[S_ * 64];
__device__ float g_sin[S_ * 64];

// ---------------- helpers ----------------
__device__ __forceinline__ unsigned f2tf(float x) {
    unsigned u;
    asm("cvt.rna.tf32.f32 %0, %1;" : "=r"(u) : "f"(x));
    return u;
}
__device__ __forceinline__ void cp16(unsigned dst, const void* src) {
    asm volatile("cp.async.cg.shared.global [%0], [%1], 16;" :: "r"(dst), "l"(src));
}
__device__ __forceinline__ void cp_commit() { asm volatile("cp.async.commit_group;"); }
__device__ __forceinline__ void cp_wait1()  { asm volatile("cp.async.wait_group 1;"); }
__device__ __forceinline__ void cp_wait0()  { asm volatile("cp.async.wait_group 0;"); }

__device__ __forceinline__ void split2(float x, float y, unsigned& hi, unsigned& lo) {
    __nv_bfloat16 hx = __float2bfloat16_rn(x);
    __nv_bfloat16 hy = __float2bfloat16_rn(y);
    float rx = x - __bfloat162float(hx);
    float ry = y - __bfloat162float(hy);
    __nv_bfloat162 h; h.x = hx; h.y = hy;
    __nv_bfloat162 l; l.x = __float2bfloat16_rn(rx); l.y = __float2bfloat16_rn(ry);
    hi = *(unsigned*)&h;
    lo = *(unsigned*)&l;
}

__device__ __forceinline__ void mma_tf32(float* d, const unsigned* a, const unsigned* b) {
    asm volatile(
        "mma.sync.aligned.m16n8k8.row.col.f32.tf32.tf32.f32 "
        "{%0,%1,%2,%3}, {%4,%5,%6,%7}, {%8,%9}, {%0,%1,%2,%3};\n"
        : "+f"(d[0]), "+f"(d[1]), "+f"(d[2]), "+f"(d[3])
        : "r"(a[0]), "r"(a[1]), "r"(a[2]), "r"(a[3]), "r"(b[0]), "r"(b[1]));
}
__device__ __forceinline__ void mma_bf16(float* d, const unsigned* a, const unsigned* b) {
    asm volatile(
        "mma.sync.aligned.m16n8k16.row.col.f32.bf16.bf16.f32 "
        "{%0,%1,%2,%3}, {%4,%5,%6,%7}, {%8,%9}, {%0,%1,%2,%3};\n"
        : "+f"(d[0]), "+f"(d[1]), "+f"(d[2]), "+f"(d[3])
        : "r"(a[0]), "r"(a[1]), "r"(a[2]), "r"(a[3]), "r"(b[0]), "r"(b[1]));
}

// ============================================================
// Fused packing of all GEMM operands (layouts validated R7/R8).
// ============================================================
__device__ __forceinline__ void pack_a_one(
    const float* __restrict__ A, unsigned* __restrict__ P, int id)
{
    int w      = id & 1023;
    int chunk  = id >> 10;
    int kchunk = chunk & 63;
    int mtile  = chunk >> 6;
    int lane = w & 31, rf = (w >> 5) & 7, kk = w >> 8;
    int row = mtile * 128 + rf * 16 + (lane >> 2);
    int col = kchunk * 32 + kk * 8 + (lane & 3);
    const float* a0 = A + (size_t)row * HID_ + col;
    ((uint4*)P)[id] = make_uint4(
        f2tf(a0[0]), f2tf(a0[8 * HID_]), f2tf(a0[4]), f2tf(a0[8 * HID_ + 4]));
}

__device__ __forceinline__ void pack_b_one(
    const float* __restrict__ W, unsigned* __restrict__ P, int N, int id)
{
    int w      = id & 2047;
    int chunk  = id >> 11;
    int kchunk = chunk & 63;
    int ntile  = chunk >> 6;
    int lane = w & 31, nb = (w >> 5) & 15, kk = w >> 9;
    int n = ntile * 128 + nb * 8 + (lane >> 2);
    int c = kchunk * 32 + kk * 8 + (lane & 3);
    ((uint2*)P)[id] = make_uint2(
        f2tf(W[(size_t)c * N + n]), f2tf(W[(size_t)(c + 4) * N + n]));
}

__global__ void pack_all(const float* __restrict__ X,
                         const float* __restrict__ Wq, const float* __restrict__ Wk,
                         const float* __restrict__ Wv, const float* __restrict__ Wo)
{
    const int NA = (BSR_ * HID_) / 4;       // uint4 jobs
    const int NQ = (2048 * HID_) / 2;       // uint2 jobs
    const int NK = (1024 * HID_) / 2;
    int id = blockIdx.x * blockDim.x + threadIdx.x;
    if (id < NA) { pack_a_one(X, g_Xp, id); return; }
    id -= NA;
    if (id < NQ)              { pack_b_one(Wq, g_Wqp, 2048, id); return; }
    if (id < NQ + NK)         { pack_b_one(Wk, g_Wkp, 1024, id - NQ); return; }
    if (id < NQ + 2 * NK)     { pack_b_one(Wv, g_Wvp, 1024, id - NQ - NK); return; }
    if (id < NQ + 2 * NK + NQ)  pack_b_one(Wo, g_Wop, 2048, id - NQ - 2 * NK);
}

// ============================================================
// RoPE tables
// ============================================================
__global__ void rope_table_kernel()
{
    int idx = blockIdx.x * blockDim.x + threadIdx.x;
    if (idx >= S_ * 64) return;
    int s = idx >> 6, i = idx & 63;
    const double NEG_LOG_STEP = -0.2158673524681918;
    double freq = exp((double)i * NEG_LOG_STEP);
    double sd, cd;
    sincos((double)s * freq, &sd, &cd);
    g_cos[idx] = (float)cd;
    g_sin[idx] = (float)sd;
}

// ============================================================
// TF32 GEMM core: fragment-packed, 3-stage cp.async, one barrier/chunk.
// ============================================================
#define CHUNK_BYTES 16384
#define STAGE_BYTES (2 * CHUNK_BYTES)
#define GEMM_SMEM   (3 * STAGE_BYTES)          // 98304

__device__ __forceinline__ void gemm_issue_v3(
    unsigned sbase, int stage, const unsigned* __restrict__ Ac,
    const unsigned* __restrict__ Bc, int tid)
{
    unsigned st = sbase + stage * STAGE_BYTES;
#pragma unroll
    for (int p = 0; p < 4; p++) {
        int id = tid + p * 256;
        cp16(st + id * 16,               Ac + id * 4);
        cp16(st + CHUNK_BYTES + id * 16, Bc + id * 4);
    }
    cp_commit();
}

__device__ __forceinline__ void gemm_compute_v3(
    const char* st, float acc[4][4][4], int lane, int wm, int wn)
{
    const char* sA = st;
    const char* sB = st + CHUNK_BYTES;
#pragma unroll
    for (int kk = 0; kk < 4; kk++) {
        uint4 a[4]; uint2 b[4];
#pragma unroll
        for (int mf = 0; mf < 4; mf++)
            a[mf] = *(const uint4*)(sA + (((kk * 8 + wm * 4 + mf) * 32) + lane) * 16);
#pragma unroll
        for (int nf = 0; nf < 4; nf++)
            b[nf] = *(const uint2*)(sB + (((kk * 16 + wn * 4 + nf) * 32) + lane) * 8);
#pragma unroll
        for (int mf = 0; mf < 4; mf++)
#pragma unroll
            for (int nf = 0; nf < 4; nf++)
                mma_tf32(acc[mf][nf], (const unsigned*)&a[mf], (const unsigned*)&b[nf]);
    }
}

__device__ __forceinline__ void gemm_main_v4(
    const unsigned* __restrict__ Ab, const unsigned* __restrict__ Bb,
    float acc[4][4][4], char* smem)
{
    const int tid  = threadIdx.x;
    const int lane = tid & 31;
    const int wm   = (tid >> 5) >> 2;
    const int wn   = (tid >> 5) & 3;
    unsigned sbase = (unsigned)__cvta_generic_to_shared(smem);

    gemm_issue_v3(sbase, 0, Ab, Bb, tid);
    gemm_issue_v3(sbase, 1, Ab + 4096, Bb + 4096, tid);

    for (int i = 0; i < 64; i++) {
        if (i < 63) cp_wait1(); else cp_wait0();
        __syncthreads();
        if (i + 2 < 64)
            gemm_issue_v3(sbase, (i + 2) % 3,
                          Ab + (size_t)(i + 2) * 4096,
                          Bb + (size_t)(i + 2) * 4096, tid);
        gemm_compute_v3(smem + (i % 3) * STAGE_BYTES, acc, lane, wm, wn);
    }
}

// ============================================================
// Fused QKV projections with rope/split/transpose epilogues.
// 1024 blocks: 512 Q, 256 K, 256 V. Smem tile staged at [128][132].
// ============================================================
__global__ __launch_bounds__(256, 2) void gemm_qkv(
    const unsigned* __restrict__ Ap,
    const float* __restrict__ bq, const float* __restrict__ bk,
    const float* __restrict__ bv)
{
    extern __shared__ char smem[];
    float* sf = (float*)smem;                  // staging tile (67.6 KB <= 96 KB)
    const int id = blockIdx.x;
    const unsigned* Bp; const float* bias;
    int bx, by, mode;                          // mode 0=Q,1=K,2=V
    if (id < 512)      { Bp = g_Wqp; bias = bq; bx = id & 15; by = id >> 4; mode = 0; }
    else if (id < 768) { int t = id - 512; Bp = g_Wkp; bias = bk; bx = t & 7; by = t >> 3; mode = 1; }
    else               { int t = id - 768; Bp = g_Wvp; bias = bv; bx = t & 7; by = t >> 3; mode = 2; }

    float acc[4][4][4];
#pragma unroll
    for (int i = 0; i < 4; i++)
#pragma unroll
        for (int j = 0; j < 4; j++)
#pragma unroll
            for (int e = 0; e < 4; e++) acc[i][j][e] = 0.0f;

    gemm_main_v4(Ap + (size_t)by * 64 * 4096, Bp + (size_t)bx * 64 * 4096, acc, smem);
    __syncthreads();                           // mainloop done with smem

    const int tid  = threadIdx.x;
    const int lane = tid & 31;
    const int warp = tid >> 5;
    const int wm = warp >> 2, wn = warp & 3;

    // ---- stage tile in smem (Q/K: row-major [r][132]; V: transposed [col][132]) ----
#pragma unroll
    for (int mf = 0; mf < 4; mf++) {
        int r = wm * 64 + mf * 16 + (lane >> 2);
#pragma unroll
        for (int nf = 0; nf < 4; nf++) {
            int col = wn * 32 + nf * 8 + 2 * (lane & 3);
            float b0 = bias[bx * 128 + col], b1 = bias[bx * 128 + col + 1];
            float v00 = acc[mf][nf][0] + b0, v01 = acc[mf][nf][1] + b1;
            float v10 = acc[mf][nf][2] + b0, v11 = acc[mf][nf][3] + b1;
            if (mode != 2) {
                *(float2*)(sf + r * 132 + col)       = make_float2(v00, v01);
                *(float2*)(sf + (r + 8) * 132 + col) = make_float2(v10, v11);
            } else {
                sf[col * 132 + r]           = v00;
                sf[(col + 1) * 132 + r]     = v01;
                sf[col * 132 + r + 8]       = v10;
                sf[(col + 1) * 132 + r + 8] = v11;
            }
        }
    }
    __syncthreads();

    if (mode != 2) {
        // ---- Q/K: rope + bf16 hi/lo split, row-major out ----
        __nv_bfloat16* Oh = mode ? g_Kh : g_Qh;
        __nv_bfloat16* Ol = mode ? g_Kl : g_Ql;
        const int NHx = mode ? NKV_ : NH_;
        for (int it = tid; it < 128 * 64; it += 256) {
            int r = it >> 6, i = it & 63;
            int row = by * 128 + r;
            int s = row & (S_ - 1);
            float c  = g_cos[s * 64 + i];
            float sn = g_sin[s * 64 + i];
            float x1 = sf[r * 132 + i];
            float x2 = sf[r * 132 + i + 64];
            float o1 = x1 * c - x2 * sn;
            float o2 = x2 * c + x1 * sn;
            size_t base = ((size_t)row * NHx + bx) * D_;
            __nv_bfloat16 h1 = __float2bfloat16_rn(o1);
            __nv_bfloat16 h2 = __float2bfloat16_rn(o2);
            Oh[base + i]      = h1;
            Ol[base + i]      = __float2bfloat16_rn(o1 - __bfloat162float(h1));
            Oh[base + i + 64] = h2;
            Ol[base + i + 64] = __float2bfloat16_rn(o2 - __bfloat162float(h2));
        }
    } else {
        // ---- V: coalesced transposed hi/lo out: Vt[b][kvh][d][s] ----
        const int bb = (by * 128) >> 11;
        const int s0 = (by * 128) & (S_ - 1);
        for (int it = tid; it < 128 * 16; it += 256) {
            int d = it >> 4, sg = it & 15;
            float4 v0 = *(const float4*)(sf + d * 132 + sg * 8);
            float4 v1 = *(const float4*)(sf + d * 132 + sg * 8 + 4);
            unsigned h01, l01, h23, l23, h45, l45, h67, l67;
            split2(v0.x, v0.y, h01, l01); split2(v0.z, v0.w, h23, l23);
            split2(v1.x, v1.y, h45, l45); split2(v1.z, v1.w, h67, l67);
            size_t base = ((size_t)(bb * NKV_ + bx) * D_ + d) * S_ + s0 + sg * 8;
            *(uint4*)(g_Vth + base) = make_uint4(h01, h23, h45, h67);
            *(uint4*)(g_Vtl + base) = make_uint4(l01, l23, l45, l67);
        }
    }
}

// ============================================================
// O projection GEMM (unchanged core; writes final out)
// ============================================================
__global__ __launch_bounds__(256, 2) void gemm_v3(
    const unsigned* __restrict__ Ap, const unsigned* __restrict__ Bp,
    float* __restrict__ C, int N)
{
    extern __shared__ char smem[];
    float acc[4][4][4];
#pragma unroll
    for (int i = 0; i < 4; i++)
#pragma unroll
        for (int j = 0; j < 4; j++)
#pragma unroll
            for (int e = 0; e < 4; e++) acc[i][j][e] = 0.0f;

    gemm_main_v4(Ap + (size_t)blockIdx.y * 64 * 4096,
                 Bp + (size_t)blockIdx.x * 64 * 4096, acc, smem);

    const int lane = threadIdx.x & 31;
    const int warp = threadIdx.x >> 5;
    const int wm = warp >> 2, wn = warp & 3;
#pragma unroll
    for (int mf = 0; mf < 4; mf++) {
        int row = blockIdx.y * 128 + wm * 64 + mf * 16 + (lane >> 2);
#pragma unroll
        for (int nf = 0; nf < 4; nf++) {
            int col = blockIdx.x * 128 + wn * 32 + nf * 8 + 2 * (lane & 3);
            *(float2*)&C[(size_t)row * N + col] =
                make_float2(acc[mf][nf][0], acc[mf][nf][1]);
            *(float2*)&C[(size_t)(row + 8) * N + col] =
                make_float2(acc[mf][nf][2], acc[mf][nf][3]);
        }
    }
}

// ============================================================
// Flash attention (R8 core) + fused ctx A-pack epilogue.
// ============================================================
#define BQ 128
#define QH_OFF 0
#define QL_OFF (QH_OFF + BQ*136*2)
#define ST0_OFF (QL_OFF + BQ*136*2)
#define KH_SZ (64*136*2)
#define VH_SZ (128*72*2)
#define STAGE_SZ (2*KH_SZ + 2*VH_SZ)
#define FLASH_SMEM (ST0_OFF + 2*STAGE_SZ)     // 212992

__device__ __forceinline__ void flash_issue(
    unsigned sbase, int stage, int b, int kvh, int kb, int tid)
{
    unsigned st = sbase + ST0_OFF + stage * STAGE_SZ;
#pragma unroll
    for (int p = 0; p < 4; p++) {
        int id = tid + p * 256;
        int r = id >> 4, c8 = (id & 15) << 3;
        size_t go = (((size_t)(b * S_ + kb + r)) * NKV_ + kvh) * D_ + c8;
        unsigned so = st + (r * 136 + c8) * 2;
        cp16(so,         g_Kh + go);
        cp16(so + KH_SZ, g_Kl + go);
    }
#pragma unroll
    for (int p = 0; p < 4; p++) {
        int id = tid + p * 256;
        int d = id >> 3, c8 = (id & 7) << 3;
        size_t go = ((size_t)(b * NKV_ + kvh) * D_ + d) * S_ + kb + c8;
        unsigned so = st + 2 * KH_SZ + (d * 72 + c8) * 2;
        cp16(so,         g_Vth + go);
        cp16(so + VH_SZ, g_Vtl + go);
    }
    cp_commit();
}

__global__ __launch_bounds__(256, 1) void flash_bf16()
{
    extern __shared__ char sm[];
    const int tid  = threadIdx.x;
    const int lane = tid & 31;
    const int warp = tid >> 5;
    const int qtile = (gridDim.x - 1) - blockIdx.x;
    const int h    = blockIdx.y;
    const int b    = blockIdx.z;
    const int kvh  = h / G_;
    const int qbase = qtile * BQ;
    const float scale = 0.08838834764831845f;
    const int g = lane >> 2;
    const int t = lane & 3;
    const int m0 = warp * 16;
    unsigned sbase = (unsigned)__cvta_generic_to_shared(sm);

    flash_issue(sbase, 0, b, kvh, 0, tid);

    for (int it = tid; it < BQ * 16; it += 256) {
        int r = it >> 4, c8 = (it & 15) << 3;
        size_t go = (((size_t)(b * S_ + qbase + r)) * NH_ + h) * D_ + c8;
        *(uint4*)(sm + QH_OFF + (r * 136 + c8) * 2) = *(const uint4*)(g_Qh + go);
        *(uint4*)(sm + QL_OFF + (r * 136 + c8) * 2) = *(const uint4*)(g_Ql + go);
    }

    float ctx[16][4];
#pragma unroll
    for (int i = 0; i < 16; i++)
#pragma unroll
        for (int e = 0; e < 4; e++) ctx[i][e] = 0.0f;
    float mr0 = -INFINITY, mr1 = -INFINITY, lr0 = 0.0f, lr1 = 0.0f;

    const int row0 = qbase + m0 + g;
    const int row1 = row0 + 8;
    const int ntile = 2 * qtile + 2;

    for (int j = 0; j < ntile; j++) {
        const int kb = j * 64;
        if (j + 1 < ntile) {
            flash_issue(sbase, (j + 1) & 1, b, kvh, (j + 1) * 64, tid);
            cp_wait1();
        } else {
            cp_wait0();
        }
        __syncthreads();

        const char* stK  = sm + ST0_OFF + (j & 1) * STAGE_SZ;
        const char* stKL = stK + KH_SZ;
        const char* stV  = stK + 2 * KH_SZ;
        const char* stVL = stV + VH_SZ;

        float acc[8][4];
#pragma unroll
        for (int nf = 0; nf < 8; nf++)
#pragma unroll
            for (int e = 0; e < 4; e++) acc[nf][e] = 0.0f;

#pragma unroll
        for (int kk = 0; kk < 8; kk++) {
            int c = kk * 16 + 2 * t;
            unsigned aH[4], aL[4];
            aH[0] = *(const unsigned*)(sm + QH_OFF + ((m0+g)*136 + c)*2);
            aH[1] = *(const unsigned*)(sm + QH_OFF + ((m0+g+8)*136 + c)*2);
            aH[2] = *(const unsigned*)(sm + QH_OFF + ((m0+g)*136 + c + 8)*2);
            aH[3] = *(const unsigned*)(sm + QH_OFF + ((m0+g+8)*136 + c + 8)*2);
            aL[0] = *(const unsigned*)(sm + QL_OFF + ((m0+g)*136 + c)*2);
            aL[1] = *(const unsigned*)(sm + QL_OFF + ((m0+g+8)*136 + c)*2);
            aL[2] = *(const unsigned*)(sm + QL_OFF + ((m0+g)*136 + c + 8)*2);
            aL[3] = *(const unsigned*)(sm + QL_OFF + ((m0+g+8)*136 + c + 8)*2);
#pragma unroll
            for (int nf = 0; nf < 8; nf++) {
                int n = nf * 8 + g;
                unsigned bH[2], bL[2];
                bH[0] = *(const unsigned*)(stK  + (n*136 + c)*2);
                bH[1] = *(const unsigned*)(stK  + (n*136 + c + 8)*2);
                bL[0] = *(const unsigned*)(stKL + (n*136 + c)*2);
                bL[1] = *(const unsigned*)(stKL + (n*136 + c + 8)*2);
                mma_bf16(acc[nf], aH, bH);
                mma_bf16(acc[nf], aH, bL);
                mma_bf16(acc[nf], aL, bH);
            }
        }

#pragma unroll
        for (int nf = 0; nf < 8; nf++)
#pragma unroll
            for (int e = 0; e < 4; e++) acc[nf][e] *= scale;

        if (kb + 63 > qbase + m0) {
#pragma unroll
            for (int nf = 0; nf < 8; nf++) {
                int k0 = kb + nf * 8 + 2 * t;
                if (k0     > row0) acc[nf][0] = -INFINITY;
                if (k0 + 1 > row0) acc[nf][1] = -INFINITY;
                if (k0     > row1) acc[nf][2] = -INFINITY;
                if (k0 + 1 > row1) acc[nf][3] = -INFINITY;
            }
        }

        float mx0 = -INFINITY, mx1 = -INFINITY;
#pragma unroll
        for (int nf = 0; nf < 8; nf++) {
            mx0 = fmaxf(mx0, fmaxf(acc[nf][0], acc[nf][1]));
            mx1 = fmaxf(mx1, fmaxf(acc[nf][2], acc[nf][3]));
        }
        mx0 = fmaxf(mx0, __shfl_xor_sync(0xffffffffu, mx0, 1));
        mx0 = fmaxf(mx0, __shfl_xor_sync(0xffffffffu, mx0, 2));
        mx1 = fmaxf(mx1, __shfl_xor_sync(0xffffffffu, mx1, 1));
        mx1 = fmaxf(mx1, __shfl_xor_sync(0xffffffffu, mx1, 2));

        float mn0 = fmaxf(mr0, mx0);
        float mn1 = fmaxf(mr1, mx1);
        float al0 = __expf(mr0 - mn0);
        float al1 = __expf(mr1 - mn1);
        mr0 = mn0; mr1 = mn1;

        unsigned pH[4][4], pL[4][4];
        float s0 = 0.0f, s1 = 0.0f;
#pragma unroll
        for (int nf = 0; nf < 8; nf++) {
            float p00 = __expf(acc[nf][0] - mn0);
            float p01 = __expf(acc[nf][1] - mn0);
            float p10 = __expf(acc[nf][2] - mn1);
            float p11 = __expf(acc[nf][3] - mn1);
            s0 += p00 + p01;
            s1 += p10 + p11;
            int kk2 = nf >> 1;
            int sl  = (nf & 1) << 1;
            split2(p00, p01, pH[kk2][sl],     pL[kk2][sl]);
            split2(p10, p11, pH[kk2][sl + 1], pL[kk2][sl + 1]);
        }
        s0 += __shfl_xor_sync(0xffffffffu, s0, 1);
        s0 += __shfl_xor_sync(0xffffffffu, s0, 2);
        s1 += __shfl_xor_sync(0xffffffffu, s1, 1);
        s1 += __shfl_xor_sync(0xffffffffu, s1, 2);
        lr0 = lr0 * al0 + s0;
        lr1 = lr1 * al1 + s1;

#pragma unroll
        for (int nf = 0; nf < 16; nf++) {
            ctx[nf][0] *= al0; ctx[nf][1] *= al0;
            ctx[nf][2] *= al1; ctx[nf][3] *= al1;
        }
#pragma unroll
        for (int kk2 = 0; kk2 < 4; kk2++) {
            int c = kk2 * 16 + 2 * t;
#pragma unroll
            for (int nf = 0; nf < 16; nf++) {
                int n = nf * 8 + g;
                unsigned vH[2], vL[2];
                vH[0] = *(const unsigned*)(stV  + (n*72 + c)*2);
                vH[1] = *(const unsigned*)(stV  + (n*72 + c + 8)*2);
                vL[0] = *(const unsigned*)(stVL + (n*72 + c)*2);
                vL[1] = *(const unsigned*)(stVL + (n*72 + c + 8)*2);
                mma_bf16(ctx[nf], pH[kk2], vH);
                mma_bf16(ctx[nf], pL[kk2], vH);
                mma_bf16(ctx[nf], pH[kk2], vL);
            }
        }
        __syncthreads();
    }

    // ---- fused epilogue: stage ctx f32, emit A-packed tf32 g_Ctp ----
    float* cs = (float*)(sm + ST0_OFF);        // 128x132 f32 (stage area free)
    {
        float il0 = 1.0f / lr0;
        float il1 = 1.0f / lr1;
        int rl0 = m0 + g;                      // local rows
#pragma unroll
        for (int nf = 0; nf < 16; nf++) {
            int d = nf * 8 + 2 * t;
            *(float2*)(cs + rl0 * 132 + d) =
                make_float2(ctx[nf][0] * il0, ctx[nf][1] * il0);
            *(float2*)(cs + (rl0 + 8) * 132 + d) =
                make_float2(ctx[nf][2] * il1, ctx[nf][3] * il1);
        }
    }
    __syncthreads();

    {
        const int mtile = (b * S_ + qbase) >> 7;
        for (int it = tid; it < 4096; it += 256) {
            int ln = it & 31, rf = (it >> 5) & 7, kk = (it >> 8) & 3, kc = it >> 10;
            int rl = rf * 16 + (ln >> 2);
            int cl = kc * 32 + kk * 8 + (ln & 3);
            uint4 o = make_uint4(
                f2tf(cs[rl * 132 + cl]),       f2tf(cs[(rl + 8) * 132 + cl]),
                f2tf(cs[rl * 132 + cl + 4]),   f2tf(cs[(rl + 8) * 132 + cl + 4]));
            size_t idx = ((size_t)(mtile * 64 + h * 4 + kc) << 10) +
                         (kk << 8) + (rf << 5) + ln;
            ((uint4*)g_Ctp)[idx] = o;
        }
    }
}

// ============================================================
// launch
// ============================================================
extern "C" void kernel_launch(void* const* d_in, const int* in_sizes, int n_in,
                              void* d_out, int out_size)
{
    (void)in_sizes; (void)n_in; (void)out_size;
    const float* hidden = (const float*)d_in[0];
    const float* Wq = (const float*)d_in[1];
    const float* bq = (const float*)d_in[2];
    const float* Wk = (const float*)d_in[3];
    const float* bk = (const float*)d_in[4];
    const float* Wv = (const float*)d_in[5];
    const float* bv = (const float*)d_in[6];
    const float* Wo = (const float*)d_in[7];
    float* out = (float*)d_out;

    unsigned *xp, *ctp, *wop;
    cudaGetSymbolAddress((void**)&xp,  g_Xp);
    cudaGetSymbolAddress((void**)&ctp, g_Ctp);
    cudaGetSymbolAddress((void**)&wop, g_Wop);

    cudaFuncSetAttribute(gemm_qkv,
        cudaFuncAttributeMaxDynamicSharedMemorySize, GEMM_SMEM);
    cudaFuncSetAttribute(gemm_v3,
        cudaFuncAttributeMaxDynamicSharedMemorySize, GEMM_SMEM);
    cudaFuncSetAttribute(flash_bf16,
        cudaFuncAttributeMaxDynamicSharedMemorySize, FLASH_SMEM);

    const int NPACK = BSR_ * HID_ / 4 + (2048 + 1024 + 1024 + 2048) * HID_ / 2;

    // 1: pack everything (X A-packed; Wq/Wk/Wv/Wo B-packed)
    pack_all<<<(NPACK + 255) / 256, 256>>>(hidden, Wq, Wk, Wv, Wo);
    // 2: RoPE tables
    rope_table_kernel<<<(S_ * 64 + 255) / 256, 256>>>();
    // 3: fused QKV projections + rope/split/transpose epilogues
    gemm_qkv<<<1024, 256, GEMM_SMEM>>>(xp, bq, bk, bv);
    // 4: flash attention (+ ctx A-pack epilogue)  ← profiled launch
    flash_bf16<<<dim3(S_ / BQ, NH_, B_), 256, FLASH_SMEM>>>();
    // 5: O projection → final output
    gemm_v3<<<dim3(16, 32), 256, GEMM_SMEM>>>(ctp, wop, out, HID_);
}

// round 10
// speedup vs baseline: 4.7945x; 1.0378x over previous
#include <cuda_runtime.h>
#include <cuda_bf16.h>
#include <math.h>

#define B_    2
#define S_    2048
#define HID_  2048
#define NH_   16
#define NKV_  8
#define D_    128
#define G_    (NH_/NKV_)
#define BSR_  (B_*S_)          // 4096

// -------- scratch (__device__ globals; no allocations) --------
// flash operands, mma-fragment-packed bf16 hi/lo (see layouts below)
__device__ unsigned g_Qph[BSR_ * NH_ * D_ / 2];     // [rowblk32*NH_][kk8][wr8][ln32] uint4
__device__ unsigned g_Qpl[BSR_ * NH_ * D_ / 2];
__device__ unsigned g_Kph[BSR_ * NKV_ * D_ / 2];    // [b2][kvh8][kt32][kk8][nf8][ln32] uint2
__device__ unsigned g_Kpl[BSR_ * NKV_ * D_ / 2];
__device__ unsigned g_Vph[BSR_ * NKV_ * D_ / 2];    // [b2][kvh8][kt32][kk2 4][nf16][ln32] uint2
__device__ unsigned g_Vpl[BSR_ * NKV_ * D_ / 2];
// GEMM operands, fragment-packed tf32 (R7 layouts, validated)
__device__ unsigned g_Xp [BSR_ * HID_];
__device__ unsigned g_Ctp[BSR_ * NH_ * D_];
__device__ unsigned g_Wqp[HID_ * NH_ * D_];
__device__ unsigned g_Wkp[HID_ * NKV_ * D_];
__device__ unsigned g_Wvp[HID_ * NKV_ * D_];
__device__ unsigned g_Wop[NH_ * D_ * HID_];
__device__ float g_cos[S_ * 64];
__device__ float g_sin[S_ * 64];

// ---------------- helpers ----------------
__device__ __forceinline__ unsigned f2tf(float x) {
    unsigned u;
    asm("cvt.rna.tf32.f32 %0, %1;" : "=r"(u) : "f"(x));
    return u;
}
__device__ __forceinline__ void cp16(unsigned dst, const void* src) {
    asm volatile("cp.async.cg.shared.global [%0], [%1], 16;" :: "r"(dst), "l"(src));
}
__device__ __forceinline__ void cp_commit() { asm volatile("cp.async.commit_group;"); }
__device__ __forceinline__ void cp_wait1()  { asm volatile("cp.async.wait_group 1;"); }
__device__ __forceinline__ void cp_wait0()  { asm volatile("cp.async.wait_group 0;"); }

__device__ __forceinline__ void split2(float x, float y, unsigned& hi, unsigned& lo) {
    __nv_bfloat16 hx = __float2bfloat16_rn(x);
    __nv_bfloat16 hy = __float2bfloat16_rn(y);
    float rx = x - __bfloat162float(hx);
    float ry = y - __bfloat162float(hy);
    __nv_bfloat162 h; h.x = hx; h.y = hy;
    __nv_bfloat162 l; l.x = __float2bfloat16_rn(rx); l.y = __float2bfloat16_rn(ry);
    hi = *(unsigned*)&h;
    lo = *(unsigned*)&l;
}

__device__ __forceinline__ void mma_tf32(float* d, const unsigned* a, const unsigned* b) {
    asm volatile(
        "mma.sync.aligned.m16n8k8.row.col.f32.tf32.tf32.f32 "
        "{%0,%1,%2,%3}, {%4,%5,%6,%7}, {%8,%9}, {%0,%1,%2,%3};\n"
        : "+f"(d[0]), "+f"(d[1]), "+f"(d[2]), "+f"(d[3])
        : "r"(a[0]), "r"(a[1]), "r"(a[2]), "r"(a[3]), "r"(b[0]), "r"(b[1]));
}
__device__ __forceinline__ void mma_bf16(float* d, const unsigned* a, const unsigned* b) {
    asm volatile(
        "mma.sync.aligned.m16n8k16.row.col.f32.bf16.bf16.f32 "
        "{%0,%1,%2,%3}, {%4,%5,%6,%7}, {%8,%9}, {%0,%1,%2,%3};\n"
        : "+f"(d[0]), "+f"(d[1]), "+f"(d[2]), "+f"(d[3])
        : "r"(a[0]), "r"(a[1]), "r"(a[2]), "r"(a[3]), "r"(b[0]), "r"(b[1]));
}

// RoPE of one staged element (sf row-major [r][132], raw values)
__device__ __forceinline__ float rope_elem(const float* sf, int r, int s, int c) {
    if (c < 64)
        return sf[r * 132 + c] * g_cos[s * 64 + c] - sf[r * 132 + c + 64] * g_sin[s * 64 + c];
    int i = c - 64;
    return sf[r * 132 + c] * g_cos[s * 64 + i] + sf[r * 132 + c - 64] * g_sin[s * 64 + i];
}

// ============================================================
// Fused packing of all GEMM operands (layouts validated R7/R8).
// ============================================================
__device__ __forceinline__ void pack_a_one(
    const float* __restrict__ A, unsigned* __restrict__ P, int id)
{
    int w      = id & 1023;
    int chunk  = id >> 10;
    int kchunk = chunk & 63;
    int mtile  = chunk >> 6;
    int lane = w & 31, rf = (w >> 5) & 7, kk = w >> 8;
    int row = mtile * 128 + rf * 16 + (lane >> 2);
    int col = kchunk * 32 + kk * 8 + (lane & 3);
    const float* a0 = A + (size_t)row * HID_ + col;
    ((uint4*)P)[id] = make_uint4(
        f2tf(a0[0]), f2tf(a0[8 * HID_]), f2tf(a0[4]), f2tf(a0[8 * HID_ + 4]));
}

__device__ __forceinline__ void pack_b_one(
    const float* __restrict__ W, unsigned* __restrict__ P, int N, int id)
{
    int w      = id & 2047;
    int chunk  = id >> 11;
    int kchunk = chunk & 63;
    int ntile  = chunk >> 6;
    int lane = w & 31, nb = (w >> 5) & 15, kk = w >> 9;
    int n = ntile * 128 + nb * 8 + (lane >> 2);
    int c = kchunk * 32 + kk * 8 + (lane & 3);
    ((uint2*)P)[id] = make_uint2(
        f2tf(W[(size_t)c * N + n]), f2tf(W[(size_t)(c + 4) * N + n]));
}

__global__ void pack_all(const float* __restrict__ X,
                         const float* __restrict__ Wq, const float* __restrict__ Wk,
                         const float* __restrict__ Wv, const float* __restrict__ Wo)
{
    const int NA = (BSR_ * HID_) / 4;
    const int NQ = (2048 * HID_) / 2;
    const int NK = (1024 * HID_) / 2;
    int id = blockIdx.x * blockDim.x + threadIdx.x;
    if (id < NA) { pack_a_one(X, g_Xp, id); return; }
    id -= NA;
    if (id < NQ)              { pack_b_one(Wq, g_Wqp, 2048, id); return; }
    if (id < NQ + NK)         { pack_b_one(Wk, g_Wkp, 1024, id - NQ); return; }
    if (id < NQ + 2 * NK)     { pack_b_one(Wv, g_Wvp, 1024, id - NQ - NK); return; }
    if (id < NQ + 2 * NK + NQ)  pack_b_one(Wo, g_Wop, 2048, id - NQ - 2 * NK);
}

// ============================================================
// RoPE tables
// ============================================================
__global__ void rope_table_kernel()
{
    int idx = blockIdx.x * blockDim.x + threadIdx.x;
    if (idx >= S_ * 64) return;
    int s = idx >> 6, i = idx & 63;
    const double NEG_LOG_STEP = -0.2158673524681918;
    double freq = exp((double)i * NEG_LOG_STEP);
    double sd, cd;
    sincos((double)s * freq, &sd, &cd);
    g_cos[idx] = (float)cd;
    g_sin[idx] = (float)sd;
}

// ============================================================
// TF32 GEMM core (R8, validated): 3-stage cp.async, one barrier/chunk.
// ============================================================
#define CHUNK_BYTES 16384
#define STAGE_BYTES (2 * CHUNK_BYTES)
#define GEMM_SMEM   (3 * STAGE_BYTES)          // 98304

__device__ __forceinline__ void gemm_issue_v3(
    unsigned sbase, int stage, const unsigned* __restrict__ Ac,
    const unsigned* __restrict__ Bc, int tid)
{
    unsigned st = sbase + stage * STAGE_BYTES;
#pragma unroll
    for (int p = 0; p < 4; p++) {
        int id = tid + p * 256;
        cp16(st + id * 16,               Ac + id * 4);
        cp16(st + CHUNK_BYTES + id * 16, Bc + id * 4);
    }
    cp_commit();
}

__device__ __forceinline__ void gemm_compute_v3(
    const char* st, float acc[4][4][4], int lane, int wm, int wn)
{
    const char* sA = st;
    const char* sB = st + CHUNK_BYTES;
#pragma unroll
    for (int kk = 0; kk < 4; kk++) {
        uint4 a[4]; uint2 b[4];
#pragma unroll
        for (int mf = 0; mf < 4; mf++)
            a[mf] = *(const uint4*)(sA + (((kk * 8 + wm * 4 + mf) * 32) + lane) * 16);
#pragma unroll
        for (int nf = 0; nf < 4; nf++)
            b[nf] = *(const uint2*)(sB + (((kk * 16 + wn * 4 + nf) * 32) + lane) * 8);
#pragma unroll
        for (int mf = 0; mf < 4; mf++)
#pragma unroll
            for (int nf = 0; nf < 4; nf++)
                mma_tf32(acc[mf][nf], (const unsigned*)&a[mf], (const unsigned*)&b[nf]);
    }
}

__device__ __forceinline__ void gemm_main_v4(
    const unsigned* __restrict__ Ab, const unsigned* __restrict__ Bb,
    float acc[4][4][4], char* smem)
{
    const int tid  = threadIdx.x;
    const int lane = tid & 31;
    const int wm   = (tid >> 5) >> 2;
    const int wn   = (tid >> 5) & 3;
    unsigned sbase = (unsigned)__cvta_generic_to_shared(smem);

    gemm_issue_v3(sbase, 0, Ab, Bb, tid);
    gemm_issue_v3(sbase, 1, Ab + 4096, Bb + 4096, tid);

    for (int i = 0; i < 64; i++) {
        if (i < 63) cp_wait1(); else cp_wait0();
        __syncthreads();
        if (i + 2 < 64)
            gemm_issue_v3(sbase, (i + 2) % 3,
                          Ab + (size_t)(i + 2) * 4096,
                          Bb + (size_t)(i + 2) * 4096, tid);
        gemm_compute_v3(smem + (i % 3) * STAGE_BYTES, acc, lane, wm, wn);
    }
}

// ============================================================
// Fused QKV projections; epilogues emit flash-fragment-packed
// Q/K (with RoPE + bf16 hi/lo split) and V (transposed).
// 1024 blocks: 512 Q, 256 K, 256 V.
// ============================================================
__global__ __launch_bounds__(256, 2) void gemm_qkv(
    const unsigned* __restrict__ Ap,
    const float* __restrict__ bq, const float* __restrict__ bk,
    const float* __restrict__ bv)
{
    extern __shared__ char smem[];
    float* sf = (float*)smem;                  // staging tile 128x132 f32
    const int id = blockIdx.x;
    const unsigned* Bp; const float* bias;
    int bx, by, mode;                          // 0=Q,1=K,2=V
    if (id < 512)      { Bp = g_Wqp; bias = bq; bx = id & 15; by = id >> 4; mode = 0; }
    else if (id < 768) { int t = id - 512; Bp = g_Wkp; bias = bk; bx = t & 7; by = t >> 3; mode = 1; }
    else               { int t = id - 768; Bp = g_Wvp; bias = bv; bx = t & 7; by = t >> 3; mode = 2; }

    float acc[4][4][4];
#pragma unroll
    for (int i = 0; i < 4; i++)
#pragma unroll
        for (int j = 0; j < 4; j++)
#pragma unroll
            for (int e = 0; e < 4; e++) acc[i][j][e] = 0.0f;

    gemm_main_v4(Ap + (size_t)by * 64 * 4096, Bp + (size_t)bx * 64 * 4096, acc, smem);
    __syncthreads();

    const int tid  = threadIdx.x;
    const int lane = tid & 31;
    const int warp = tid >> 5;
    const int wm = warp >> 2, wn = warp & 3;

    // ---- stage tile (Q/K row-major [r][132]; V transposed [d][132]) ----
#pragma unroll
    for (int mf = 0; mf < 4; mf++) {
        int r = wm * 64 + mf * 16 + (lane >> 2);
#pragma unroll
        for (int nf = 0; nf < 4; nf++) {
            int col = wn * 32 + nf * 8 + 2 * (lane & 3);
            float b0 = bias[bx * 128 + col], b1 = bias[bx * 128 + col + 1];
            float v00 = acc[mf][nf][0] + b0, v01 = acc[mf][nf][1] + b1;
            float v10 = acc[mf][nf][2] + b0, v11 = acc[mf][nf][3] + b1;
            if (mode != 2) {
                *(float2*)(sf + r * 132 + col)       = make_float2(v00, v01);
                *(float2*)(sf + (r + 8) * 132 + col) = make_float2(v10, v11);
            } else {
                sf[col * 132 + r]           = v00;
                sf[(col + 1) * 132 + r]     = v01;
                sf[col * 132 + r + 8]       = v10;
                sf[(col + 1) * 132 + r + 8] = v11;
            }
        }
    }
    __syncthreads();

    if (mode == 0) {
        // ---- Q: rope + split, A-frag packed per (rowblk by, head bx) ----
        unsigned* Qh = g_Qph + (size_t)(by * 16 + bx) * 8192;   // 2048 uint4
        unsigned* Ql = g_Qpl + (size_t)(by * 16 + bx) * 8192;
        for (int it = tid; it < 2048; it += 256) {
            int kk = it >> 8, wr = (it >> 5) & 7, ln = it & 31;
            int r = wr * 16 + (ln >> 2);
            int c = kk * 16 + 2 * (ln & 3);
            int s  = (by * 128 + r) & (S_ - 1);
            int s8 = s + 8;
            float e0 = rope_elem(sf, r, s, c);
            float e1 = rope_elem(sf, r, s, c + 1);
            float e2 = rope_elem(sf, r + 8, s8, c);
            float e3 = rope_elem(sf, r + 8, s8, c + 1);
            float e4 = rope_elem(sf, r, s, c + 8);
            float e5 = rope_elem(sf, r, s, c + 9);
            float e6 = rope_elem(sf, r + 8, s8, c + 8);
            float e7 = rope_elem(sf, r + 8, s8, c + 9);
            unsigned h0,l0,h1,l1,h2,l2,h3,l3;
            split2(e0, e1, h0, l0); split2(e2, e3, h1, l1);
            split2(e4, e5, h2, l2); split2(e6, e7, h3, l3);
            ((uint4*)Qh)[it] = make_uint4(h0, h1, h2, h3);
            ((uint4*)Ql)[it] = make_uint4(l0, l1, l2, l3);
        }
    } else if (mode == 1) {
        // ---- K: rope + split, B-frag packed per 64-key tile ----
        const int bb  = (by * 128) >> 11;
        const int kt0 = ((by * 128) & (S_ - 1)) >> 6;
        size_t kbase = ((size_t)((bb * NKV_ + bx) * 32 + kt0)) * 2048;   // uint2 units
        for (int it = tid; it < 4096; it += 256) {
            int kt = it >> 11, w = it & 2047;
            int kk = w >> 8, nf = (w >> 5) & 7, ln = w & 31;
            int n = nf * 8 + (ln >> 2);
            int r = kt * 64 + n;
            int c = kk * 16 + 2 * (ln & 3);
            int s = (by * 128 + r) & (S_ - 1);
            float e0 = rope_elem(sf, r, s, c);
            float e1 = rope_elem(sf, r, s, c + 1);
            float e2 = rope_elem(sf, r, s, c + 8);
            float e3 = rope_elem(sf, r, s, c + 9);
            unsigned h0,l0,h1,l1;
            split2(e0, e1, h0, l0); split2(e2, e3, h1, l1);
            ((uint2*)g_Kph)[kbase + kt * 2048 + w] = make_uint2(h0, h1);
            ((uint2*)g_Kpl)[kbase + kt * 2048 + w] = make_uint2(l0, l1);
        }
    } else {
        // ---- V: split, transposed B-frag packed per 64-key tile ----
        const int bb  = (by * 128) >> 11;
        const int kt0 = ((by * 128) & (S_ - 1)) >> 6;
        size_t vbase = ((size_t)((bb * NKV_ + bx) * 32 + kt0)) * 2048;
        for (int it = tid; it < 4096; it += 256) {
            int kt = it >> 11, w = it & 2047;
            int kk2 = w >> 9, nf = (w >> 5) & 15, ln = w & 31;
            int n  = nf * 8 + (ln >> 2);          // d
            int cl = kk2 * 16 + 2 * (ln & 3);     // key within tile
            int r  = kt * 64 + cl;
            float e0 = sf[n * 132 + r],     e1 = sf[n * 132 + r + 1];
            float e2 = sf[n * 132 + r + 8], e3 = sf[n * 132 + r + 9];
            unsigned h0,l0,h1,l1;
            split2(e0, e1, h0, l0); split2(e2, e3, h1, l1);
            ((uint2*)g_Vph)[vbase + kt * 2048 + w] = make_uint2(h0, h1);
            ((uint2*)g_Vpl)[vbase + kt * 2048 + w] = make_uint2(l0, l1);
        }
    }
}

// ============================================================
// O projection GEMM (unchanged, writes final out)
// ============================================================
__global__ __launch_bounds__(256, 2) void gemm_v3(
    const unsigned* __restrict__ Ap, const unsigned* __restrict__ Bp,
    float* __restrict__ C, int N)
{
    extern __shared__ char smem[];
    float acc[4][4][4];
#pragma unroll
    for (int i = 0; i < 4; i++)
#pragma unroll
        for (int j = 0; j < 4; j++)
#pragma unroll
            for (int e = 0; e < 4; e++) acc[i][j][e] = 0.0f;

    gemm_main_v4(Ap + (size_t)blockIdx.y * 64 * 4096,
                 Bp + (size_t)blockIdx.x * 64 * 4096, acc, smem);

    const int lane = threadIdx.x & 31;
    const int warp = threadIdx.x >> 5;
    const int wm = warp >> 2, wn = warp & 3;
#pragma unroll
    for (int mf = 0; mf < 4; mf++) {
        int row = blockIdx.y * 128 + wm * 64 + mf * 16 + (lane >> 2);
#pragma unroll
        for (int nf = 0; nf < 4; nf++) {
            int col = blockIdx.x * 128 + wn * 32 + nf * 8 + 2 * (lane & 3);
            *(float2*)&C[(size_t)row * N + col] =
                make_float2(acc[mf][nf][0], acc[mf][nf][1]);
            *(float2*)&C[(size_t)(row + 8) * N + col] =
                make_float2(acc[mf][nf][2], acc[mf][nf][3]);
        }
    }
}

// ============================================================
// Flash attention: fragment-packed operands, wide LDS,
// register softmax/P, ctx A-pack epilogue.
// smem: QH 32K | QL 32K | 2 stages x (Kh16K Kl16K Vh16K Vl16K)
// ============================================================
#define BQ 128
#define QH_OFF 0
#define QL_OFF 32768
#define ST0_OFF 65536
#define FSTAGE 65536
#define FLASH_SMEM (ST0_OFF + 2 * FSTAGE)     // 196608

__device__ __forceinline__ void flash_issue(
    unsigned sbase, int stage, size_t base_u, int tid)
{
    unsigned st = sbase + ST0_OFF + stage * FSTAGE;
#pragma unroll
    for (int p = 0; p < 4; p++) {
        int id = tid + p * 256;                 // 0..1023
        cp16(st + id * 16,         g_Kph + base_u + id * 4);
        cp16(st + 16384 + id * 16, g_Kpl + base_u + id * 4);
        cp16(st + 32768 + id * 16, g_Vph + base_u + id * 4);
        cp16(st + 49152 + id * 16, g_Vpl + base_u + id * 4);
    }
    cp_commit();
}

__global__ __launch_bounds__(256, 1) void flash_bf16()
{
    extern __shared__ char sm[];
    const int tid  = threadIdx.x;
    const int lane = tid & 31;
    const int warp = tid >> 5;
    const int qtile = (gridDim.x - 1) - blockIdx.x;
    const int h    = blockIdx.y;
    const int b    = blockIdx.z;
    const int kvh  = h / G_;
    const int qbase = qtile * BQ;
    const float scale = 0.08838834764831845f;
    const int g = lane >> 2;
    const int t = lane & 3;
    const int m0 = warp * 16;
    unsigned sbase = (unsigned)__cvta_generic_to_shared(sm);

    const size_t kvstep = 4096;                       // unsigned per 64-key tile
    const size_t kvb0 = ((size_t)(b * NKV_ + kvh) * 32) * kvstep;

    flash_issue(sbase, 0, kvb0, tid);

    // Q tile: linear copy of packed fragments
    {
        const int mq = (b * S_ + qbase) >> 7;
        const uint4* qh = (const uint4*)g_Qph + (size_t)(mq * 16 + h) * 2048;
        const uint4* ql = (const uint4*)g_Qpl + (size_t)(mq * 16 + h) * 2048;
        for (int it = tid; it < 2048; it += 256) {
            *(uint4*)(sm + QH_OFF + it * 16) = qh[it];
            *(uint4*)(sm + QL_OFF + it * 16) = ql[it];
        }
    }

    float ctx[16][4];
#pragma unroll
    for (int i = 0; i < 16; i++)
#pragma unroll
        for (int e = 0; e < 4; e++) ctx[i][e] = 0.0f;
    float mr0 = -INFINITY, mr1 = -INFINITY, lr0 = 0.0f, lr1 = 0.0f;

    const int row0 = qbase + m0 + g;
    const int row1 = row0 + 8;
    const int ntile = 2 * qtile + 2;

    for (int j = 0; j < ntile; j++) {
        const int kb = j * 64;
        if (j + 1 < ntile) {
            flash_issue(sbase, (j + 1) & 1, kvb0 + (size_t)(j + 1) * kvstep, tid);
            cp_wait1();
        } else {
            cp_wait0();
        }
        __syncthreads();

        const char* stg  = sm + ST0_OFF + (j & 1) * FSTAGE;
        const char* stK  = stg;
        const char* stKL = stg + 16384;
        const char* stV  = stg + 32768;
        const char* stVL = stg + 49152;

        float acc[8][4];
#pragma unroll
        for (int nf = 0; nf < 8; nf++)
#pragma unroll
            for (int e = 0; e < 4; e++) acc[nf][e] = 0.0f;

#pragma unroll
        for (int kk = 0; kk < 8; kk++) {
            uint4 aH = *(const uint4*)(sm + QH_OFF + (kk * 256 + warp * 32 + lane) * 16);
            uint4 aL = *(const uint4*)(sm + QL_OFF + (kk * 256 + warp * 32 + lane) * 16);
#pragma unroll
            for (int nf = 0; nf < 8; nf++) {
                uint2 bH = *(const uint2*)(stK  + (kk * 256 + nf * 32 + lane) * 8);
                uint2 bL = *(const uint2*)(stKL + (kk * 256 + nf * 32 + lane) * 8);
                mma_bf16(acc[nf], (const unsigned*)&aH, (const unsigned*)&bH);
                mma_bf16(acc[nf], (const unsigned*)&aH, (const unsigned*)&bL);
                mma_bf16(acc[nf], (const unsigned*)&aL, (const unsigned*)&bH);
            }
        }

#pragma unroll
        for (int nf = 0; nf < 8; nf++)
#pragma unroll
            for (int e = 0; e < 4; e++) acc[nf][e] *= scale;

        if (kb + 63 > qbase + m0) {
#pragma unroll
            for (int nf = 0; nf < 8; nf++) {
                int k0 = kb + nf * 8 + 2 * t;
                if (k0     > row0) acc[nf][0] = -INFINITY;
                if (k0 + 1 > row0) acc[nf][1] = -INFINITY;
                if (k0     > row1) acc[nf][2] = -INFINITY;
                if (k0 + 1 > row1) acc[nf][3] = -INFINITY;
            }
        }

        float mx0 = -INFINITY, mx1 = -INFINITY;
#pragma unroll
        for (int nf = 0; nf < 8; nf++) {
            mx0 = fmaxf(mx0, fmaxf(acc[nf][0], acc[nf][1]));
            mx1 = fmaxf(mx1, fmaxf(acc[nf][2], acc[nf][3]));
        }
        mx0 = fmaxf(mx0, __shfl_xor_sync(0xffffffffu, mx0, 1));
        mx0 = fmaxf(mx0, __shfl_xor_sync(0xffffffffu, mx0, 2));
        mx1 = fmaxf(mx1, __shfl_xor_sync(0xffffffffu, mx1, 1));
        mx1 = fmaxf(mx1, __shfl_xor_sync(0xffffffffu, mx1, 2));

        float mn0 = fmaxf(mr0, mx0);
        float mn1 = fmaxf(mr1, mx1);
        float al0 = __expf(mr0 - mn0);
        float al1 = __expf(mr1 - mn1);
        mr0 = mn0; mr1 = mn1;

        unsigned pH[4][4], pL[4][4];
        float s0 = 0.0f, s1 = 0.0f;
#pragma unroll
        for (int nf = 0; nf < 8; nf++) {
            float p00 = __expf(acc[nf][0] - mn0);
            float p01 = __expf(acc[nf][1] - mn0);
            float p10 = __expf(acc[nf][2] - mn1);
            float p11 = __expf(acc[nf][3] - mn1);
            s0 += p00 + p01;
            s1 += p10 + p11;
            int kk2 = nf >> 1;
            int sl  = (nf & 1) << 1;
            split2(p00, p01, pH[kk2][sl],     pL[kk2][sl]);
            split2(p10, p11, pH[kk2][sl + 1], pL[kk2][sl + 1]);
        }
        s0 += __shfl_xor_sync(0xffffffffu, s0, 1);
        s0 += __shfl_xor_sync(0xffffffffu, s0, 2);
        s1 += __shfl_xor_sync(0xffffffffu, s1, 1);
        s1 += __shfl_xor_sync(0xffffffffu, s1, 2);
        lr0 = lr0 * al0 + s0;
        lr1 = lr1 * al1 + s1;

#pragma unroll
        for (int nf = 0; nf < 16; nf++) {
            ctx[nf][0] *= al0; ctx[nf][1] *= al0;
            ctx[nf][2] *= al1; ctx[nf][3] *= al1;
        }
#pragma unroll
        for (int kk2 = 0; kk2 < 4; kk2++) {
#pragma unroll
            for (int nf = 0; nf < 16; nf++) {
                uint2 vH = *(const uint2*)(stV  + (kk2 * 512 + nf * 32 + lane) * 8);
                uint2 vL = *(const uint2*)(stVL + (kk2 * 512 + nf * 32 + lane) * 8);
                mma_bf16(ctx[nf], pH[kk2], (const unsigned*)&vH);
                mma_bf16(ctx[nf], pL[kk2], (const unsigned*)&vH);
                mma_bf16(ctx[nf], pH[kk2], (const unsigned*)&vL);
            }
        }
        __syncthreads();
    }

    // ---- fused epilogue: stage ctx f32, emit A-packed tf32 g_Ctp ----
    float* cs = (float*)(sm + ST0_OFF);        // 128x132 f32
    {
        float il0 = 1.0f / lr0;
        float il1 = 1.0f / lr1;
        int rl0 = m0 + g;
#pragma unroll
        for (int nf = 0; nf < 16; nf++) {
            int d = nf * 8 + 2 * t;
            *(float2*)(cs + rl0 * 132 + d) =
                make_float2(ctx[nf][0] * il0, ctx[nf][1] * il0);
            *(float2*)(cs + (rl0 + 8) * 132 + d) =
                make_float2(ctx[nf][2] * il1, ctx[nf][3] * il1);
        }
    }
    __syncthreads();

    {
        const int mtile = (b * S_ + qbase) >> 7;
        for (int it = tid; it < 4096; it += 256) {
            int ln = it & 31, rf = (it >> 5) & 7, kk = (it >> 8) & 3, kc = it >> 10;
            int rl = rf * 16 + (ln >> 2);
            int cl = kc * 32 + kk * 8 + (ln & 3);
            uint4 o = make_uint4(
                f2tf(cs[rl * 132 + cl]),       f2tf(cs[(rl + 8) * 132 + cl]),
                f2tf(cs[rl * 132 + cl + 4]),   f2tf(cs[(rl + 8) * 132 + cl + 4]));
            size_t idx = ((size_t)(mtile * 64 + h * 4 + kc) << 10) +
                         (kk << 8) + (rf << 5) + ln;
            ((uint4*)g_Ctp)[idx] = o;
        }
    }
}

// ============================================================
// launch
// ============================================================
extern "C" void kernel_launch(void* const* d_in, const int* in_sizes, int n_in,
                              void* d_out, int out_size)
{
    (void)in_sizes; (void)n_in; (void)out_size;
    const float* hidden = (const float*)d_in[0];
    const float* Wq = (const float*)d_in[1];
    const float* bq = (const float*)d_in[2];
    const float* Wk = (const float*)d_in[3];
    const float* bk = (const float*)d_in[4];
    const float* Wv = (const float*)d_in[5];
    const float* bv = (const float*)d_in[6];
    const float* Wo = (const float*)d_in[7];
    float* out = (float*)d_out;

    unsigned *xp, *ctp, *wop;
    cudaGetSymbolAddress((void**)&xp,  g_Xp);
    cudaGetSymbolAddress((void**)&ctp, g_Ctp);
    cudaGetSymbolAddress((void**)&wop, g_Wop);

    cudaFuncSetAttribute(gemm_qkv,
        cudaFuncAttributeMaxDynamicSharedMemorySize, GEMM_SMEM);
    cudaFuncSetAttribute(gemm_v3,
        cudaFuncAttributeMaxDynamicSharedMemorySize, GEMM_SMEM);
    cudaFuncSetAttribute(flash_bf16,
        cudaFuncAttributeMaxDynamicSharedMemorySize, FLASH_SMEM);

    const int NPACK = BSR_ * HID_ / 4 + (2048 + 1024 + 1024 + 2048) * HID_ / 2;

    // 1: pack GEMM operands
    pack_all<<<(NPACK + 255) / 256, 256>>>(hidden, Wq, Wk, Wv, Wo);
    // 2: RoPE tables
    rope_table_kernel<<<(S_ * 64 + 255) / 256, 256>>>();
    // 3: fused QKV projections + flash-fragment-packed epilogues
    gemm_qkv<<<1024, 256, GEMM_SMEM>>>(xp, bq, bk, bv);
    // 4: flash attention (+ ctx A-pack epilogue)  ← profiled launch
    flash_bf16<<<dim3(S_ / BQ, NH_, B_), 256, FLASH_SMEM>>>();
    // 5: O projection → final output
    gemm_v3<<<dim3(16, 32), 256, GEMM_SMEM>>>(ctp, wop, out, HID_);
}

// round 11
// speedup vs baseline: 4.7948x; 1.0001x over previous
#include <cuda_runtime.h>
#include <cuda_bf16.h>
#include <math.h>

#define B_    2
#define S_    2048
#define HID_  2048
#define NH_   16
#define NKV_  8
#define D_    128
#define G_    (NH_/NKV_)
#define BSR_  (B_*S_)          // 4096

// -------- scratch (__device__ globals; no allocations) --------
// flash operands, mma-fragment-packed bf16 hi/lo
__device__ unsigned g_Qph[BSR_ * NH_ * D_ / 2];     // [rowblk32*NH_][kk8][wr8][ln32] uint4
__device__ unsigned g_Qpl[BSR_ * NH_ * D_ / 2];
__device__ unsigned g_Kph[BSR_ * NKV_ * D_ / 2];    // [b2][kvh8][kt32][kk8][nf8][ln32] uint2
__device__ unsigned g_Kpl[BSR_ * NKV_ * D_ / 2];
__device__ unsigned g_Vph[BSR_ * NKV_ * D_ / 2];    // [b2][kvh8][kt32][kk2 4][nf16][ln32] uint2
__device__ unsigned g_Vpl[BSR_ * NKV_ * D_ / 2];
// GEMM operands, fragment-packed tf32
__device__ unsigned g_Xp [BSR_ * HID_];
__device__ unsigned g_Ctp[BSR_ * NH_ * D_];
__device__ unsigned g_Wqp[HID_ * NH_ * D_];
__device__ unsigned g_Wkp[HID_ * NKV_ * D_];
__device__ unsigned g_Wvp[HID_ * NKV_ * D_];
__device__ unsigned g_Wop[NH_ * D_ * HID_];
__device__ float g_cos[S_ * 64];
__device__ float g_sin[S_ * 64];

// ---------------- helpers ----------------
__device__ __forceinline__ unsigned f2tf(float x) {
    unsigned u;
    asm("cvt.rna.tf32.f32 %0, %1;" : "=r"(u) : "f"(x));
    return u;
}
__device__ __forceinline__ void cp16(unsigned dst, const void* src) {
    asm volatile("cp.async.cg.shared.global [%0], [%1], 16;" :: "r"(dst), "l"(src));
}
__device__ __forceinline__ void cp_commit() { asm volatile("cp.async.commit_group;"); }
__device__ __forceinline__ void cp_wait1()  { asm volatile("cp.async.wait_group 1;"); }
__device__ __forceinline__ void cp_wait0()  { asm volatile("cp.async.wait_group 0;"); }

__device__ __forceinline__ void split2(float x, float y, unsigned& hi, unsigned& lo) {
    __nv_bfloat16 hx = __float2bfloat16_rn(x);
    __nv_bfloat16 hy = __float2bfloat16_rn(y);
    float rx = x - __bfloat162float(hx);
    float ry = y - __bfloat162float(hy);
    __nv_bfloat162 h; h.x = hx; h.y = hy;
    __nv_bfloat162 l; l.x = __float2bfloat16_rn(rx); l.y = __float2bfloat16_rn(ry);
    hi = *(unsigned*)&h;
    lo = *(unsigned*)&l;
}

__device__ __forceinline__ void mma_tf32(float* d, const unsigned* a, const unsigned* b) {
    asm volatile(
        "mma.sync.aligned.m16n8k8.row.col.f32.tf32.tf32.f32 "
        "{%0,%1,%2,%3}, {%4,%5,%6,%7}, {%8,%9}, {%0,%1,%2,%3};\n"
        : "+f"(d[0]), "+f"(d[1]), "+f"(d[2]), "+f"(d[3])
        : "r"(a[0]), "r"(a[1]), "r"(a[2]), "r"(a[3]), "r"(b[0]), "r"(b[1]));
}
__device__ __forceinline__ void mma_bf16(float* d, const unsigned* a, const unsigned* b) {
    asm volatile(
        "mma.sync.aligned.m16n8k16.row.col.f32.bf16.bf16.f32 "
        "{%0,%1,%2,%3}, {%4,%5,%6,%7}, {%8,%9}, {%0,%1,%2,%3};\n"
        : "+f"(d[0]), "+f"(d[1]), "+f"(d[2]), "+f"(d[3])
        : "r"(a[0]), "r"(a[1]), "r"(a[2]), "r"(a[3]), "r"(b[0]), "r"(b[1]));
}

__device__ __forceinline__ float rope_elem(const float* sf, int r, int s, int c) {
    if (c < 64)
        return sf[r * 132 + c] * g_cos[s * 64 + c] - sf[r * 132 + c + 64] * g_sin[s * 64 + c];
    int i = c - 64;
    return sf[r * 132 + c] * g_cos[s * 64 + i] + sf[r * 132 + c - 64] * g_sin[s * 64 + i];
}

// ============================================================
// Fused packing of GEMM operands + RoPE tables (one launch).
// ============================================================
__device__ __forceinline__ void pack_a_one(
    const float* __restrict__ A, unsigned* __restrict__ P, int id)
{
    int w      = id & 1023;
    int chunk  = id >> 10;
    int kchunk = chunk & 63;
    int mtile  = chunk >> 6;
    int lane = w & 31, rf = (w >> 5) & 7, kk = w >> 8;
    int row = mtile * 128 + rf * 16 + (lane >> 2);
    int col = kchunk * 32 + kk * 8 + (lane & 3);
    const float* a0 = A + (size_t)row * HID_ + col;
    ((uint4*)P)[id] = make_uint4(
        f2tf(a0[0]), f2tf(a0[8 * HID_]), f2tf(a0[4]), f2tf(a0[8 * HID_ + 4]));
}

__device__ __forceinline__ void pack_b_one(
    const float* __restrict__ W, unsigned* __restrict__ P, int N, int id)
{
    int w      = id & 2047;
    int chunk  = id >> 11;
    int kchunk = chunk & 63;
    int ntile  = chunk >> 6;
    int lane = w & 31, nb = (w >> 5) & 15, kk = w >> 9;
    int n = ntile * 128 + nb * 8 + (lane >> 2);
    int c = kchunk * 32 + kk * 8 + (lane & 3);
    ((uint2*)P)[id] = make_uint2(
        f2tf(W[(size_t)c * N + n]), f2tf(W[(size_t)(c + 4) * N + n]));
}

__global__ void pack_all(const float* __restrict__ X,
                         const float* __restrict__ Wq, const float* __restrict__ Wk,
                         const float* __restrict__ Wv, const float* __restrict__ Wo)
{
    const int NA = (BSR_ * HID_) / 4;
    const int NQ = (2048 * HID_) / 2;
    const int NK = (1024 * HID_) / 2;
    int id = blockIdx.x * blockDim.x + threadIdx.x;
    if (id < NA) { pack_a_one(X, g_Xp, id); return; }
    id -= NA;
    if (id < NQ)              { pack_b_one(Wq, g_Wqp, 2048, id); return; }
    if (id < NQ + NK)         { pack_b_one(Wk, g_Wkp, 1024, id - NQ); return; }
    if (id < NQ + 2 * NK)     { pack_b_one(Wv, g_Wvp, 1024, id - NQ - NK); return; }
    if (id < NQ + 2 * NK + NQ) { pack_b_one(Wo, g_Wop, 2048, id - NQ - 2 * NK); return; }
    id -= NQ + 2 * NK + NQ;
    if (id < S_ * 64) {
        int s = id >> 6, i = id & 63;
        const double NEG_LOG_STEP = -0.2158673524681918;
        double freq = exp((double)i * NEG_LOG_STEP);
        double sd, cd;
        sincos((double)s * freq, &sd, &cd);
        g_cos[id] = (float)cd;
        g_sin[id] = (float)sd;
    }
}

// ============================================================
// TF32 GEMM core (validated): 3-stage cp.async, one barrier/chunk.
// ============================================================
#define CHUNK_BYTES 16384
#define STAGE_BYTES (2 * CHUNK_BYTES)
#define GEMM_SMEM   (3 * STAGE_BYTES)          // 98304

__device__ __forceinline__ void gemm_issue_v3(
    unsigned sbase, int stage, const unsigned* __restrict__ Ac,
    const unsigned* __restrict__ Bc, int tid)
{
    unsigned st = sbase + stage * STAGE_BYTES;
#pragma unroll
    for (int p = 0; p < 4; p++) {
        int id = tid + p * 256;
        cp16(st + id * 16,               Ac + id * 4);
        cp16(st + CHUNK_BYTES + id * 16, Bc + id * 4);
    }
    cp_commit();
}

__device__ __forceinline__ void gemm_compute_v3(
    const char* st, float acc[4][4][4], int lane, int wm, int wn)
{
    const char* sA = st;
    const char* sB = st + CHUNK_BYTES;
#pragma unroll
    for (int kk = 0; kk < 4; kk++) {
        uint4 a[4]; uint2 b[4];
#pragma unroll
        for (int mf = 0; mf < 4; mf++)
            a[mf] = *(const uint4*)(sA + (((kk * 8 + wm * 4 + mf) * 32) + lane) * 16);
#pragma unroll
        for (int nf = 0; nf < 4; nf++)
            b[nf] = *(const uint2*)(sB + (((kk * 16 + wn * 4 + nf) * 32) + lane) * 8);
#pragma unroll
        for (int mf = 0; mf < 4; mf++)
#pragma unroll
            for (int nf = 0; nf < 4; nf++)
                mma_tf32(acc[mf][nf], (const unsigned*)&a[mf], (const unsigned*)&b[nf]);
    }
}

__device__ __forceinline__ void gemm_main_v4(
    const unsigned* __restrict__ Ab, const unsigned* __restrict__ Bb,
    float acc[4][4][4], char* smem)
{
    const int tid  = threadIdx.x;
    const int lane = tid & 31;
    const int wm   = (tid >> 5) >> 2;
    const int wn   = (tid >> 5) & 3;
    unsigned sbase = (unsigned)__cvta_generic_to_shared(smem);

    gemm_issue_v3(sbase, 0, Ab, Bb, tid);
    gemm_issue_v3(sbase, 1, Ab + 4096, Bb + 4096, tid);

    for (int i = 0; i < 64; i++) {
        if (i < 63) cp_wait1(); else cp_wait0();
        __syncthreads();
        if (i + 2 < 64)
            gemm_issue_v3(sbase, (i + 2) % 3,
                          Ab + (size_t)(i + 2) * 4096,
                          Bb + (size_t)(i + 2) * 4096, tid);
        gemm_compute_v3(smem + (i % 3) * STAGE_BYTES, acc, lane, wm, wn);
    }
}

// ============================================================
// Fused QKV projections; epilogues emit flash-fragment-packed
// Q/K (RoPE + bf16 hi/lo) and V (transposed). (validated R10)
// ============================================================
__global__ __launch_bounds__(256, 2) void gemm_qkv(
    const unsigned* __restrict__ Ap,
    const float* __restrict__ bq, const float* __restrict__ bk,
    const float* __restrict__ bv)
{
    extern __shared__ char smem[];
    float* sf = (float*)smem;
    const int id = blockIdx.x;
    const unsigned* Bp; const float* bias;
    int bx, by, mode;
    if (id < 512)      { Bp = g_Wqp; bias = bq; bx = id & 15; by = id >> 4; mode = 0; }
    else if (id < 768) { int t = id - 512; Bp = g_Wkp; bias = bk; bx = t & 7; by = t >> 3; mode = 1; }
    else               { int t = id - 768; Bp = g_Wvp; bias = bv; bx = t & 7; by = t >> 3; mode = 2; }

    float acc[4][4][4];
#pragma unroll
    for (int i = 0; i < 4; i++)
#pragma unroll
        for (int j = 0; j < 4; j++)
#pragma unroll
            for (int e = 0; e < 4; e++) acc[i][j][e] = 0.0f;

    gemm_main_v4(Ap + (size_t)by * 64 * 4096, Bp + (size_t)bx * 64 * 4096, acc, smem);
    __syncthreads();

    const int tid  = threadIdx.x;
    const int lane = tid & 31;
    const int warp = tid >> 5;
    const int wm = warp >> 2, wn = warp & 3;

#pragma unroll
    for (int mf = 0; mf < 4; mf++) {
        int r = wm * 64 + mf * 16 + (lane >> 2);
#pragma unroll
        for (int nf = 0; nf < 4; nf++) {
            int col = wn * 32 + nf * 8 + 2 * (lane & 3);
            float b0 = bias[bx * 128 + col], b1 = bias[bx * 128 + col + 1];
            float v00 = acc[mf][nf][0] + b0, v01 = acc[mf][nf][1] + b1;
            float v10 = acc[mf][nf][2] + b0, v11 = acc[mf][nf][3] + b1;
            if (mode != 2) {
                *(float2*)(sf + r * 132 + col)       = make_float2(v00, v01);
                *(float2*)(sf + (r + 8) * 132 + col) = make_float2(v10, v11);
            } else {
                sf[col * 132 + r]           = v00;
                sf[(col + 1) * 132 + r]     = v01;
                sf[col * 132 + r + 8]       = v10;
                sf[(col + 1) * 132 + r + 8] = v11;
            }
        }
    }
    __syncthreads();

    if (mode == 0) {
        unsigned* Qh = g_Qph + (size_t)(by * 16 + bx) * 8192;
        unsigned* Ql = g_Qpl + (size_t)(by * 16 + bx) * 8192;
        for (int it = tid; it < 2048; it += 256) {
            int kk = it >> 8, wr = (it >> 5) & 7, ln = it & 31;
            int r = wr * 16 + (ln >> 2);
            int c = kk * 16 + 2 * (ln & 3);
            int s  = (by * 128 + r) & (S_ - 1);
            int s8 = s + 8;
            float e0 = rope_elem(sf, r, s, c);
            float e1 = rope_elem(sf, r, s, c + 1);
            float e2 = rope_elem(sf, r + 8, s8, c);
            float e3 = rope_elem(sf, r + 8, s8, c + 1);
            float e4 = rope_elem(sf, r, s, c + 8);
            float e5 = rope_elem(sf, r, s, c + 9);
            float e6 = rope_elem(sf, r + 8, s8, c + 8);
            float e7 = rope_elem(sf, r + 8, s8, c + 9);
            unsigned h0,l0,h1,l1,h2,l2,h3,l3;
            split2(e0, e1, h0, l0); split2(e2, e3, h1, l1);
            split2(e4, e5, h2, l2); split2(e6, e7, h3, l3);
            ((uint4*)Qh)[it] = make_uint4(h0, h1, h2, h3);
            ((uint4*)Ql)[it] = make_uint4(l0, l1, l2, l3);
        }
    } else if (mode == 1) {
        const int bb  = (by * 128) >> 11;
        const int kt0 = ((by * 128) & (S_ - 1)) >> 6;
        size_t kbase = ((size_t)((bb * NKV_ + bx) * 32 + kt0)) * 2048;
        for (int it = tid; it < 4096; it += 256) {
            int kt = it >> 11, w = it & 2047;
            int kk = w >> 8, nf = (w >> 5) & 7, ln = w & 31;
            int n = nf * 8 + (ln >> 2);
            int r = kt * 64 + n;
            int c = kk * 16 + 2 * (ln & 3);
            int s = (by * 128 + r) & (S_ - 1);
            float e0 = rope_elem(sf, r, s, c);
            float e1 = rope_elem(sf, r, s, c + 1);
            float e2 = rope_elem(sf, r, s, c + 8);
            float e3 = rope_elem(sf, r, s, c + 9);
            unsigned h0,l0,h1,l1;
            split2(e0, e1, h0, l0); split2(e2, e3, h1, l1);
            ((uint2*)g_Kph)[kbase + kt * 2048 + w] = make_uint2(h0, h1);
            ((uint2*)g_Kpl)[kbase + kt * 2048 + w] = make_uint2(l0, l1);
        }
    } else {
        const int bb  = (by * 128) >> 11;
        const int kt0 = ((by * 128) & (S_ - 1)) >> 6;
        size_t vbase = ((size_t)((bb * NKV_ + bx) * 32 + kt0)) * 2048;
        for (int it = tid; it < 4096; it += 256) {
            int kt = it >> 11, w = it & 2047;
            int kk2 = w >> 9, nf = (w >> 5) & 15, ln = w & 31;
            int n  = nf * 8 + (ln >> 2);
            int cl = kk2 * 16 + 2 * (ln & 3);
            int r  = kt * 64 + cl;
            float e0 = sf[n * 132 + r],     e1 = sf[n * 132 + r + 1];
            float e2 = sf[n * 132 + r + 8], e3 = sf[n * 132 + r + 9];
            unsigned h0,l0,h1,l1;
            split2(e0, e1, h0, l0); split2(e2, e3, h1, l1);
            ((uint2*)g_Vph)[vbase + kt * 2048 + w] = make_uint2(h0, h1);
            ((uint2*)g_Vpl)[vbase + kt * 2048 + w] = make_uint2(l0, l1);
        }
    }
}

// ============================================================
// O projection GEMM (unchanged)
// ============================================================
__global__ __launch_bounds__(256, 2) void gemm_v3(
    const unsigned* __restrict__ Ap, const unsigned* __restrict__ Bp,
    float* __restrict__ C, int N)
{
    extern __shared__ char smem[];
    float acc[4][4][4];
#pragma unroll
    for (int i = 0; i < 4; i++)
#pragma unroll
        for (int j = 0; j < 4; j++)
#pragma unroll
            for (int e = 0; e < 4; e++) acc[i][j][e] = 0.0f;

    gemm_main_v4(Ap + (size_t)blockIdx.y * 64 * 4096,
                 Bp + (size_t)blockIdx.x * 64 * 4096, acc, smem);

    const int lane = threadIdx.x & 31;
    const int warp = threadIdx.x >> 5;
    const int wm = warp >> 2, wn = warp & 3;
#pragma unroll
    for (int mf = 0; mf < 4; mf++) {
        int row = blockIdx.y * 128 + wm * 64 + mf * 16 + (lane >> 2);
#pragma unroll
        for (int nf = 0; nf < 4; nf++) {
            int col = blockIdx.x * 128 + wn * 32 + nf * 8 + 2 * (lane & 3);
            *(float2*)&C[(size_t)row * N + col] =
                make_float2(acc[mf][nf][0], acc[mf][nf][1]);
            *(float2*)&C[(size_t)(row + 8) * N + col] =
                make_float2(acc[mf][nf][2], acc[mf][nf][3]);
        }
    }
}

// ============================================================
// Flash attention v5: BQ=64, 128 threads (4 warps), 32-key stages,
// 96KB smem -> 2 CTAs/SM for cross-CTA phase overlap.
// smem: QH 16K | QL 16K | 2 stages x [Kh8K Kl8K Vh8K Vl8K]
// ============================================================
#define QH_OFF 0
#define QL_OFF 16384
#define FST0   32768
#define FSTAGE 32768
#define FLASH_SMEM (FST0 + 2 * FSTAGE)        // 98304

// j = 32-key step index; kt = j>>1 (64-key packed tile), hk = j&1 (half)
__device__ __forceinline__ void flash_issue(
    unsigned sbase, int stage, size_t kvb0, int j, int tid)
{
    unsigned st = sbase + FST0 + stage * FSTAGE;
    const int kt = j >> 1, hk = j & 1;
    const size_t tb = kvb0 + (size_t)kt * 2048;      // uint2 units
#pragma unroll
    for (int p = 0; p < 4; p++) {
        int id = tid + p * 128;                       // 0..511
        int kk = id >> 6, r = id & 63;
        int nf = r >> 4, lnp = (r & 15) * 2;
        size_t src = tb + kk * 256 + (hk * 4 + nf) * 32 + lnp;
        unsigned dst = st + (kk * 128 + nf * 32 + lnp) * 8;
        cp16(dst,        (const uint2*)g_Kph + src);
        cp16(dst + 8192, (const uint2*)g_Kpl + src);
    }
#pragma unroll
    for (int p = 0; p < 4; p++) {
        int id = tid + p * 128;
        int kk2 = id >> 8, r = id & 255;
        int nf = r >> 4, lnp = (r & 15) * 2;
        size_t src = tb + (hk * 2 + kk2) * 512 + nf * 32 + lnp;
        unsigned dst = st + 16384 + (kk2 * 512 + nf * 32 + lnp) * 8;
        cp16(dst,        (const uint2*)g_Vph + src);
        cp16(dst + 8192, (const uint2*)g_Vpl + src);
    }
    cp_commit();
}

__global__ __launch_bounds__(128, 2) void flash_bf16()
{
    extern __shared__ char sm[];
    const int tid  = threadIdx.x;
    const int lane = tid & 31;
    const int warp = tid >> 5;                 // 0..3
    const int qt64 = (gridDim.x - 1) - blockIdx.x;   // 64-row q tile, heavy first
    const int h    = blockIdx.y;
    const int b    = blockIdx.z;
    const int kvh  = h / G_;
    const int qbase = qt64 * 64;
    const float scale = 0.08838834764831845f;
    const int g = lane >> 2;
    const int t = lane & 3;
    const int m0 = warp * 16;
    unsigned sbase = (unsigned)__cvta_generic_to_shared(sm);

    const size_t kvb0 = ((size_t)(b * NKV_ + kvh) * 32) * 2048;  // uint2 units

    flash_issue(sbase, 0, kvb0, 0, tid);

    // Q: copy 64-row half of the packed 128-row tile
    {
        const int mq = (b * S_ + qbase) >> 7;
        const int hq = (qbase >> 6) & 1;
        const uint4* qh = (const uint4*)g_Qph + (size_t)(mq * 16 + h) * 2048;
        const uint4* ql = (const uint4*)g_Qpl + (size_t)(mq * 16 + h) * 2048;
        for (int it = tid; it < 1024; it += 128) {
            int kk = it >> 7, r = it & 127;
            int wr = r >> 5, ln = r & 31;
            int src = kk * 256 + (hq * 4 + wr) * 32 + ln;
            *(uint4*)(sm + QH_OFF + it * 16) = qh[src];
            *(uint4*)(sm + QL_OFF + it * 16) = ql[src];
        }
    }

    float ctx[16][4];
#pragma unroll
    for (int i = 0; i < 16; i++)
#pragma unroll
        for (int e = 0; e < 4; e++) ctx[i][e] = 0.0f;
    float mr0 = -INFINITY, mr1 = -INFINITY, lr0 = 0.0f, lr1 = 0.0f;

    const int row0 = qbase + m0 + g;
    const int row1 = row0 + 8;
    const int ntile = 2 * qt64 + 2;            // 32-key steps

    for (int j = 0; j < ntile; j++) {
        const int kb = j * 32;
        if (j + 1 < ntile) {
            flash_issue(sbase, (j + 1) & 1, kvb0, j + 1, tid);
            cp_wait1();
        } else {
            cp_wait0();
        }
        __syncthreads();

        const char* stg  = sm + FST0 + (j & 1) * FSTAGE;
        const char* stK  = stg;
        const char* stKL = stg + 8192;
        const char* stV  = stg + 16384;
        const char* stVL = stg + 24576;

        float acc[4][4];
#pragma unroll
        for (int nf = 0; nf < 4; nf++)
#pragma unroll
            for (int e = 0; e < 4; e++) acc[nf][e] = 0.0f;

#pragma unroll
        for (int kk = 0; kk < 8; kk++) {
            uint4 aH = *(const uint4*)(sm + QH_OFF + (kk * 128 + warp * 32 + lane) * 16);
            uint4 aL = *(const uint4*)(sm + QL_OFF + (kk * 128 + warp * 32 + lane) * 16);
#pragma unroll
            for (int nf = 0; nf < 4; nf++) {
                uint2 bH = *(const uint2*)(stK  + (kk * 128 + nf * 32 + lane) * 8);
                uint2 bL = *(const uint2*)(stKL + (kk * 128 + nf * 32 + lane) * 8);
                mma_bf16(acc[nf], (const unsigned*)&aH, (const unsigned*)&bH);
                mma_bf16(acc[nf], (const unsigned*)&aH, (const unsigned*)&bL);
                mma_bf16(acc[nf], (const unsigned*)&aL, (const unsigned*)&bH);
            }
        }

#pragma unroll
        for (int nf = 0; nf < 4; nf++)
#pragma unroll
            for (int e = 0; e < 4; e++) acc[nf][e] *= scale;

        if (kb + 31 > qbase + m0) {
#pragma unroll
            for (int nf = 0; nf < 4; nf++) {
                int k0 = kb + nf * 8 + 2 * t;
                if (k0     > row0) acc[nf][0] = -INFINITY;
                if (k0 + 1 > row0) acc[nf][1] = -INFINITY;
                if (k0     > row1) acc[nf][2] = -INFINITY;
                if (k0 + 1 > row1) acc[nf][3] = -INFINITY;
            }
        }

        float mx0 = -INFINITY, mx1 = -INFINITY;
#pragma unroll
        for (int nf = 0; nf < 4; nf++) {
            mx0 = fmaxf(mx0, fmaxf(acc[nf][0], acc[nf][1]));
            mx1 = fmaxf(mx1, fmaxf(acc[nf][2], acc[nf][3]));
        }
        mx0 = fmaxf(mx0, __shfl_xor_sync(0xffffffffu, mx0, 1));
        mx0 = fmaxf(mx0, __shfl_xor_sync(0xffffffffu, mx0, 2));
        mx1 = fmaxf(mx1, __shfl_xor_sync(0xffffffffu, mx1, 1));
        mx1 = fmaxf(mx1, __shfl_xor_sync(0xffffffffu, mx1, 2));

        float mn0 = fmaxf(mr0, mx0);
        float mn1 = fmaxf(mr1, mx1);
        float al0 = __expf(mr0 - mn0);
        float al1 = __expf(mr1 - mn1);
        mr0 = mn0; mr1 = mn1;

        unsigned pH[2][4], pL[2][4];
        float s0 = 0.0f, s1 = 0.0f;
#pragma unroll
        for (int nf = 0; nf < 4; nf++) {
            float p00 = __expf(acc[nf][0] - mn0);
            float p01 = __expf(acc[nf][1] - mn0);
            float p10 = __expf(acc[nf][2] - mn1);
            float p11 = __expf(acc[nf][3] - mn1);
            s0 += p00 + p01;
            s1 += p10 + p11;
            int kk2 = nf >> 1;
            int sl  = (nf & 1) << 1;
            split2(p00, p01, pH[kk2][sl],     pL[kk2][sl]);
            split2(p10, p11, pH[kk2][sl + 1], pL[kk2][sl + 1]);
        }
        s0 += __shfl_xor_sync(0xffffffffu, s0, 1);
        s0 += __shfl_xor_sync(0xffffffffu, s0, 2);
        s1 += __shfl_xor_sync(0xffffffffu, s1, 1);
        s1 += __shfl_xor_sync(0xffffffffu, s1, 2);
        lr0 = lr0 * al0 + s0;
        lr1 = lr1 * al1 + s1;

#pragma unroll
        for (int nf = 0; nf < 16; nf++) {
            ctx[nf][0] *= al0; ctx[nf][1] *= al0;
            ctx[nf][2] *= al1; ctx[nf][3] *= al1;
        }
#pragma unroll
        for (int kk2 = 0; kk2 < 2; kk2++) {
#pragma unroll
            for (int nf = 0; nf < 16; nf++) {
                uint2 vH = *(const uint2*)(stV  + (kk2 * 512 + nf * 32 + lane) * 8);
                uint2 vL = *(const uint2*)(stVL + (kk2 * 512 + nf * 32 + lane) * 8);
                mma_bf16(ctx[nf], pH[kk2], (const unsigned*)&vH);
                mma_bf16(ctx[nf], pL[kk2], (const unsigned*)&vH);
                mma_bf16(ctx[nf], pH[kk2], (const unsigned*)&vL);
            }
        }
        __syncthreads();
    }

    // ---- fused epilogue: stage ctx f32 (64x132), emit A-packed tf32 ----
    float* cs = (float*)(sm + FST0);           // 33.8KB <= 64KB stage area
    {
        float il0 = 1.0f / lr0;
        float il1 = 1.0f / lr1;
        int rl0 = m0 + g;
#pragma unroll
        for (int nf = 0; nf < 16; nf++) {
            int d = nf * 8 + 2 * t;
            *(float2*)(cs + rl0 * 132 + d) =
                make_float2(ctx[nf][0] * il0, ctx[nf][1] * il0);
            *(float2*)(cs + (rl0 + 8) * 132 + d) =
                make_float2(ctx[nf][2] * il1, ctx[nf][3] * il1);
        }
    }
    __syncthreads();

    {
        const int mtile = (b * S_ + qbase) >> 7;
        const int hq    = (qbase >> 6) & 1;
        for (int it = tid; it < 2048; it += 128) {
            int ln = it & 31, rf = (it >> 5) & 3, kk = (it >> 7) & 3, kc = it >> 9;
            int rl = rf * 16 + (ln >> 2);                  // local row 0..63
            int cl = kc * 32 + kk * 8 + (ln & 3);
            uint4 o = make_uint4(
                f2tf(cs[rl * 132 + cl]),       f2tf(cs[(rl + 8) * 132 + cl]),
                f2tf(cs[rl * 132 + cl + 4]),   f2tf(cs[(rl + 8) * 132 + cl + 4]));
            size_t idx = ((size_t)(mtile * 64 + h * 4 + kc) << 10) +
                         (kk << 8) + ((hq * 4 + rf) << 5) + ln;
            ((uint4*)g_Ctp)[idx] = o;
        }
    }
}

// ============================================================
// launch
// ============================================================
extern "C" void kernel_launch(void* const* d_in, const int* in_sizes, int n_in,
                              void* d_out, int out_size)
{
    (void)in_sizes; (void)n_in; (void)out_size;
    const float* hidden = (const float*)d_in[0];
    const float* Wq = (const float*)d_in[1];
    const float* bq = (const float*)d_in[2];
    const float* Wk = (const float*)d_in[3];
    const float* bk = (const float*)d_in[4];
    const float* Wv = (const float*)d_in[5];
    const float* bv = (const float*)d_in[6];
    const float* Wo = (const float*)d_in[7];
    float* out = (float*)d_out;

    unsigned *xp, *ctp, *wop;
    cudaGetSymbolAddress((void**)&xp,  g_Xp);
    cudaGetSymbolAddress((void**)&ctp, g_Ctp);
    cudaGetSymbolAddress((void**)&wop, g_Wop);

    cudaFuncSetAttribute(gemm_qkv,
        cudaFuncAttributeMaxDynamicSharedMemorySize, GEMM_SMEM);
    cudaFuncSetAttribute(gemm_v3,
        cudaFuncAttributeMaxDynamicSharedMemorySize, GEMM_SMEM);
    cudaFuncSetAttribute(flash_bf16,
        cudaFuncAttributeMaxDynamicSharedMemorySize, FLASH_SMEM);

    const int NPACK = BSR_ * HID_ / 4 +
                      (2048 + 1024 + 1024 + 2048) * HID_ / 2 + S_ * 64;

    // 1: pack GEMM operands + RoPE tables
    pack_all<<<(NPACK + 255) / 256, 256>>>(hidden, Wq, Wk, Wv, Wo);
    // 2: fused QKV projections + flash-fragment-packed epilogues
    gemm_qkv<<<1024, 256, GEMM_SMEM>>>(xp, bq, bk, bv);
    // 3: flash attention (BQ=64, 2 CTAs/SM)
    flash_bf16<<<dim3(S_ / 64, NH_, B_), 128, FLASH_SMEM>>>();
    // 4: O projection → final output
    gemm_v3<<<dim3(16, 32), 256, GEMM_SMEM>>>(ctp, wop, out, HID_);
}